// round 1
// baseline (speedup 1.0000x reference)
#include <cuda_runtime.h>

// ---------------------------------------------------------------------------
// Static scratch buffers (no allocation allowed)
// ---------------------------------------------------------------------------
__device__ float g_bufA[16 * 64 * 128 * 128];   // 16.78M floats (h1 / up0 out)
__device__ float g_bufB[16 * 128 * 64 * 64];    // 8.39M  (h2 / dec h)
__device__ float g_bufC[16 * 128 * 64 * 64];    // 8.39M  (enc_wf out / enc res h)
__device__ float g_bufT[16 * 32 * 64 * 64];     // 2.10M  (res temp)
__device__ float g_bufZ[16 * 64 * 64 * 64];     // 4.19M  (z)
__device__ float g_bufQ[16 * 64 * 64 * 64];     // 4.19M  (zq)

// ---------------------------------------------------------------------------
// Generic direct conv, NCHW. Each thread: 2 output channels x 8 contiguous ow.
// Block: 128 threads = 4 co-pairs x 32 spatial groups. blockIdx.y picks an
// 8-channel co block whose weights are staged in shared memory.
// ---------------------------------------------------------------------------
template <int KH, int KW, int S, int P, bool RIN, bool ROUT, bool ADD>
__global__ void __launch_bounds__(128) convk(
    const float* __restrict__ in, const float* __restrict__ wt,
    const float* __restrict__ bias, const float* __restrict__ res,
    float* __restrict__ out,
    int N, int CI, int CO, int IH, int IW, int OH, int OW)
{
    constexpr int TW = 8;
    constexpr int LW = (TW - 1) * S + KW;
    const int CO_T = 8;

    extern __shared__ float ws[];  // CO_T * CI * KH * KW
    const int tid = threadIdx.x;
    const int co0blk = blockIdx.y * CO_T;
    const int wcount = CO_T * CI * KH * KW;
    const float* wg = wt + (long)co0blk * CI * KH * KW;
    for (int i = tid; i < wcount; i += 128) ws[i] = wg[i];
    __syncthreads();

    const int cp = tid >> 5;          // 0..3 co-pair (uniform per warp)
    const int co_l = cp * 2;
    const int co = co0blk + co_l;
    const int sp = blockIdx.x * 32 + (tid & 31);
    const int OWG = OW / TW;
    const int owg = sp % OWG;
    const int t2 = sp / OWG;
    const int oh = t2 % OH;
    const int n = t2 / OH;
    if (n >= N) return;

    float acc0[TW], acc1[TW];
    {
        const float b0 = __ldg(bias + co);
        const float b1 = __ldg(bias + co + 1);
#pragma unroll
        for (int j = 0; j < TW; j++) { acc0[j] = b0; acc1[j] = b1; }
    }

    const int ix0 = owg * TW * S - P;
    const int iybase = oh * S - P;
    const float* inn = in + (long)n * CI * IH * IW;
    const float* w0p = ws + co_l * CI * KH * KW;
    const float* w1p = w0p + CI * KH * KW;
    const bool xin = (ix0 >= 0) && (ix0 + LW <= IW);

    for (int ci = 0; ci < CI; ci++) {
        const float* ic = inn + (long)ci * IH * IW;
        const float* wr0 = w0p + ci * KH * KW;
        const float* wr1 = w1p + ci * KH * KW;
#pragma unroll
        for (int kh = 0; kh < KH; kh++) {
            const int iy = iybase + kh;
            float ir[LW];
            if (iy >= 0 && iy < IH) {
                const float* irow = ic + (long)iy * IW;
                if (xin) {
#pragma unroll
                    for (int l = 0; l < LW; l++) {
                        float v = __ldg(irow + ix0 + l);
                        if (RIN) v = fmaxf(v, 0.f);
                        ir[l] = v;
                    }
                } else {
#pragma unroll
                    for (int l = 0; l < LW; l++) {
                        const int ix = ix0 + l;
                        float v = (ix >= 0 && ix < IW) ? __ldg(irow + ix) : 0.f;
                        if (RIN) v = fmaxf(v, 0.f);
                        ir[l] = v;
                    }
                }
            } else {
#pragma unroll
                for (int l = 0; l < LW; l++) ir[l] = 0.f;
            }
#pragma unroll
            for (int kw = 0; kw < KW; kw++) {
                const float w0 = wr0[kh * KW + kw];
                const float w1 = wr1[kh * KW + kw];
#pragma unroll
                for (int j = 0; j < TW; j++) {
                    const float v = ir[j * S + kw];
                    acc0[j] = fmaf(v, w0, acc0[j]);
                    acc1[j] = fmaf(v, w1, acc1[j]);
                }
            }
        }
    }

    const long obase0 = (((long)n * CO + co) * OH + oh) * OW + owg * TW;
    const long obase1 = obase0 + (long)OH * OW;
    if (ADD) {
#pragma unroll
        for (int j = 0; j < TW; j++) {
            acc0[j] += __ldg(res + obase0 + j);
            acc1[j] += __ldg(res + obase1 + j);
        }
    }
    if (ROUT) {
#pragma unroll
        for (int j = 0; j < TW; j++) {
            acc0[j] = fmaxf(acc0[j], 0.f);
            acc1[j] = fmaxf(acc1[j], 0.f);
        }
    }
    float4* o0 = reinterpret_cast<float4*>(out + obase0);
    float4* o1 = reinterpret_cast<float4*>(out + obase1);
    o0[0] = make_float4(acc0[0], acc0[1], acc0[2], acc0[3]);
    o0[1] = make_float4(acc0[4], acc0[5], acc0[6], acc0[7]);
    o1[0] = make_float4(acc1[0], acc1[1], acc1[2], acc1[3]);
    o1[1] = make_float4(acc1[4], acc1[5], acc1[6], acc1[7]);
}

// ---------------------------------------------------------------------------
// ConvTranspose2d, kernel=4, stride=2, pad=1 (torch weight layout Cin,Cout,4,4)
// gather form: out[oy,ox] += in[(oy+1-ky)/2, (ox+1-kx)/2] * w[ci,co,ky,kx]
// One co per block (handles CO=3); thread computes 8 contiguous ox.
// ---------------------------------------------------------------------------
template <bool RIN, bool ROUT>
__global__ void __launch_bounds__(128) convtk(
    const float* __restrict__ in, const float* __restrict__ wt,
    const float* __restrict__ bias, float* __restrict__ out,
    int N, int CI, int CO, int IH, int IW, int OH, int OW)
{
    constexpr int TW = 8;
    extern __shared__ float ws[];  // CI * 16
    const int tid = threadIdx.x;
    const int co = blockIdx.y;
    for (int i = tid; i < CI * 16; i += 128) {
        const int ci = i >> 4;
        const int kk = i & 15;
        ws[i] = wt[((long)ci * CO + co) * 16 + kk];
    }
    __syncthreads();

    const int sp = blockIdx.x * 128 + tid;
    const int OXG = OW / TW;
    const int oxg = sp % OXG;
    const int t2 = sp / OXG;
    const int oy = t2 % OH;
    const int n = t2 / OH;
    if (n >= N) return;

    const int ox0 = oxg * TW;
    float acc[TW];
    {
        const float b = __ldg(bias + co);
#pragma unroll
        for (int j = 0; j < TW; j++) acc[j] = b;
    }
    const int bx = ox0 / 2 - 1;
    const float* inn = in + (long)n * CI * IH * IW;

    for (int ci = 0; ci < CI; ci++) {
        const float* ic = inn + (long)ci * IH * IW;
        const float* wc = ws + ci * 16;
#pragma unroll
        for (int ky = 0; ky < 4; ky++) {
            const int num = oy + 1 - ky;
            if (num & 1) continue;
            const int iy = num >> 1;
            if (iy < 0 || iy >= IH) continue;
            const float* irow = ic + (long)iy * IW;
            float ir[6];
#pragma unroll
            for (int l = 0; l < 6; l++) {
                const int ix = bx + l;
                float v = (ix >= 0 && ix < IW) ? __ldg(irow + ix) : 0.f;
                if (RIN) v = fmaxf(v, 0.f);
                ir[l] = v;
            }
#pragma unroll
            for (int kx = 0; kx < 4; kx++) {
                const float w = wc[ky * 4 + kx];
#pragma unroll
                for (int jj = 0; jj < 4; jj++) {
                    const int j = 2 * jj + ((kx + 1) & 1);
                    const int rel = (j + 1 - kx) / 2 + 1;
                    acc[j] = fmaf(ir[rel], w, acc[j]);
                }
            }
        }
    }
    if (ROUT) {
#pragma unroll
        for (int j = 0; j < TW; j++) acc[j] = fmaxf(acc[j], 0.f);
    }
    float* op = out + (((long)n * CO + co) * OH + oy) * OW + ox0;
    float4* o4 = reinterpret_cast<float4*>(op);
    o4[0] = make_float4(acc[0], acc[1], acc[2], acc[3]);
    o4[1] = make_float4(acc[4], acc[5], acc[6], acc[7]);
}

// ---------------------------------------------------------------------------
// Vector quantizer: for each pixel vector f (D=64), argmin_k ||c_k||^2 - 2 f.c_k
// over K=512 codes; writes q = codebook[:, argmin]. Codebook tiled 128 codes
// at a time into smem; f held in registers. Strict < keeps first-min ties.
// z layout: [B, 64, H, W]; one thread per pixel.
// ---------------------------------------------------------------------------
__global__ void __launch_bounds__(256) vqk(
    const float* __restrict__ z, const float* __restrict__ cb,
    float* __restrict__ q, int NPIX, int B)
{
    __shared__ float cbs[64 * 128];
    __shared__ float cns[512];
    const int tid = threadIdx.x;

    // codebook column norms (redundant per block; tiny)
    for (int k = tid; k < 512; k += 256) {
        float s = 0.f;
#pragma unroll
        for (int d = 0; d < 64; d++) {
            const float v = __ldg(cb + d * 512 + k);
            s += v * v;
        }
        cns[k] = s;
    }

    const int p = blockIdx.x * 256 + tid;
    const int b = p / NPIX;
    const int pix = p % NPIX;
    const float* zp = z + (long)b * 64 * NPIX + pix;
    float f[64];
#pragma unroll
    for (int d = 0; d < 64; d++) f[d] = zp[(long)d * NPIX];

    float best = 3.4e38f;
    int bidx = 0;
    for (int t = 0; t < 4; t++) {
        __syncthreads();
        for (int i = tid; i < 64 * 128; i += 256) {
            const int d = i >> 7;
            const int kk = i & 127;
            cbs[i] = __ldg(cb + d * 512 + t * 128 + kk);
        }
        __syncthreads();
        for (int kk = 0; kk < 128; kk++) {
            float d0 = 0.f, d1 = 0.f, d2 = 0.f, d3 = 0.f;
#pragma unroll
            for (int d = 0; d < 64; d += 4) {
                d0 += f[d + 0] * cbs[(d + 0) * 128 + kk];
                d1 += f[d + 1] * cbs[(d + 1) * 128 + kk];
                d2 += f[d + 2] * cbs[(d + 2) * 128 + kk];
                d3 += f[d + 3] * cbs[(d + 3) * 128 + kk];
            }
            const int k = t * 128 + kk;
            const float dist = cns[k] - 2.f * ((d0 + d1) + (d2 + d3));
            if (dist < best) { best = dist; bidx = k; }
        }
    }
    float* qp = q + (long)b * 64 * NPIX + pix;
#pragma unroll
    for (int d = 0; d < 64; d++) qp[(long)d * NPIX] = __ldg(cb + d * 512 + bidx);
}

// ---------------------------------------------------------------------------
// Host launcher
// ---------------------------------------------------------------------------
extern "C" void kernel_launch(void* const* d_in, const int* in_sizes, int n_in,
                              void* d_out, int out_size)
{
    (void)in_sizes; (void)n_in; (void)out_size;
    const float* x        = (const float*)d_in[0];
    const float* enc_w0   = (const float*)d_in[1];
    const float* enc_b0   = (const float*)d_in[2];
    const float* enc_w1   = (const float*)d_in[3];
    const float* enc_b1   = (const float*)d_in[4];
    const float* enc_wf   = (const float*)d_in[5];
    const float* enc_bf   = (const float*)d_in[6];
    const float* enc_rw1  = (const float*)d_in[7];
    const float* enc_rb1  = (const float*)d_in[8];
    const float* enc_rw2  = (const float*)d_in[9];
    const float* enc_rb2  = (const float*)d_in[10];
    const float* pre_w    = (const float*)d_in[11];
    const float* pre_b    = (const float*)d_in[12];
    const float* codebook = (const float*)d_in[13];
    const float* dec_w    = (const float*)d_in[14];
    const float* dec_b    = (const float*)d_in[15];
    const float* dec_rw1  = (const float*)d_in[16];
    const float* dec_rb1  = (const float*)d_in[17];
    const float* dec_rw2  = (const float*)d_in[18];
    const float* dec_rb2  = (const float*)d_in[19];
    const float* up_w0    = (const float*)d_in[20];
    const float* up_b0    = (const float*)d_in[21];
    const float* up_w1    = (const float*)d_in[22];
    const float* up_b1    = (const float*)d_in[23];
    float* out = (float*)d_out;

    float *pA, *pB, *pC, *pT, *pZ, *pQ;
    cudaGetSymbolAddress((void**)&pA, g_bufA);
    cudaGetSymbolAddress((void**)&pB, g_bufB);
    cudaGetSymbolAddress((void**)&pC, g_bufC);
    cudaGetSymbolAddress((void**)&pT, g_bufT);
    cudaGetSymbolAddress((void**)&pZ, g_bufZ);
    cudaGetSymbolAddress((void**)&pQ, g_bufQ);

    const int N = 16;

    // grid helper: gx = N*OH*(OW/8)/32, gy = CO/8
    auto smem = [](int CI, int KH, int KW) { return 8 * CI * KH * KW * (int)sizeof(float); };

    // --- Encoder ---
    // L1: x[16,3,256,256] -> relu -> bufA[16,64,128,128]
    convk<4, 4, 2, 1, false, true, false><<<dim3(16 * 128 * 16 / 32, 64 / 8), 128, smem(3, 4, 4)>>>(
        x, enc_w0, enc_b0, nullptr, pA, N, 3, 64, 256, 256, 128, 128);
    // L2: bufA -> relu -> bufB[16,128,64,64]
    convk<4, 4, 2, 1, false, true, false><<<dim3(16 * 64 * 8 / 32, 128 / 8), 128, smem(64, 4, 4)>>>(
        pA, enc_w1, enc_b1, nullptr, pB, N, 64, 128, 128, 128, 64, 64);
    // enc_wf: bufB -> bufC (no relu)
    convk<3, 3, 1, 1, false, false, false><<<dim3(16 * 64 * 8 / 32, 128 / 8), 128, smem(128, 3, 3)>>>(
        pB, enc_wf, enc_bf, nullptr, pC, N, 128, 128, 64, 64, 64, 64);
    // enc res blocks (h in bufC, temp bufT)
    for (int i = 0; i < 2; i++) {
        convk<3, 3, 1, 1, true, false, false><<<dim3(16 * 64 * 8 / 32, 32 / 8), 128, smem(128, 3, 3)>>>(
            pC, enc_rw1 + (long)i * 32 * 128 * 9, enc_rb1 + i * 32, nullptr, pT,
            N, 128, 32, 64, 64, 64, 64);
        convk<1, 1, 1, 0, true, false, true><<<dim3(16 * 64 * 8 / 32, 128 / 8), 128, smem(32, 1, 1)>>>(
            pT, enc_rw2 + (long)i * 128 * 32, enc_rb2 + i * 128, pC, pC,
            N, 32, 128, 64, 64, 64, 64);
    }
    // pre: relu-in (trailing res_stack relu) bufC -> bufZ[16,64,64,64]
    convk<1, 1, 1, 0, true, false, false><<<dim3(16 * 64 * 8 / 32, 64 / 8), 128, smem(128, 1, 1)>>>(
        pC, pre_w, pre_b, nullptr, pZ, N, 128, 64, 64, 64, 64, 64);

    // --- VQ --- (65536 pixels, 256/block)
    vqk<<<256, 256>>>(pZ, codebook, pQ, 64 * 64, N);

    // --- Decoder ---
    // dec: bufQ -> bufB[16,128,64,64] (no relu)
    convk<3, 3, 1, 1, false, false, false><<<dim3(16 * 64 * 8 / 32, 128 / 8), 128, smem(64, 3, 3)>>>(
        pQ, dec_w, dec_b, nullptr, pB, N, 64, 128, 64, 64, 64, 64);
    // dec res blocks (h in bufB)
    for (int i = 0; i < 2; i++) {
        convk<3, 3, 1, 1, true, false, false><<<dim3(16 * 64 * 8 / 32, 32 / 8), 128, smem(128, 3, 3)>>>(
            pB, dec_rw1 + (long)i * 32 * 128 * 9, dec_rb1 + i * 32, nullptr, pT,
            N, 128, 32, 64, 64, 64, 64);
        convk<1, 1, 1, 0, true, false, true><<<dim3(16 * 64 * 8 / 32, 128 / 8), 128, smem(32, 1, 1)>>>(
            pT, dec_rw2 + (long)i * 128 * 32, dec_rb2 + i * 128, pB, pB,
            N, 32, 128, 64, 64, 64, 64);
    }
    // up0: relu-in (trailing res_stack relu), relu-out, bufB -> bufA[16,64,128,128]
    convtk<true, true><<<dim3(16 * 128 * 16 / 128, 64), 128, 128 * 16 * (int)sizeof(float)>>>(
        pB, up_w0, up_b0, pA, N, 128, 64, 64, 64, 128, 128);
    // up1: bufA -> out[16,3,256,256]
    convtk<false, false><<<dim3(16 * 256 * 32 / 128, 3), 128, 64 * 16 * (int)sizeof(float)>>>(
        pA, up_w1, up_b1, out, N, 64, 3, 128, 128, 256, 256);
}

// round 2
// speedup vs baseline: 2.5937x; 2.5937x over previous
#include <cuda_runtime.h>

// ---------------------------------------------------------------------------
// Static scratch buffers (no allocation allowed)
// ---------------------------------------------------------------------------
__device__ float g_bufA[16 * 64 * 128 * 128];   // 16.78M floats (h1 / up0 out)
__device__ float g_bufB[16 * 128 * 64 * 64];    // 8.39M  (h2 / dec h)
__device__ float g_bufC[16 * 128 * 64 * 64];    // 8.39M  (enc_wf out / enc res h)
__device__ float g_bufT[16 * 32 * 64 * 64];     // 2.10M  (res temp)
__device__ float g_bufZ[16 * 64 * 64 * 64];     // 4.19M  (z)
__device__ float g_bufQ[16 * 64 * 64 * 64];     // 4.19M  (zq)

// ---------------------------------------------------------------------------
// Shared-memory tiled direct conv, NCHW.
// Block: one n, COB=16 output channels, OHB output rows, full output width OW.
// Thread: COT=4 channels x 8 contiguous ow. lane%4 = channel group so input
// smem reads are 4-lane broadcasts. Input tile (with halo) staged per ci.
// ---------------------------------------------------------------------------
template <int KH, int KW, int S, int P, int OHB, bool RIN, bool ROUT, bool ADD>
__global__ void __launch_bounds__(256) conv_sm(
    const float* __restrict__ in, const float* __restrict__ wt,
    const float* __restrict__ bias, const float* __restrict__ res,
    float* __restrict__ out,
    int N, int CI, int CO, int IH, int IW, int OH, int OW)
{
    constexpr int COB = 16, COT = 4, COG = 4;
    constexpr int LW = 7 * S + KW;           // per-thread input row segment
    constexpr int TROWS = (OHB - 1) * S + KH;
    constexpr int TAPS = KH * KW;

    extern __shared__ float sm[];
    const int TWID = (OW - 1) * S + KW;       // valid tile width
    const int TWIDP = (TWID + 3) & ~3;        // padded (16B-aligned rows)
    float* tile = sm;                         // TROWS * TWIDP
    float* wsm = sm + TROWS * TWIDP;          // COB * TAPS

    const int RB = OH / OHB;
    const int n = blockIdx.x / RB;
    const int rb = blockIdx.x % RB;
    const int oy0 = rb * OHB;
    const int co0 = blockIdx.y * COB;

    const int tid = threadIdx.x;
    const int cog = tid & (COG - 1);
    const int spat = tid >> 2;
    const int OWG = OW >> 3;
    const int owg = spat % OWG;
    const int ohr = spat / OWG;
    const int co_l = cog * COT;

    float acc[COT][8];
#pragma unroll
    for (int c = 0; c < COT; c++) {
        const float b = __ldg(bias + co0 + co_l + c);
#pragma unroll
        for (int j = 0; j < 8; j++) acc[c][j] = b;
    }

    const float* inn = in + (long)n * CI * IH * IW;
    const int iy0 = oy0 * S - P;
    const int tile_elems = TROWS * TWIDP;
    const int wel = COB * TAPS;

    for (int ci = 0; ci < CI; ci++) {
        __syncthreads();
        const float* ip = inn + (long)ci * IH * IW;
        for (int i = tid; i < tile_elems; i += 256) {
            const int r = i / TWIDP, c = i % TWIDP;
            const int iy = iy0 + r, ix = c - P;
            float v = 0.f;
            if (c < TWID && iy >= 0 && iy < IH && ix >= 0 && ix < IW)
                v = __ldg(ip + (long)iy * IW + ix);
            if (RIN) v = fmaxf(v, 0.f);
            tile[i] = v;
        }
        for (int i = tid; i < wel; i += 256) {
            const int c = i / TAPS, t = i % TAPS;
            wsm[i] = __ldg(wt + ((long)(co0 + c) * CI + ci) * TAPS + t);
        }
        __syncthreads();

#pragma unroll
        for (int kh = 0; kh < KH; kh++) {
            const float* trow = tile + (ohr * S + kh) * TWIDP + owg * 8 * S;
            float ir[LW];
            constexpr int LW4 = LW / 4;
            const float4* t4 = reinterpret_cast<const float4*>(trow);
#pragma unroll
            for (int v = 0; v < LW4; v++) {
                const float4 q = t4[v];
                ir[4 * v + 0] = q.x; ir[4 * v + 1] = q.y;
                ir[4 * v + 2] = q.z; ir[4 * v + 3] = q.w;
            }
#pragma unroll
            for (int l = LW4 * 4; l < LW; l++) ir[l] = trow[l];
#pragma unroll
            for (int kw = 0; kw < KW; kw++) {
#pragma unroll
                for (int c = 0; c < COT; c++) {
                    const float w = wsm[(co_l + c) * TAPS + kh * KW + kw];
#pragma unroll
                    for (int j = 0; j < 8; j++)
                        acc[c][j] = fmaf(ir[j * S + kw], w, acc[c][j]);
                }
            }
        }
    }

    const int oy = oy0 + ohr;
    const long chs = (long)OH * OW;
    const long ob = (((long)n * CO + co0 + co_l) * OH + oy) * OW + owg * 8;
#pragma unroll
    for (int c = 0; c < COT; c++) {
        float* op = out + ob + c * chs;
        if (ADD) {
            const float* rp = res + ob + c * chs;
#pragma unroll
            for (int j = 0; j < 8; j++) acc[c][j] += __ldg(rp + j);
        }
        if (ROUT) {
#pragma unroll
            for (int j = 0; j < 8; j++) acc[c][j] = fmaxf(acc[c][j], 0.f);
        }
        reinterpret_cast<float4*>(op)[0] = make_float4(acc[c][0], acc[c][1], acc[c][2], acc[c][3]);
        reinterpret_cast<float4*>(op)[1] = make_float4(acc[c][4], acc[c][5], acc[c][6], acc[c][7]);
    }
}

// ---------------------------------------------------------------------------
// Shared-memory tiled ConvTranspose2d, kernel=4, stride=2, pad=1.
// out[oy,ox] = sum_ci sum_{ky,kx: (oy+1-ky) even, (ox+1-kx) even}
//              in[(oy+1-ky)/2, (ox+1-kx)/2] * w[ci,co,ky,kx]
// Block: one n, COB channels, OHB output rows, full width OW. Input tile
// rows iy0..iy0+OHB/2+1 (halo) staged per ci.
// ---------------------------------------------------------------------------
template <int COB, int COT, int OHB, bool RIN, bool ROUT>
__global__ void convt_sm(
    const float* __restrict__ in, const float* __restrict__ wt,
    const float* __restrict__ bias, float* __restrict__ out,
    int N, int CI, int CO, int IH, int IW, int OH, int OW)
{
    constexpr int COG = COB / COT;
    constexpr int TROWS = OHB / 2 + 2;

    extern __shared__ float sm[];
    const int TWID = OW / 2 + 2;
    const int TWIDP = (TWID + 3) & ~3;
    float* tile = sm;                  // TROWS * TWIDP
    float* wsm = sm + TROWS * TWIDP;   // COB * 16

    const int RB = OH / OHB;
    const int n = blockIdx.x / RB;
    const int rb = blockIdx.x % RB;
    const int oy0 = rb * OHB;
    const int co0 = blockIdx.y * COB;

    const int tid = threadIdx.x;
    const int cog = tid % COG;
    const int spat = tid / COG;
    const int OWG = OW >> 3;
    const int owg = spat % OWG;
    const int ohr = spat / OWG;
    const int co_l = cog * COT;

    float acc[COT][8];
#pragma unroll
    for (int c = 0; c < COT; c++) {
        const float b = __ldg(bias + co0 + co_l + c);
#pragma unroll
        for (int j = 0; j < 8; j++) acc[c][j] = b;
    }

    const int iy0 = oy0 / 2 - 1;           // tile row 0 <-> this iy
    const float* inn = in + (long)n * CI * IH * IW;
    const int tile_elems = TROWS * TWIDP;
    const int wel = COB * 16;
    const int nthr = blockDim.x;

    const int oy = oy0 + ohr;
    const int ky0 = (oy + 1) & 1;

    for (int ci = 0; ci < CI; ci++) {
        __syncthreads();
        const float* ip = inn + (long)ci * IH * IW;
        for (int i = tid; i < tile_elems; i += nthr) {
            const int r = i / TWIDP, c = i % TWIDP;
            const int iy = iy0 + r, ix = c - 1;
            float v = 0.f;
            if (c < TWID && iy >= 0 && iy < IH && ix >= 0 && ix < IW)
                v = __ldg(ip + (long)iy * IW + ix);
            if (RIN) v = fmaxf(v, 0.f);
            tile[i] = v;
        }
        for (int i = tid; i < wel; i += nthr) {
            const int c = i >> 4, t = i & 15;
            wsm[i] = __ldg(wt + ((long)ci * CO + co0 + c) * 16 + t);
        }
        __syncthreads();

#pragma unroll
        for (int t2 = 0; t2 < 2; t2++) {
            const int ky = ky0 + 2 * t2;
            const int iy = (oy + 1 - ky) >> 1;      // may be -1 (in halo)
            const int r = iy - iy0;
            const float* trow = tile + r * TWIDP + owg * 4;  // tile col ox0/2
            float ir[6];
            {
                const float4 q = *reinterpret_cast<const float4*>(trow);
                ir[0] = q.x; ir[1] = q.y; ir[2] = q.z; ir[3] = q.w;
                ir[4] = trow[4]; ir[5] = trow[5];
            }
#pragma unroll
            for (int kx = 0; kx < 4; kx++) {
                // phase: j = 2m + ((kx+1)&1); ir index l = m + d + 1
                constexpr int dtab[4] = {1, 0, 0, -1};
                const int p = (kx + 1) & 1;
#pragma unroll
                for (int c = 0; c < COT; c++) {
                    const float w = wsm[(co_l + c) * 16 + ky * 4 + kx];
#pragma unroll
                    for (int m = 0; m < 4; m++) {
                        const int j = 2 * m + p;
                        const int l = m + dtab[kx] + 1;
                        acc[c][j] = fmaf(ir[l], w, acc[c][j]);
                    }
                }
            }
        }
    }

    const long chs = (long)OH * OW;
    const long ob = (((long)n * CO + co0 + co_l) * OH + oy) * OW + owg * 8;
#pragma unroll
    for (int c = 0; c < COT; c++) {
        if (ROUT) {
#pragma unroll
            for (int j = 0; j < 8; j++) acc[c][j] = fmaxf(acc[c][j], 0.f);
        }
        float* op = out + ob + c * chs;
        reinterpret_cast<float4*>(op)[0] = make_float4(acc[c][0], acc[c][1], acc[c][2], acc[c][3]);
        reinterpret_cast<float4*>(op)[1] = make_float4(acc[c][4], acc[c][5], acc[c][6], acc[c][7]);
    }
}

// ---------------------------------------------------------------------------
// Vector quantizer: argmin_k ||c_k||^2 - 2 f.c_k over 512 codes (D=64);
// writes q = codebook[:, argmin]. Strict < keeps first-min tie semantics.
// ---------------------------------------------------------------------------
__global__ void __launch_bounds__(256) vqk(
    const float* __restrict__ z, const float* __restrict__ cb,
    float* __restrict__ q, int NPIX, int B)
{
    __shared__ float cbs[64 * 128];
    __shared__ float cns[512];
    const int tid = threadIdx.x;

    for (int k = tid; k < 512; k += 256) {
        float s = 0.f;
#pragma unroll
        for (int d = 0; d < 64; d++) {
            const float v = __ldg(cb + d * 512 + k);
            s += v * v;
        }
        cns[k] = s;
    }

    const int p = blockIdx.x * 256 + tid;
    const int b = p / NPIX;
    const int pix = p % NPIX;
    const float* zp = z + (long)b * 64 * NPIX + pix;
    float f[64];
#pragma unroll
    for (int d = 0; d < 64; d++) f[d] = zp[(long)d * NPIX];

    float best = 3.4e38f;
    int bidx = 0;
    for (int t = 0; t < 4; t++) {
        __syncthreads();
        for (int i = tid; i < 64 * 128; i += 256) {
            const int d = i >> 7;
            const int kk = i & 127;
            cbs[i] = __ldg(cb + d * 512 + t * 128 + kk);
        }
        __syncthreads();
        for (int kk = 0; kk < 128; kk++) {
            float d0 = 0.f, d1 = 0.f, d2 = 0.f, d3 = 0.f;
#pragma unroll
            for (int d = 0; d < 64; d += 4) {
                d0 += f[d + 0] * cbs[(d + 0) * 128 + kk];
                d1 += f[d + 1] * cbs[(d + 1) * 128 + kk];
                d2 += f[d + 2] * cbs[(d + 2) * 128 + kk];
                d3 += f[d + 3] * cbs[(d + 3) * 128 + kk];
            }
            const int k = t * 128 + kk;
            const float dist = cns[k] - 2.f * ((d0 + d1) + (d2 + d3));
            if (dist < best) { best = dist; bidx = k; }
        }
    }
    float* qp = q + (long)b * 64 * NPIX + pix;
#pragma unroll
    for (int d = 0; d < 64; d++) qp[(long)d * NPIX] = __ldg(cb + d * 512 + bidx);
}

// ---------------------------------------------------------------------------
// Host launcher
// ---------------------------------------------------------------------------
static inline int conv_smem(int OW, int S, int KH, int KW, int OHB) {
    const int TWID = (OW - 1) * S + KW;
    const int TWIDP = (TWID + 3) & ~3;
    const int TROWS = (OHB - 1) * S + KH;
    return (TROWS * TWIDP + 16 * KH * KW) * (int)sizeof(float);
}
static inline int convt_smem(int OW, int OHB, int COB) {
    const int TWID = OW / 2 + 2;
    const int TWIDP = (TWID + 3) & ~3;
    const int TROWS = OHB / 2 + 2;
    return (TROWS * TWIDP + COB * 16) * (int)sizeof(float);
}

extern "C" void kernel_launch(void* const* d_in, const int* in_sizes, int n_in,
                              void* d_out, int out_size)
{
    (void)in_sizes; (void)n_in; (void)out_size;
    const float* x        = (const float*)d_in[0];
    const float* enc_w0   = (const float*)d_in[1];
    const float* enc_b0   = (const float*)d_in[2];
    const float* enc_w1   = (const float*)d_in[3];
    const float* enc_b1   = (const float*)d_in[4];
    const float* enc_wf   = (const float*)d_in[5];
    const float* enc_bf   = (const float*)d_in[6];
    const float* enc_rw1  = (const float*)d_in[7];
    const float* enc_rb1  = (const float*)d_in[8];
    const float* enc_rw2  = (const float*)d_in[9];
    const float* enc_rb2  = (const float*)d_in[10];
    const float* pre_w    = (const float*)d_in[11];
    const float* pre_b    = (const float*)d_in[12];
    const float* codebook = (const float*)d_in[13];
    const float* dec_w    = (const float*)d_in[14];
    const float* dec_b    = (const float*)d_in[15];
    const float* dec_rw1  = (const float*)d_in[16];
    const float* dec_rb1  = (const float*)d_in[17];
    const float* dec_rw2  = (const float*)d_in[18];
    const float* dec_rb2  = (const float*)d_in[19];
    const float* up_w0    = (const float*)d_in[20];
    const float* up_b0    = (const float*)d_in[21];
    const float* up_w1    = (const float*)d_in[22];
    const float* up_b1    = (const float*)d_in[23];
    float* out = (float*)d_out;

    float *pA, *pB, *pC, *pT, *pZ, *pQ;
    cudaGetSymbolAddress((void**)&pA, g_bufA);
    cudaGetSymbolAddress((void**)&pB, g_bufB);
    cudaGetSymbolAddress((void**)&pC, g_bufC);
    cudaGetSymbolAddress((void**)&pT, g_bufT);
    cudaGetSymbolAddress((void**)&pZ, g_bufZ);
    cudaGetSymbolAddress((void**)&pQ, g_bufQ);

    const int N = 16;

    // --- Encoder ---
    // L1: x[16,3,256,256] -> relu -> bufA[16,64,128,128]  (OHB=4, OW=128)
    conv_sm<4, 4, 2, 1, 4, false, true, false>
        <<<dim3(N * (128 / 4), 64 / 16), 256, conv_smem(128, 2, 4, 4, 4)>>>(
        x, enc_w0, enc_b0, nullptr, pA, N, 3, 64, 256, 256, 128, 128);
    // L2: bufA -> relu -> bufB[16,128,64,64]  (OHB=8)
    conv_sm<4, 4, 2, 1, 8, false, true, false>
        <<<dim3(N * (64 / 8), 128 / 16), 256, conv_smem(64, 2, 4, 4, 8)>>>(
        pA, enc_w1, enc_b1, nullptr, pB, N, 64, 128, 128, 128, 64, 64);
    // enc_wf: bufB -> bufC (no relu)
    conv_sm<3, 3, 1, 1, 8, false, false, false>
        <<<dim3(N * 8, 128 / 16), 256, conv_smem(64, 1, 3, 3, 8)>>>(
        pB, enc_wf, enc_bf, nullptr, pC, N, 128, 128, 64, 64, 64, 64);
    // enc res blocks (h in bufC, temp bufT)
    for (int i = 0; i < 2; i++) {
        conv_sm<3, 3, 1, 1, 8, true, false, false>
            <<<dim3(N * 8, 32 / 16), 256, conv_smem(64, 1, 3, 3, 8)>>>(
            pC, enc_rw1 + (long)i * 32 * 128 * 9, enc_rb1 + i * 32, nullptr, pT,
            N, 128, 32, 64, 64, 64, 64);
        conv_sm<1, 1, 1, 0, 8, true, false, true>
            <<<dim3(N * 8, 128 / 16), 256, conv_smem(64, 1, 1, 1, 8)>>>(
            pT, enc_rw2 + (long)i * 128 * 32, enc_rb2 + i * 128, pC, pC,
            N, 32, 128, 64, 64, 64, 64);
    }
    // pre: relu-in (trailing res_stack relu) bufC -> bufZ[16,64,64,64]
    conv_sm<1, 1, 1, 0, 8, true, false, false>
        <<<dim3(N * 8, 64 / 16), 256, conv_smem(64, 1, 1, 1, 8)>>>(
        pC, pre_w, pre_b, nullptr, pZ, N, 128, 64, 64, 64, 64, 64);

    // --- VQ ---
    vqk<<<256, 256>>>(pZ, codebook, pQ, 64 * 64, N);

    // --- Decoder ---
    // dec: bufQ -> bufB[16,128,64,64] (no relu)
    conv_sm<3, 3, 1, 1, 8, false, false, false>
        <<<dim3(N * 8, 128 / 16), 256, conv_smem(64, 1, 3, 3, 8)>>>(
        pQ, dec_w, dec_b, nullptr, pB, N, 64, 128, 64, 64, 64, 64);
    // dec res blocks (h in bufB)
    for (int i = 0; i < 2; i++) {
        conv_sm<3, 3, 1, 1, 8, true, false, false>
            <<<dim3(N * 8, 32 / 16), 256, conv_smem(64, 1, 3, 3, 8)>>>(
            pB, dec_rw1 + (long)i * 32 * 128 * 9, dec_rb1 + i * 32, nullptr, pT,
            N, 128, 32, 64, 64, 64, 64);
        conv_sm<1, 1, 1, 0, 8, true, false, true>
            <<<dim3(N * 8, 128 / 16), 256, conv_smem(64, 1, 1, 1, 8)>>>(
            pT, dec_rw2 + (long)i * 128 * 32, dec_rb2 + i * 128, pB, pB,
            N, 32, 128, 64, 64, 64, 64);
    }
    // up0: relu-in + relu-out, bufB[16,128,64,64] -> bufA[16,64,128,128]
    // COB=16, COT=4, OHB=4 -> 256 threads
    convt_sm<16, 4, 4, true, true>
        <<<dim3(N * (128 / 4), 64 / 16), 256, convt_smem(128, 4, 16)>>>(
        pB, up_w0, up_b0, pA, N, 128, 64, 64, 64, 128, 128);
    // up1: bufA[16,64,128,128] -> out[16,3,256,256]
    // COB=3, COT=1, OHB=2 -> (256/8)*2*3 = 192 threads
    convt_sm<3, 1, 2, false, false>
        <<<dim3(N * (256 / 2), 1), 192, convt_smem(256, 2, 3)>>>(
        pA, up_w1, up_b1, out, N, 64, 3, 128, 128, 256, 256);
}

// round 3
// speedup vs baseline: 3.7814x; 1.4579x over previous
#include <cuda_runtime.h>
#include <cstdint>

typedef unsigned long long ull;

// ---------------------------------------------------------------------------
// Static scratch buffers (no allocation allowed)
// ---------------------------------------------------------------------------
__device__ float g_bufA[16 * 64 * 128 * 128];
__device__ float g_bufB[16 * 128 * 64 * 64];
__device__ float g_bufC[16 * 128 * 64 * 64];
__device__ float g_bufT[16 * 32 * 64 * 64];
__device__ float g_bufZ[16 * 64 * 64 * 64];
__device__ float g_bufQ[16 * 64 * 64 * 64];

// ---------------------------------------------------------------------------
// f32x2 + cp.async helpers
// ---------------------------------------------------------------------------
__device__ __forceinline__ ull pk2(float lo, float hi) {
    ull r; asm("mov.b64 %0, {%1, %2};" : "=l"(r) : "f"(lo), "f"(hi)); return r;
}
__device__ __forceinline__ void fma2(ull& a, ull v, ull w) {
    asm("fma.rn.f32x2 %0, %1, %2, %0;" : "+l"(a) : "l"(v), "l"(w));
}
__device__ __forceinline__ float2 upk(ull v) {
    float2 r; asm("mov.b64 {%0, %1}, %2;" : "=f"(r.x), "=f"(r.y) : "l"(v)); return r;
}
__device__ __forceinline__ void cpa4(uint32_t s, const float* g, bool ok) {
    asm volatile("cp.async.ca.shared.global [%0], [%1], 4, %2;"
                 :: "r"(s), "l"(g), "r"(ok ? 4u : 0u));
}
__device__ __forceinline__ void cpacommit() { asm volatile("cp.async.commit_group;"); }
template <int NN> __device__ __forceinline__ void cpawait() {
    asm volatile("cp.async.wait_group %0;" :: "n"(NN));
}

// host/device shared smem-size formulas (must mirror kernel constexprs!)
__host__ __device__ constexpr int c2_stride(int KH, int KW, int S, int OW, int OHB, int CIB) {
    int TWID = (OW - 1) * S + KW; int TWIDP = (TWID + 3) & ~3;
    int TROWS = (OHB - 1) * S + KH;
    return CIB * TROWS * TWIDP * 4 + 16 * (CIB * KH * KW + 1) * 8;
}
__host__ __device__ constexpr int c2_smem(int KH, int KW, int S, int OW, int OHB, int CIB, int CI) {
    return (CI > CIB ? 2 : 1) * c2_stride(KH, KW, S, OW, OHB, CIB);
}
__host__ __device__ constexpr int ct_stride(int OW, int OHB, int CIB, int COB) {
    int TWIDP = ((OW / 2 + 2) + 3) & ~3;
    return CIB * (OHB / 2 + 2) * TWIDP * 4 + (COB / 2) * (CIB * 16 + 1) * 8;
}

// ---------------------------------------------------------------------------
// Conv2: cp.async double-buffered, CIB-grouped staging, f32x2 inner loop.
// Block 256 thr: cog=tid&3 (4 co-groups of COT=4 ch), spat = (OW/8)*OHB = 64.
// ---------------------------------------------------------------------------
template <int KH, int KW, int S, int P, int OWt, int OHB, int CIB,
          bool RIN, bool ROUT, bool ADD>
__global__ void __launch_bounds__(256) conv2(
    const float* __restrict__ in, const float* __restrict__ wt,
    const float* __restrict__ bias, const float* __restrict__ res,
    float* __restrict__ out, int N, int CI, int CO, int IH, int IW, int OH)
{
    constexpr int OW = OWt;
    constexpr int TAPS = KH * KW;
    constexpr int TWID = (OW - 1) * S + KW;
    constexpr int TWIDP = (TWID + 3) & ~3;
    constexpr int TROWS = (OHB - 1) * S + KH;
    constexpr int TILE_CI = TROWS * TWIDP;
    constexpr int TILE = CIB * TILE_CI;
    constexpr int WSTR = CIB * TAPS + 1;          // ull, padded vs bank conflicts
    constexpr int STRIDEB = TILE * 4 + 16 * WSTR * 8;
    constexpr int LW = 7 * S + KW;
    constexpr int OWG8 = OW / 8;
    static_assert(OWG8 * OHB * 4 == 256, "block mapping");

    extern __shared__ char smx[];

    const int RB = OH / OHB;
    const int n = blockIdx.x / RB;
    const int rb = blockIdx.x % RB;
    const int oy0 = rb * OHB;
    const int co0 = blockIdx.y * 16;
    const int tid = threadIdx.x;
    const int cog = tid & 3;
    const int spat = tid >> 2;
    const int owg = spat % OWG8;
    const int ohr = spat / OWG8;
    const int co_l = cog * 4;
    const int iy0 = oy0 * S - P;

    const float* inn = in + (long)n * CI * IH * IW;
    const int G = CI / CIB;

    ull acc[4][4];
#pragma unroll
    for (int c = 0; c < 4; c++) {
        const float b = __ldg(bias + co0 + co_l + c);
        const ull bb = pk2(b, b);
#pragma unroll
        for (int m = 0; m < 4; m++) acc[c][m] = bb;
    }

    // ---- staging helper (inlined via lambda-free macro-style function) ----
    auto stage = [&](int gidx, int bi) {
        char* buf = smx + bi * STRIDEB;
        float* tile = (float*)buf;
        ull* wp = (ull*)(buf + TILE * 4);
        const uint32_t tadr = (uint32_t)__cvta_generic_to_shared(tile);
        const int ci0 = gidx * CIB;
        for (int i = tid; i < TILE; i += 256) {
            const int ci_l = i / TILE_CI;
            const int rem = i - ci_l * TILE_CI;
            const int r = rem / TWIDP, c = rem - r * TWIDP;
            const int iy = iy0 + r, ix = c - P;
            const bool ok = (c < TWID) & (iy >= 0) & (iy < IH) & (ix >= 0) & (ix < IW);
            const float* src = ok ? inn + ((long)(ci0 + ci_l) * IH + iy) * IW + ix : inn;
            cpa4(tadr + 4u * (uint32_t)i, src, ok);
        }
        for (int i = tid; i < 16 * CIB * TAPS; i += 256) {
            const int c = i / (CIB * TAPS);
            const int rem = i - c * (CIB * TAPS);
            const float w = __ldg(wt + ((long)(co0 + c) * CI + ci0 + rem / TAPS) * TAPS + rem % TAPS);
            wp[c * WSTR + rem] = pk2(w, w);
        }
    };

    stage(0, 0);
    cpacommit();

    for (int g = 0; g < G; g++) {
        const int bi = g & 1;
        if (g + 1 < G) { stage(g + 1, bi ^ 1); cpacommit(); cpawait<1>(); }
        else cpawait<0>();
        __syncthreads();
        const float* tb = (const float*)(smx + bi * STRIDEB);
        const ull* wb = (const ull*)(smx + bi * STRIDEB + TILE * 4);
#pragma unroll 1
        for (int ci_l = 0; ci_l < CIB; ci_l++) {
            const float* tci = tb + ci_l * TILE_CI;
#pragma unroll
            for (int kh = 0; kh < KH; kh++) {
                const float* trow = tci + (ohr * S + kh) * TWIDP + owg * 8 * S;
                float ir[LW];
#pragma unroll
                for (int v = 0; v < LW / 4; v++) {
                    const float4 q = reinterpret_cast<const float4*>(trow)[v];
                    ir[4 * v + 0] = q.x; ir[4 * v + 1] = q.y;
                    ir[4 * v + 2] = q.z; ir[4 * v + 3] = q.w;
                }
#pragma unroll
                for (int l = (LW / 4) * 4; l < LW; l++) ir[l] = trow[l];
                if (RIN) {
#pragma unroll
                    for (int l = 0; l < LW; l++) ir[l] = fmaxf(ir[l], 0.f);
                }
#pragma unroll
                for (int kw = 0; kw < KW; kw++) {
                    ull p[4];
#pragma unroll
                    for (int m = 0; m < 4; m++)
                        p[m] = pk2(ir[2 * m * S + kw], ir[(2 * m + 1) * S + kw]);
#pragma unroll
                    for (int c = 0; c < 4; c++) {
                        const ull w2 = wb[(co_l + c) * WSTR + ci_l * TAPS + kh * KW + kw];
#pragma unroll
                        for (int m = 0; m < 4; m++) fma2(acc[c][m], p[m], w2);
                    }
                }
            }
        }
        __syncthreads();
    }

    const int oy = oy0 + ohr;
    const long chs = (long)OH * OW;
    const long ob = (((long)n * CO + co0 + co_l) * OH + oy) * OW + owg * 8;
#pragma unroll
    for (int c = 0; c < 4; c++) {
        float o[8];
#pragma unroll
        for (int m = 0; m < 4; m++) {
            const float2 t = upk(acc[c][m]);
            o[2 * m] = t.x; o[2 * m + 1] = t.y;
        }
        float* op = out + ob + c * chs;
        if (ADD) {
            const float* rp = res + ob + c * chs;
#pragma unroll
            for (int j = 0; j < 8; j++) o[j] += __ldg(rp + j);
        }
        if (ROUT) {
#pragma unroll
            for (int j = 0; j < 8; j++) o[j] = fmaxf(o[j], 0.f);
        }
        reinterpret_cast<float4*>(op)[0] = make_float4(o[0], o[1], o[2], o[3]);
        reinterpret_cast<float4*>(op)[1] = make_float4(o[4], o[5], o[6], o[7]);
    }
}

// ---------------------------------------------------------------------------
// ConvTranspose2d k=4 s=2 p=1, cp.async pipelined, f32x2 packed along co-pairs.
// ---------------------------------------------------------------------------
template <int OWt, int OHB, int CIB, int COB, int COT, bool RIN, bool ROUT>
__global__ void __launch_bounds__(256) convt2(
    const float* __restrict__ in, const float* __restrict__ wt,
    const float* __restrict__ bias, float* __restrict__ out,
    int N, int CI, int CO, int IH, int IW, int OH)
{
    constexpr int OW = OWt;
    constexpr int COG = COB / COT;
    constexpr int CP = COT / 2;
    constexpr int TROWS = OHB / 2 + 2;
    constexpr int TWID = OW / 2 + 2;
    constexpr int TWIDP = (TWID + 3) & ~3;
    constexpr int TILE_CI = TROWS * TWIDP;
    constexpr int TILE = CIB * TILE_CI;
    constexpr int WTSTR = CIB * 16 + 1;           // ull
    constexpr int STRIDEB = TILE * 4 + (COB / 2) * WTSTR * 8;
    constexpr int OWG8 = OW / 8;
    static_assert(OWG8 * OHB * COG == 256, "block mapping");

    extern __shared__ char smx[];

    const int RB = OH / OHB;
    const int n = blockIdx.x / RB;
    const int rb = blockIdx.x % RB;
    const int oy0 = rb * OHB;
    const int co0 = blockIdx.y * COB;
    const int tid = threadIdx.x;
    const int cog = tid % COG;
    const int spat = tid / COG;
    const int owg = spat % OWG8;
    const int ohr = spat / OWG8;
    const int co_l = cog * COT;
    const int iy0 = oy0 / 2 - 1;
    const int oy = oy0 + ohr;
    const int ky0 = (oy + 1) & 1;

    const float* inn = in + (long)n * CI * IH * IW;
    const int G = CI / CIB;

    ull accp[CP][8];
#pragma unroll
    for (int q = 0; q < CP; q++) {
        const int c0 = co0 + co_l + 2 * q, c1 = c0 + 1;
        const float b0 = (c0 < CO) ? __ldg(bias + c0) : 0.f;
        const float b1 = (c1 < CO) ? __ldg(bias + c1) : 0.f;
        const ull bb = pk2(b0, b1);
#pragma unroll
        for (int j = 0; j < 8; j++) accp[q][j] = bb;
    }

    auto stage = [&](int gidx, int bi) {
        char* buf = smx + bi * STRIDEB;
        float* tile = (float*)buf;
        ull* wp = (ull*)(buf + TILE * 4);
        const uint32_t tadr = (uint32_t)__cvta_generic_to_shared(tile);
        const int ci0 = gidx * CIB;
        for (int i = tid; i < TILE; i += 256) {
            const int ci_l = i / TILE_CI;
            const int rem = i - ci_l * TILE_CI;
            const int r = rem / TWIDP, c = rem - r * TWIDP;
            const int iy = iy0 + r, ix = c - 1;
            const bool ok = (c < TWID) & (iy >= 0) & (iy < IH) & (ix >= 0) & (ix < IW);
            const float* src = ok ? inn + ((long)(ci0 + ci_l) * IH + iy) * IW + ix : inn;
            cpa4(tadr + 4u * (uint32_t)i, src, ok);
        }
        for (int i = tid; i < (COB / 2) * CIB * 16; i += 256) {
            const int cpg = i / (CIB * 16);
            const int rem = i - cpg * (CIB * 16);
            const int ci_l = rem >> 4, tap = rem & 15;
            const int c0 = co0 + 2 * cpg, c1 = c0 + 1;
            const float w0 = (c0 < CO) ? __ldg(wt + ((long)(ci0 + ci_l) * CO + c0) * 16 + tap) : 0.f;
            const float w1 = (c1 < CO) ? __ldg(wt + ((long)(ci0 + ci_l) * CO + c1) * 16 + tap) : 0.f;
            wp[cpg * WTSTR + rem] = pk2(w0, w1);
        }
    };

    stage(0, 0);
    cpacommit();

    for (int g = 0; g < G; g++) {
        const int bi = g & 1;
        if (g + 1 < G) { stage(g + 1, bi ^ 1); cpacommit(); cpawait<1>(); }
        else cpawait<0>();
        __syncthreads();
        const float* tb = (const float*)(smx + bi * STRIDEB);
        const ull* wb = (const ull*)(smx + bi * STRIDEB + TILE * 4);
#pragma unroll 1
        for (int ci_l = 0; ci_l < CIB; ci_l++) {
            const float* tci = tb + ci_l * TILE_CI;
#pragma unroll
            for (int t2 = 0; t2 < 2; t2++) {
                const int ky = ky0 + 2 * t2;
                const int r = ((oy + 1 - ky) >> 1) - iy0;
                const float* trow = tci + r * TWIDP + owg * 4;
                float ir[6];
                {
                    const float4 q4 = *reinterpret_cast<const float4*>(trow);
                    ir[0] = q4.x; ir[1] = q4.y; ir[2] = q4.z; ir[3] = q4.w;
                    ir[4] = trow[4]; ir[5] = trow[5];
                }
                if (RIN) {
#pragma unroll
                    for (int l = 0; l < 6; l++) ir[l] = fmaxf(ir[l], 0.f);
                }
#pragma unroll
                for (int kx = 0; kx < 4; kx++) {
                    const int ph = (kx + 1) & 1;
                    const int dt = (kx == 0) ? 1 : ((kx == 3) ? -1 : 0);
                    ull vv[4];
#pragma unroll
                    for (int m = 0; m < 4; m++) {
                        const float v = ir[m + dt + 1];
                        vv[m] = pk2(v, v);
                    }
#pragma unroll
                    for (int q = 0; q < CP; q++) {
                        const ull w2 = wb[(cog * CP + q) * WTSTR + ci_l * 16 + ky * 4 + kx];
#pragma unroll
                        for (int m = 0; m < 4; m++) fma2(accp[q][2 * m + ph], vv[m], w2);
                    }
                }
            }
        }
        __syncthreads();
    }

    const long chs = (long)OH * OW;
#pragma unroll
    for (int q = 0; q < CP; q++) {
        float o0[8], o1[8];
#pragma unroll
        for (int j = 0; j < 8; j++) {
            const float2 t = upk(accp[q][j]);
            o0[j] = ROUT ? fmaxf(t.x, 0.f) : t.x;
            o1[j] = ROUT ? fmaxf(t.y, 0.f) : t.y;
        }
        const int c0 = co0 + co_l + 2 * q, c1 = c0 + 1;
        if (c0 < CO) {
            float* op = out + (((long)n * CO + c0) * OH + oy) * OW + owg * 8;
            reinterpret_cast<float4*>(op)[0] = make_float4(o0[0], o0[1], o0[2], o0[3]);
            reinterpret_cast<float4*>(op)[1] = make_float4(o0[4], o0[5], o0[6], o0[7]);
        }
        if (c1 < CO) {
            float* op = out + (((long)n * CO + c1) * OH + oy) * OW + owg * 8;
            reinterpret_cast<float4*>(op)[0] = make_float4(o1[0], o1[1], o1[2], o1[3]);
            reinterpret_cast<float4*>(op)[1] = make_float4(o1[4], o1[5], o1[6], o1[7]);
        }
    }
}

// ---------------------------------------------------------------------------
// VQ: transposed smem codebook tile (LDS.128) + f32x2 dot, per-tile norms.
// dist = ||c||^2 - 2 f.c  (||f||^2 constant per pixel); first-min on ties.
// ---------------------------------------------------------------------------
__global__ void __launch_bounds__(256) vqk2(
    const float* __restrict__ z, const float* __restrict__ cb,
    float* __restrict__ q)
{
    constexpr int NPIX = 4096;
    __shared__ float cbs[128][68];
    __shared__ float cns[128];
    const int tid = threadIdx.x;
    const int p = blockIdx.x * 256 + tid;
    const int b = p >> 12;
    const int pix = p & 4095;

    const float* zp = z + (long)b * 64 * NPIX + pix;
    float f[64];
#pragma unroll
    for (int d = 0; d < 64; d++) f[d] = zp[(long)d * NPIX];
    ull fp[32];
#pragma unroll
    for (int i = 0; i < 32; i++) fp[i] = pk2(f[2 * i], f[2 * i + 1]);

    float best = 3.4e38f;
    int bidx = 0;
    for (int t = 0; t < 4; t++) {
        __syncthreads();
        for (int i = tid; i < 8192; i += 256) {
            const int d = i >> 7, kk = i & 127;
            cbs[kk][d] = __ldg(cb + d * 512 + t * 128 + kk);
        }
        __syncthreads();
        if (tid < 128) {
            const float* row = cbs[tid];
            float s = 0.f;
#pragma unroll
            for (int d = 0; d < 64; d++) s += row[d] * row[d];
            cns[tid] = s;
        }
        __syncthreads();
        for (int kk = 0; kk < 128; kk++) {
            const ulonglong2* row = reinterpret_cast<const ulonglong2*>(cbs[kk]);
            ull a0 = 0, a1 = 0, a2 = 0, a3 = 0;
#pragma unroll
            for (int i = 0; i < 16; i += 2) {
                const ulonglong2 u = row[i];
                const ulonglong2 v = row[i + 1];
                fma2(a0, u.x, fp[2 * i + 0]);
                fma2(a1, u.y, fp[2 * i + 1]);
                fma2(a2, v.x, fp[2 * i + 2]);
                fma2(a3, v.y, fp[2 * i + 3]);
            }
            const float2 x0 = upk(a0), x1 = upk(a1), x2 = upk(a2), x3 = upk(a3);
            const float dot = ((x0.x + x0.y) + (x1.x + x1.y)) + ((x2.x + x2.y) + (x3.x + x3.y));
            const float dist = cns[kk] - 2.f * dot;
            if (dist < best) { best = dist; bidx = t * 128 + kk; }
        }
    }
    float* qp = q + (long)b * 64 * NPIX + pix;
#pragma unroll
    for (int d = 0; d < 64; d++) qp[(long)d * NPIX] = __ldg(cb + d * 512 + bidx);
}

// ---------------------------------------------------------------------------
// Host launcher
// ---------------------------------------------------------------------------
extern "C" void kernel_launch(void* const* d_in, const int* in_sizes, int n_in,
                              void* d_out, int out_size)
{
    (void)in_sizes; (void)n_in; (void)out_size;
    const float* x        = (const float*)d_in[0];
    const float* enc_w0   = (const float*)d_in[1];
    const float* enc_b0   = (const float*)d_in[2];
    const float* enc_w1   = (const float*)d_in[3];
    const float* enc_b1   = (const float*)d_in[4];
    const float* enc_wf   = (const float*)d_in[5];
    const float* enc_bf   = (const float*)d_in[6];
    const float* enc_rw1  = (const float*)d_in[7];
    const float* enc_rb1  = (const float*)d_in[8];
    const float* enc_rw2  = (const float*)d_in[9];
    const float* enc_rb2  = (const float*)d_in[10];
    const float* pre_w    = (const float*)d_in[11];
    const float* pre_b    = (const float*)d_in[12];
    const float* codebook = (const float*)d_in[13];
    const float* dec_w    = (const float*)d_in[14];
    const float* dec_b    = (const float*)d_in[15];
    const float* dec_rw1  = (const float*)d_in[16];
    const float* dec_rb1  = (const float*)d_in[17];
    const float* dec_rw2  = (const float*)d_in[18];
    const float* dec_rb2  = (const float*)d_in[19];
    const float* up_w0    = (const float*)d_in[20];
    const float* up_b0    = (const float*)d_in[21];
    const float* up_w1    = (const float*)d_in[22];
    const float* up_b1    = (const float*)d_in[23];
    float* out = (float*)d_out;

    float *pA, *pB, *pC, *pT, *pZ, *pQ;
    cudaGetSymbolAddress((void**)&pA, g_bufA);
    cudaGetSymbolAddress((void**)&pB, g_bufB);
    cudaGetSymbolAddress((void**)&pC, g_bufC);
    cudaGetSymbolAddress((void**)&pT, g_bufT);
    cudaGetSymbolAddress((void**)&pZ, g_bufZ);
    cudaGetSymbolAddress((void**)&pQ, g_bufQ);

    const int N = 16;

    // opt-in smem sizes (>48KB) — attribute set is idempotent, not a stream op
    {
        cudaFuncSetAttribute((const void*)conv2<4,4,2,1,64,8,4,false,true,false>,
            cudaFuncAttributeMaxDynamicSharedMemorySize, c2_smem(4,4,2,64,8,4,64));
        cudaFuncSetAttribute((const void*)conv2<3,3,1,1,64,8,8,false,false,false>,
            cudaFuncAttributeMaxDynamicSharedMemorySize, c2_smem(3,3,1,64,8,8,128));
        cudaFuncSetAttribute((const void*)conv2<3,3,1,1,64,8,8,true,false,false>,
            cudaFuncAttributeMaxDynamicSharedMemorySize, c2_smem(3,3,1,64,8,8,128));
        cudaFuncSetAttribute((const void*)convt2<256,8,8,4,4,false,false>,
            cudaFuncAttributeMaxDynamicSharedMemorySize, 2 * ct_stride(256,8,8,4));
    }

    // --- Encoder ---
    // L1: x[16,3,256,256] -> relu -> bufA[16,64,128,128]
    conv2<4,4,2,1,128,4,3,false,true,false>
        <<<dim3(N * 32, 4), 256, c2_smem(4,4,2,128,4,3,3)>>>(
        x, enc_w0, enc_b0, nullptr, pA, N, 3, 64, 256, 256, 128);
    // L2: bufA -> relu -> bufB[16,128,64,64]
    conv2<4,4,2,1,64,8,4,false,true,false>
        <<<dim3(N * 8, 8), 256, c2_smem(4,4,2,64,8,4,64)>>>(
        pA, enc_w1, enc_b1, nullptr, pB, N, 64, 128, 128, 128, 64);
    // enc_wf: bufB -> bufC
    conv2<3,3,1,1,64,8,8,false,false,false>
        <<<dim3(N * 8, 8), 256, c2_smem(3,3,1,64,8,8,128)>>>(
        pB, enc_wf, enc_bf, nullptr, pC, N, 128, 128, 64, 64, 64);
    // enc res blocks
    for (int i = 0; i < 2; i++) {
        conv2<3,3,1,1,64,8,8,true,false,false>
            <<<dim3(N * 8, 2), 256, c2_smem(3,3,1,64,8,8,128)>>>(
            pC, enc_rw1 + (long)i * 32 * 128 * 9, enc_rb1 + i * 32, nullptr, pT,
            N, 128, 32, 64, 64, 64);
        conv2<1,1,1,0,64,8,8,true,false,true>
            <<<dim3(N * 8, 8), 256, c2_smem(1,1,1,64,8,8,32)>>>(
            pT, enc_rw2 + (long)i * 128 * 32, enc_rb2 + i * 128, pC, pC,
            N, 32, 128, 64, 64, 64);
    }
    // pre: relu-in, bufC -> bufZ[16,64,64,64]
    conv2<1,1,1,0,64,8,8,true,false,false>
        <<<dim3(N * 8, 4), 256, c2_smem(1,1,1,64,8,8,128)>>>(
        pC, pre_w, pre_b, nullptr, pZ, N, 128, 64, 64, 64, 64);

    // --- VQ ---
    vqk2<<<256, 256>>>(pZ, codebook, pQ);

    // --- Decoder ---
    conv2<3,3,1,1,64,8,8,false,false,false>
        <<<dim3(N * 8, 8), 256, c2_smem(3,3,1,64,8,8,64)>>>(
        pQ, dec_w, dec_b, nullptr, pB, N, 64, 128, 64, 64, 64);
    for (int i = 0; i < 2; i++) {
        conv2<3,3,1,1,64,8,8,true,false,false>
            <<<dim3(N * 8, 2), 256, c2_smem(3,3,1,64,8,8,128)>>>(
            pB, dec_rw1 + (long)i * 32 * 128 * 9, dec_rb1 + i * 32, nullptr, pT,
            N, 128, 32, 64, 64, 64);
        conv2<1,1,1,0,64,8,8,true,false,true>
            <<<dim3(N * 8, 8), 256, c2_smem(1,1,1,64,8,8,32)>>>(
            pT, dec_rw2 + (long)i * 128 * 32, dec_rb2 + i * 128, pB, pB,
            N, 32, 128, 64, 64, 64);
    }
    // up0: relu-in + relu-out, bufB[16,128,64,64] -> bufA[16,64,128,128]
    convt2<128,4,8,16,4,true,true>
        <<<dim3(N * 32, 4), 256, 2 * ct_stride(128,4,8,16)>>>(
        pB, up_w0, up_b0, pA, N, 128, 64, 64, 64, 128);
    // up1: bufA[16,64,128,128] -> out[16,3,256,256]  (COB=4 padded, CO=3 guarded)
    convt2<256,8,8,4,4,false,false>
        <<<dim3(N * 32, 1), 256, 2 * ct_stride(256,8,8,4)>>>(
        pA, up_w1, up_b1, out, N, 64, 3, 128, 128, 256);
}

// round 4
// speedup vs baseline: 3.9949x; 1.0564x over previous
#include <cuda_runtime.h>
#include <cstdint>

typedef unsigned long long ull;

// ---------------------------------------------------------------------------
// Static scratch buffers (no allocation allowed)
// ---------------------------------------------------------------------------
__device__ float g_bufA[16 * 64 * 128 * 128];
__device__ float g_bufB[16 * 128 * 64 * 64];
__device__ float g_bufC[16 * 128 * 64 * 64];
__device__ float g_bufT[16 * 32 * 64 * 64];
__device__ float g_bufZ[16 * 64 * 64 * 64];
__device__ float g_bufQ[16 * 64 * 64 * 64];

// ---------------------------------------------------------------------------
// f32x2 + cp.async helpers
// ---------------------------------------------------------------------------
__device__ __forceinline__ ull pk2(float lo, float hi) {
    ull r; asm("mov.b64 %0, {%1, %2};" : "=l"(r) : "f"(lo), "f"(hi)); return r;
}
__device__ __forceinline__ void fma2(ull& a, ull v, ull w) {
    asm("fma.rn.f32x2 %0, %1, %2, %0;" : "+l"(a) : "l"(v), "l"(w));
}
__device__ __forceinline__ float2 upk(ull v) {
    float2 r; asm("mov.b64 {%0, %1}, %2;" : "=f"(r.x), "=f"(r.y) : "l"(v)); return r;
}
__device__ __forceinline__ void cpa4(uint32_t s, const float* g, bool ok) {
    asm volatile("cp.async.ca.shared.global [%0], [%1], 4, %2;"
                 :: "r"(s), "l"(g), "r"(ok ? 4u : 0u));
}
__device__ __forceinline__ void cpacommit() { asm volatile("cp.async.commit_group;"); }
template <int NN> __device__ __forceinline__ void cpawait() {
    asm volatile("cp.async.wait_group %0;" :: "n"(NN));
}

// host/device shared smem-size formulas (must mirror kernel constexprs!)
__host__ __device__ constexpr int c2_stride(int KH, int KW, int S, int OW, int OHB, int CIB) {
    int TWID = (OW - 1) * S + KW; int TWIDP = (TWID + 3) & ~3;
    int TROWS = (OHB - 1) * S + KH;
    return CIB * TROWS * TWIDP * 4 + 16 * (CIB * KH * KW + 1) * 8;
}
__host__ __device__ constexpr int c2_smem(int KH, int KW, int S, int OW, int OHB, int CIB, int CI) {
    return (CI > CIB ? 2 : 1) * c2_stride(KH, KW, S, OW, OHB, CIB);
}
__host__ __device__ constexpr int ct_stride(int OW, int OHB, int CIB, int COB) {
    int TWIDP = ((OW / 2 + 2) + 3) & ~3;
    return CIB * (OHB / 2 + 2) * TWIDP * 4 + (COB / 2) * (CIB * 16 + 1) * 8;
}

// ---------------------------------------------------------------------------
// Conv2: cp.async double-buffered, CIB-grouped staging, f32x2 inner loop.
// Block 256 thr: cog=tid&3 (4 co-groups of COT=4 ch), spat = (OW/8)*OHB = 64.
// ---------------------------------------------------------------------------
template <int KH, int KW, int S, int P, int OWt, int OHB, int CIB,
          bool RIN, bool ROUT, bool ADD>
__global__ void __launch_bounds__(256) conv2(
    const float* __restrict__ in, const float* __restrict__ wt,
    const float* __restrict__ bias, const float* __restrict__ res,
    float* __restrict__ out, int N, int CI, int CO, int IH, int IW, int OH)
{
    constexpr int OW = OWt;
    constexpr int TAPS = KH * KW;
    constexpr int TWID = (OW - 1) * S + KW;
    constexpr int TWIDP = (TWID + 3) & ~3;
    constexpr int TROWS = (OHB - 1) * S + KH;
    constexpr int TILE_CI = TROWS * TWIDP;
    constexpr int TILE = CIB * TILE_CI;
    constexpr int WSTR = CIB * TAPS + 1;          // ull, padded vs bank conflicts
    constexpr int STRIDEB = TILE * 4 + 16 * WSTR * 8;
    constexpr int LW = 7 * S + KW;
    constexpr int OWG8 = OW / 8;
    static_assert(OWG8 * OHB * 4 == 256, "block mapping");

    extern __shared__ char smx[];

    const int RB = OH / OHB;
    const int n = blockIdx.x / RB;
    const int rb = blockIdx.x % RB;
    const int oy0 = rb * OHB;
    const int co0 = blockIdx.y * 16;
    const int tid = threadIdx.x;
    const int cog = tid & 3;
    const int spat = tid >> 2;
    const int owg = spat % OWG8;
    const int ohr = spat / OWG8;
    const int co_l = cog * 4;
    const int iy0 = oy0 * S - P;

    const float* inn = in + (long)n * CI * IH * IW;
    const int G = CI / CIB;

    ull acc[4][4];
#pragma unroll
    for (int c = 0; c < 4; c++) {
        const float b = __ldg(bias + co0 + co_l + c);
        const ull bb = pk2(b, b);
#pragma unroll
        for (int m = 0; m < 4; m++) acc[c][m] = bb;
    }

    // ---- staging helper (inlined via lambda-free macro-style function) ----
    auto stage = [&](int gidx, int bi) {
        char* buf = smx + bi * STRIDEB;
        float* tile = (float*)buf;
        ull* wp = (ull*)(buf + TILE * 4);
        const uint32_t tadr = (uint32_t)__cvta_generic_to_shared(tile);
        const int ci0 = gidx * CIB;
        for (int i = tid; i < TILE; i += 256) {
            const int ci_l = i / TILE_CI;
            const int rem = i - ci_l * TILE_CI;
            const int r = rem / TWIDP, c = rem - r * TWIDP;
            const int iy = iy0 + r, ix = c - P;
            const bool ok = (c < TWID) & (iy >= 0) & (iy < IH) & (ix >= 0) & (ix < IW);
            const float* src = ok ? inn + ((long)(ci0 + ci_l) * IH + iy) * IW + ix : inn;
            cpa4(tadr + 4u * (uint32_t)i, src, ok);
        }
        for (int i = tid; i < 16 * CIB * TAPS; i += 256) {
            const int c = i / (CIB * TAPS);
            const int rem = i - c * (CIB * TAPS);
            const float w = __ldg(wt + ((long)(co0 + c) * CI + ci0 + rem / TAPS) * TAPS + rem % TAPS);
            wp[c * WSTR + rem] = pk2(w, w);
        }
    };

    stage(0, 0);
    cpacommit();

    for (int g = 0; g < G; g++) {
        const int bi = g & 1;
        if (g + 1 < G) { stage(g + 1, bi ^ 1); cpacommit(); cpawait<1>(); }
        else cpawait<0>();
        __syncthreads();
        const float* tb = (const float*)(smx + bi * STRIDEB);
        const ull* wb = (const ull*)(smx + bi * STRIDEB + TILE * 4);
#pragma unroll 1
        for (int ci_l = 0; ci_l < CIB; ci_l++) {
            const float* tci = tb + ci_l * TILE_CI;
#pragma unroll
            for (int kh = 0; kh < KH; kh++) {
                const float* trow = tci + (ohr * S + kh) * TWIDP + owg * 8 * S;
                float ir[LW];
#pragma unroll
                for (int v = 0; v < LW / 4; v++) {
                    const float4 q = reinterpret_cast<const float4*>(trow)[v];
                    ir[4 * v + 0] = q.x; ir[4 * v + 1] = q.y;
                    ir[4 * v + 2] = q.z; ir[4 * v + 3] = q.w;
                }
#pragma unroll
                for (int l = (LW / 4) * 4; l < LW; l++) ir[l] = trow[l];
                if (RIN) {
#pragma unroll
                    for (int l = 0; l < LW; l++) ir[l] = fmaxf(ir[l], 0.f);
                }
#pragma unroll
                for (int kw = 0; kw < KW; kw++) {
                    ull p[4];
#pragma unroll
                    for (int m = 0; m < 4; m++)
                        p[m] = pk2(ir[2 * m * S + kw], ir[(2 * m + 1) * S + kw]);
#pragma unroll
                    for (int c = 0; c < 4; c++) {
                        const ull w2 = wb[(co_l + c) * WSTR + ci_l * TAPS + kh * KW + kw];
#pragma unroll
                        for (int m = 0; m < 4; m++) fma2(acc[c][m], p[m], w2);
                    }
                }
            }
        }
        __syncthreads();
    }

    const int oy = oy0 + ohr;
    const long chs = (long)OH * OW;
    const long ob = (((long)n * CO + co0 + co_l) * OH + oy) * OW + owg * 8;
#pragma unroll
    for (int c = 0; c < 4; c++) {
        float o[8];
#pragma unroll
        for (int m = 0; m < 4; m++) {
            const float2 t = upk(acc[c][m]);
            o[2 * m] = t.x; o[2 * m + 1] = t.y;
        }
        float* op = out + ob + c * chs;
        if (ADD) {
            const float* rp = res + ob + c * chs;
#pragma unroll
            for (int j = 0; j < 8; j++) o[j] += __ldg(rp + j);
        }
        if (ROUT) {
#pragma unroll
            for (int j = 0; j < 8; j++) o[j] = fmaxf(o[j], 0.f);
        }
        reinterpret_cast<float4*>(op)[0] = make_float4(o[0], o[1], o[2], o[3]);
        reinterpret_cast<float4*>(op)[1] = make_float4(o[4], o[5], o[6], o[7]);
    }
}

// ---------------------------------------------------------------------------
// ConvTranspose2d k=4 s=2 p=1, cp.async pipelined, f32x2 packed along co-pairs.
// ---------------------------------------------------------------------------
template <int OWt, int OHB, int CIB, int COB, int COT, bool RIN, bool ROUT>
__global__ void __launch_bounds__(256) convt2(
    const float* __restrict__ in, const float* __restrict__ wt,
    const float* __restrict__ bias, float* __restrict__ out,
    int N, int CI, int CO, int IH, int IW, int OH)
{
    constexpr int OW = OWt;
    constexpr int COG = COB / COT;
    constexpr int CP = COT / 2;
    constexpr int TROWS = OHB / 2 + 2;
    constexpr int TWID = OW / 2 + 2;
    constexpr int TWIDP = (TWID + 3) & ~3;
    constexpr int TILE_CI = TROWS * TWIDP;
    constexpr int TILE = CIB * TILE_CI;
    constexpr int WTSTR = CIB * 16 + 1;           // ull
    constexpr int STRIDEB = TILE * 4 + (COB / 2) * WTSTR * 8;
    constexpr int OWG8 = OW / 8;
    static_assert(OWG8 * OHB * COG == 256, "block mapping");

    extern __shared__ char smx[];

    const int RB = OH / OHB;
    const int n = blockIdx.x / RB;
    const int rb = blockIdx.x % RB;
    const int oy0 = rb * OHB;
    const int co0 = blockIdx.y * COB;
    const int tid = threadIdx.x;
    const int cog = tid % COG;
    const int spat = tid / COG;
    const int owg = spat % OWG8;
    const int ohr = spat / OWG8;
    const int co_l = cog * COT;
    const int iy0 = oy0 / 2 - 1;
    const int oy = oy0 + ohr;
    const int ky0 = (oy + 1) & 1;

    const float* inn = in + (long)n * CI * IH * IW;
    const int G = CI / CIB;

    ull accp[CP][8];
#pragma unroll
    for (int q = 0; q < CP; q++) {
        const int c0 = co0 + co_l + 2 * q, c1 = c0 + 1;
        const float b0 = (c0 < CO) ? __ldg(bias + c0) : 0.f;
        const float b1 = (c1 < CO) ? __ldg(bias + c1) : 0.f;
        const ull bb = pk2(b0, b1);
#pragma unroll
        for (int j = 0; j < 8; j++) accp[q][j] = bb;
    }

    auto stage = [&](int gidx, int bi) {
        char* buf = smx + bi * STRIDEB;
        float* tile = (float*)buf;
        ull* wp = (ull*)(buf + TILE * 4);
        const uint32_t tadr = (uint32_t)__cvta_generic_to_shared(tile);
        const int ci0 = gidx * CIB;
        for (int i = tid; i < TILE; i += 256) {
            const int ci_l = i / TILE_CI;
            const int rem = i - ci_l * TILE_CI;
            const int r = rem / TWIDP, c = rem - r * TWIDP;
            const int iy = iy0 + r, ix = c - 1;
            const bool ok = (c < TWID) & (iy >= 0) & (iy < IH) & (ix >= 0) & (ix < IW);
            const float* src = ok ? inn + ((long)(ci0 + ci_l) * IH + iy) * IW + ix : inn;
            cpa4(tadr + 4u * (uint32_t)i, src, ok);
        }
        for (int i = tid; i < (COB / 2) * CIB * 16; i += 256) {
            const int cpg = i / (CIB * 16);
            const int rem = i - cpg * (CIB * 16);
            const int ci_l = rem >> 4, tap = rem & 15;
            const int c0 = co0 + 2 * cpg, c1 = c0 + 1;
            const float w0 = (c0 < CO) ? __ldg(wt + ((long)(ci0 + ci_l) * CO + c0) * 16 + tap) : 0.f;
            const float w1 = (c1 < CO) ? __ldg(wt + ((long)(ci0 + ci_l) * CO + c1) * 16 + tap) : 0.f;
            wp[cpg * WTSTR + rem] = pk2(w0, w1);
        }
    };

    stage(0, 0);
    cpacommit();

    for (int g = 0; g < G; g++) {
        const int bi = g & 1;
        if (g + 1 < G) { stage(g + 1, bi ^ 1); cpacommit(); cpawait<1>(); }
        else cpawait<0>();
        __syncthreads();
        const float* tb = (const float*)(smx + bi * STRIDEB);
        const ull* wb = (const ull*)(smx + bi * STRIDEB + TILE * 4);
#pragma unroll 1
        for (int ci_l = 0; ci_l < CIB; ci_l++) {
            const float* tci = tb + ci_l * TILE_CI;
#pragma unroll
            for (int t2 = 0; t2 < 2; t2++) {
                const int ky = ky0 + 2 * t2;
                const int r = ((oy + 1 - ky) >> 1) - iy0;
                const float* trow = tci + r * TWIDP + owg * 4;
                float ir[6];
                {
                    const float4 q4 = *reinterpret_cast<const float4*>(trow);
                    ir[0] = q4.x; ir[1] = q4.y; ir[2] = q4.z; ir[3] = q4.w;
                    ir[4] = trow[4]; ir[5] = trow[5];
                }
                if (RIN) {
#pragma unroll
                    for (int l = 0; l < 6; l++) ir[l] = fmaxf(ir[l], 0.f);
                }
#pragma unroll
                for (int kx = 0; kx < 4; kx++) {
                    const int ph = (kx + 1) & 1;
                    const int dt = (kx == 0) ? 1 : ((kx == 3) ? -1 : 0);
                    ull vv[4];
#pragma unroll
                    for (int m = 0; m < 4; m++) {
                        const float v = ir[m + dt + 1];
                        vv[m] = pk2(v, v);
                    }
#pragma unroll
                    for (int q = 0; q < CP; q++) {
                        const ull w2 = wb[(cog * CP + q) * WTSTR + ci_l * 16 + ky * 4 + kx];
#pragma unroll
                        for (int m = 0; m < 4; m++) fma2(accp[q][2 * m + ph], vv[m], w2);
                    }
                }
            }
        }
        __syncthreads();
    }

    const long chs = (long)OH * OW;
#pragma unroll
    for (int q = 0; q < CP; q++) {
        float o0[8], o1[8];
#pragma unroll
        for (int j = 0; j < 8; j++) {
            const float2 t = upk(accp[q][j]);
            o0[j] = ROUT ? fmaxf(t.x, 0.f) : t.x;
            o1[j] = ROUT ? fmaxf(t.y, 0.f) : t.y;
        }
        const int c0 = co0 + co_l + 2 * q, c1 = c0 + 1;
        if (c0 < CO) {
            float* op = out + (((long)n * CO + c0) * OH + oy) * OW + owg * 8;
            reinterpret_cast<float4*>(op)[0] = make_float4(o0[0], o0[1], o0[2], o0[3]);
            reinterpret_cast<float4*>(op)[1] = make_float4(o0[4], o0[5], o0[6], o0[7]);
        }
        if (c1 < CO) {
            float* op = out + (((long)n * CO + c1) * OH + oy) * OW + owg * 8;
            reinterpret_cast<float4*>(op)[0] = make_float4(o1[0], o1[1], o1[2], o1[3]);
            reinterpret_cast<float4*>(op)[1] = make_float4(o1[4], o1[5], o1[6], o1[7]);
        }
    }
}

// ---------------------------------------------------------------------------
// VQ: transposed smem codebook tile (LDS.128) + f32x2 dot, per-tile norms.
// dist = ||c||^2 - 2 f.c  (||f||^2 constant per pixel); first-min on ties.
// ---------------------------------------------------------------------------
__global__ void __launch_bounds__(256) vqk2(
    const float* __restrict__ z, const float* __restrict__ cb,
    float* __restrict__ q)
{
    constexpr int NPIX = 4096;
    __shared__ float cbs[128][68];
    __shared__ float cns[128];
    const int tid = threadIdx.x;
    const int p = blockIdx.x * 256 + tid;
    const int b = p >> 12;
    const int pix = p & 4095;

    const float* zp = z + (long)b * 64 * NPIX + pix;
    float f[64];
#pragma unroll
    for (int d = 0; d < 64; d++) f[d] = zp[(long)d * NPIX];
    ull fp[32];
#pragma unroll
    for (int i = 0; i < 32; i++) fp[i] = pk2(f[2 * i], f[2 * i + 1]);

    float best = 3.4e38f;
    int bidx = 0;
    for (int t = 0; t < 4; t++) {
        __syncthreads();
        for (int i = tid; i < 8192; i += 256) {
            const int d = i >> 7, kk = i & 127;
            cbs[kk][d] = __ldg(cb + d * 512 + t * 128 + kk);
        }
        __syncthreads();
        if (tid < 128) {
            const float* row = cbs[tid];
            float s = 0.f;
#pragma unroll
            for (int d = 0; d < 64; d++) s += row[d] * row[d];
            cns[tid] = s;
        }
        __syncthreads();
        for (int kk = 0; kk < 128; kk++) {
            const ulonglong2* row = reinterpret_cast<const ulonglong2*>(cbs[kk]);
            ull a0 = 0, a1 = 0, a2 = 0, a3 = 0;
#pragma unroll
            for (int i = 0; i < 16; i += 2) {
                const ulonglong2 u = row[i];
                const ulonglong2 v = row[i + 1];
                fma2(a0, u.x, fp[2 * i + 0]);
                fma2(a1, u.y, fp[2 * i + 1]);
                fma2(a2, v.x, fp[2 * i + 2]);
                fma2(a3, v.y, fp[2 * i + 3]);
            }
            const float2 x0 = upk(a0), x1 = upk(a1), x2 = upk(a2), x3 = upk(a3);
            const float dot = ((x0.x + x0.y) + (x1.x + x1.y)) + ((x2.x + x2.y) + (x3.x + x3.y));
            const float dist = cns[kk] - 2.f * dot;
            if (dist < best) { best = dist; bidx = t * 128 + kk; }
        }
    }
    float* qp = q + (long)b * 64 * NPIX + pix;
#pragma unroll
    for (int d = 0; d < 64; d++) qp[(long)d * NPIX] = __ldg(cb + d * 512 + bidx);
}

// ---------------------------------------------------------------------------
// Host launcher
// ---------------------------------------------------------------------------
extern "C" void kernel_launch(void* const* d_in, const int* in_sizes, int n_in,
                              void* d_out, int out_size)
{
    (void)in_sizes; (void)n_in; (void)out_size;
    const float* x        = (const float*)d_in[0];
    const float* enc_w0   = (const float*)d_in[1];
    const float* enc_b0   = (const float*)d_in[2];
    const float* enc_w1   = (const float*)d_in[3];
    const float* enc_b1   = (const float*)d_in[4];
    const float* enc_wf   = (const float*)d_in[5];
    const float* enc_bf   = (const float*)d_in[6];
    const float* enc_rw1  = (const float*)d_in[7];
    const float* enc_rb1  = (const float*)d_in[8];
    const float* enc_rw2  = (const float*)d_in[9];
    const float* enc_rb2  = (const float*)d_in[10];
    const float* pre_w    = (const float*)d_in[11];
    const float* pre_b    = (const float*)d_in[12];
    const float* codebook = (const float*)d_in[13];
    const float* dec_w    = (const float*)d_in[14];
    const float* dec_b    = (const float*)d_in[15];
    const float* dec_rw1  = (const float*)d_in[16];
    const float* dec_rb1  = (const float*)d_in[17];
    const float* dec_rw2  = (const float*)d_in[18];
    const float* dec_rb2  = (const float*)d_in[19];
    const float* up_w0    = (const float*)d_in[20];
    const float* up_b0    = (const float*)d_in[21];
    const float* up_w1    = (const float*)d_in[22];
    const float* up_b1    = (const float*)d_in[23];
    float* out = (float*)d_out;

    float *pA, *pB, *pC, *pT, *pZ, *pQ;
    cudaGetSymbolAddress((void**)&pA, g_bufA);
    cudaGetSymbolAddress((void**)&pB, g_bufB);
    cudaGetSymbolAddress((void**)&pC, g_bufC);
    cudaGetSymbolAddress((void**)&pT, g_bufT);
    cudaGetSymbolAddress((void**)&pZ, g_bufZ);
    cudaGetSymbolAddress((void**)&pQ, g_bufQ);

    const int N = 16;

    // opt-in smem sizes (>48KB) — attribute set is idempotent, not a stream op
    {
        cudaFuncSetAttribute((const void*)conv2<4,4,2,1,64,8,4,false,true,false>,
            cudaFuncAttributeMaxDynamicSharedMemorySize, c2_smem(4,4,2,64,8,4,64));
        cudaFuncSetAttribute((const void*)conv2<3,3,1,1,64,8,8,false,false,false>,
            cudaFuncAttributeMaxDynamicSharedMemorySize, c2_smem(3,3,1,64,8,8,128));
        cudaFuncSetAttribute((const void*)conv2<3,3,1,1,64,8,8,true,false,false>,
            cudaFuncAttributeMaxDynamicSharedMemorySize, c2_smem(3,3,1,64,8,8,128));
        cudaFuncSetAttribute((const void*)convt2<256,8,8,4,4,false,false>,
            cudaFuncAttributeMaxDynamicSharedMemorySize, 2 * ct_stride(256,8,8,4));
    }

    // --- Encoder ---
    // L1: x[16,3,256,256] -> relu -> bufA[16,64,128,128]
    conv2<4,4,2,1,128,4,3,false,true,false>
        <<<dim3(N * 32, 4), 256, c2_smem(4,4,2,128,4,3,3)>>>(
        x, enc_w0, enc_b0, nullptr, pA, N, 3, 64, 256, 256, 128);
    // L2: bufA -> relu -> bufB[16,128,64,64]
    conv2<4,4,2,1,64,8,4,false,true,false>
        <<<dim3(N * 8, 8), 256, c2_smem(4,4,2,64,8,4,64)>>>(
        pA, enc_w1, enc_b1, nullptr, pB, N, 64, 128, 128, 128, 64);
    // enc_wf: bufB -> bufC
    conv2<3,3,1,1,64,8,8,false,false,false>
        <<<dim3(N * 8, 8), 256, c2_smem(3,3,1,64,8,8,128)>>>(
        pB, enc_wf, enc_bf, nullptr, pC, N, 128, 128, 64, 64, 64);
    // enc res blocks
    for (int i = 0; i < 2; i++) {
        conv2<3,3,1,1,64,8,8,true,false,false>
            <<<dim3(N * 8, 2), 256, c2_smem(3,3,1,64,8,8,128)>>>(
            pC, enc_rw1 + (long)i * 32 * 128 * 9, enc_rb1 + i * 32, nullptr, pT,
            N, 128, 32, 64, 64, 64);
        conv2<1,1,1,0,64,8,8,true,false,true>
            <<<dim3(N * 8, 8), 256, c2_smem(1,1,1,64,8,8,32)>>>(
            pT, enc_rw2 + (long)i * 128 * 32, enc_rb2 + i * 128, pC, pC,
            N, 32, 128, 64, 64, 64);
    }
    // pre: relu-in, bufC -> bufZ[16,64,64,64]
    conv2<1,1,1,0,64,8,8,true,false,false>
        <<<dim3(N * 8, 4), 256, c2_smem(1,1,1,64,8,8,128)>>>(
        pC, pre_w, pre_b, nullptr, pZ, N, 128, 64, 64, 64, 64);

    // --- VQ ---
    vqk2<<<256, 256>>>(pZ, codebook, pQ);

    // --- Decoder ---
    conv2<3,3,1,1,64,8,8,false,false,false>
        <<<dim3(N * 8, 8), 256, c2_smem(3,3,1,64,8,8,64)>>>(
        pQ, dec_w, dec_b, nullptr, pB, N, 64, 128, 64, 64, 64);
    for (int i = 0; i < 2; i++) {
        conv2<3,3,1,1,64,8,8,true,false,false>
            <<<dim3(N * 8, 2), 256, c2_smem(3,3,1,64,8,8,128)>>>(
            pB, dec_rw1 + (long)i * 32 * 128 * 9, dec_rb1 + i * 32, nullptr, pT,
            N, 128, 32, 64, 64, 64);
        conv2<1,1,1,0,64,8,8,true,false,true>
            <<<dim3(N * 8, 8), 256, c2_smem(1,1,1,64,8,8,32)>>>(
            pT, dec_rw2 + (long)i * 128 * 32, dec_rb2 + i * 128, pB, pB,
            N, 32, 128, 64, 64, 64);
    }
    // up0: relu-in + relu-out, bufB[16,128,64,64] -> bufA[16,64,128,128]
    convt2<128,4,8,16,4,true,true>
        <<<dim3(N * 32, 4), 256, 2 * ct_stride(128,4,8,16)>>>(
        pB, up_w0, up_b0, pA, N, 128, 64, 64, 64, 128);
    // up1: bufA[16,64,128,128] -> out[16,3,256,256]  (COB=4 padded, CO=3 guarded)
    convt2<256,8,8,4,4,false,false>
        <<<dim3(N * 32, 1), 256, 2 * ct_stride(256,8,8,4)>>>(
        pA, up_w1, up_b1, out, N, 64, 3, 128, 128, 256);
}

// round 5
// speedup vs baseline: 6.1530x; 1.5402x over previous
#include <cuda_runtime.h>
#include <cstdint>

typedef unsigned long long ull;

__device__ float g_bufA[16 * 64 * 128 * 128];
__device__ float g_bufB[16 * 128 * 64 * 64];
__device__ float g_bufC[16 * 128 * 64 * 64];
__device__ float g_bufT[16 * 32 * 64 * 64];
__device__ float g_bufZ[16 * 64 * 64 * 64];
__device__ float g_bufQ[16 * 64 * 64 * 64];
__device__ __align__(16) unsigned short g_wb[1048576];

// ---------------- helpers ----------------
__device__ __forceinline__ ull pk2(float lo, float hi) {
    ull r; asm("mov.b64 %0, {%1, %2};" : "=l"(r) : "f"(lo), "f"(hi)); return r;
}
__device__ __forceinline__ void fma2(ull& a, ull v, ull w) {
    asm("fma.rn.f32x2 %0, %1, %2, %0;" : "+l"(a) : "l"(v), "l"(w));
}
__device__ __forceinline__ float2 upk(ull v) {
    float2 r; asm("mov.b64 {%0, %1}, %2;" : "=f"(r.x), "=f"(r.y) : "l"(v)); return r;
}
__device__ __forceinline__ void cpa4(uint32_t s, const float* g, bool ok) {
    asm volatile("cp.async.ca.shared.global [%0], [%1], 4, %2;" :: "r"(s), "l"(g), "r"(ok ? 4u : 0u));
}
__device__ __forceinline__ void cpa16(uint32_t s, const void* g) {
    asm volatile("cp.async.cg.shared.global [%0], [%1], 16;" :: "r"(s), "l"(g));
}
__device__ __forceinline__ void cpacommit() { asm volatile("cp.async.commit_group;"); }
template <int NN> __device__ __forceinline__ void cpawait() {
    asm volatile("cp.async.wait_group %0;" :: "n"(NN));
}
__device__ __forceinline__ uint32_t s2u(const void* p) { return (uint32_t)__cvta_generic_to_shared(p); }
__device__ __forceinline__ void ldsm4(uint32_t* r, uint32_t a) {
    asm volatile("ldmatrix.sync.aligned.m8n8.x4.shared.b16 {%0,%1,%2,%3}, [%4];"
                 : "=r"(r[0]), "=r"(r[1]), "=r"(r[2]), "=r"(r[3]) : "r"(a));
}
__device__ __forceinline__ void mma16816(float* c, const uint32_t* a, uint32_t b0, uint32_t b1) {
    asm volatile("mma.sync.aligned.m16n8k16.row.col.f32.bf16.bf16.f32 "
                 "{%0,%1,%2,%3}, {%4,%5,%6,%7}, {%8,%9}, {%0,%1,%2,%3};"
                 : "+f"(c[0]), "+f"(c[1]), "+f"(c[2]), "+f"(c[3])
                 : "r"(a[0]), "r"(a[1]), "r"(a[2]), "r"(a[3]), "r"(b0), "r"(b1));
}
__device__ __forceinline__ uint32_t bfsplit2(float x0, float x1, uint32_t& lopair) {
    unsigned short h0, h1, l0, l1; float f0, f1;
    asm("cvt.rn.bf16.f32 %0, %1;" : "=h"(h0) : "f"(x0));
    asm("cvt.f32.bf16 %0, %1;" : "=f"(f0) : "h"(h0));
    asm("cvt.rn.bf16.f32 %0, %1;" : "=h"(l0) : "f"(x0 - f0));
    asm("cvt.rn.bf16.f32 %0, %1;" : "=h"(h1) : "f"(x1));
    asm("cvt.f32.bf16 %0, %1;" : "=f"(f1) : "h"(h1));
    asm("cvt.rn.bf16.f32 %0, %1;" : "=h"(l1) : "f"(x1 - f1));
    lopair = (uint32_t)l0 | ((uint32_t)l1 << 16);
    return (uint32_t)h0 | ((uint32_t)h1 << 16);
}

// smem formulas (host+device)
__host__ __device__ constexpr int c2_stride(int KH, int KW, int S, int OW, int OHB, int CIB) {
    int TWID = (OW - 1) * S + KW; int TWIDP = (TWID + 3) & ~3;
    int TROWS = (OHB - 1) * S + KH;
    return CIB * TROWS * TWIDP * 4 + 16 * (CIB * KH * KW + 1) * 8;
}
__host__ __device__ constexpr int c2_smem(int KH, int KW, int S, int OW, int OHB, int CIB, int CI) {
    return (CI > CIB ? 2 : 1) * c2_stride(KH, KW, S, OW, OHB, CIB);
}
__host__ __device__ constexpr int ct_stride(int OW, int OHB, int CIB, int COB) {
    int TWIDP = ((OW / 2 + 2) + 3) & ~3;
    return CIB * (OHB / 2 + 2) * TWIDP * 4 + (COB / 2) * (CIB * 16 + 1) * 8;
}
__host__ __device__ constexpr int cmma_smem(int CO, int KS, int MW) {
    int PADK = (KS - 1) / 2;
    int PIX = (MW * 32 / 64 + 2 * PADK) * (64 + 2 * PADK);
    return ((PIX * 80 + 127) & ~127) + 2 * CO * 80;
}

// ---------------------------------------------------------------------------
// Weight prep: fp32 [CO][CI][KS][KS] -> records per (ci-chunk, tap):
// CO recs x 80B = [16 hi bf16][16 lo bf16]
// ---------------------------------------------------------------------------
__global__ void prepw(const float* __restrict__ w, unsigned short* __restrict__ dst,
                      int CI, int CO, int KS, int total)
{
    int i = blockIdx.x * 256 + threadIdx.x;
    if (i >= total) return;
    const int TT = KS * KS;
    const int kp = i & 7;
    int rest = i >> 3;
    const int n = rest % CO; rest /= CO;
    const int t = rest % TT;
    const int c = rest / TT;
    const int ci = c * 16 + 2 * kp;
    const float* base = w + (((long)n * CI + ci) * TT) + t;
    const float x0 = base[0], x1 = base[TT];
    uint32_t lo, hi = bfsplit2(x0, x1, lo);
    unsigned short* rec = dst + ((long)(c * TT + t) * CO + n) * 40;
    *(uint32_t*)(rec + 2 * kp) = hi;
    *(uint32_t*)(rec + 16 + 2 * kp) = lo;
}

// ---------------------------------------------------------------------------
// Tensor-core conv for 64x64 stride-1 layers (KS in {1,3}), bf16 2-split,
// 3 MMA combos, fp32 accum. 256 thr = MW x NW warps; warp tile 32m x NWT n.
// ---------------------------------------------------------------------------
template <int CI, int CO, int KS, int MW, int NW, bool RIN, bool ADD>
__global__ void __launch_bounds__(256, 2) convmma(
    const float* __restrict__ in, const unsigned short* __restrict__ wb,
    const float* __restrict__ bias, const float* __restrict__ res,
    float* __restrict__ out)
{
    constexpr int CH = CI / 16;
    constexpr int T = KS * KS;
    constexpr int MC = MW * 32;
    constexpr int NWT = CO / NW;
    constexpr int NB = NWT / 16;
    constexpr int PADK = (KS - 1) / 2;
    constexpr int YO = MC / 64;
    constexpr int YR = YO + 2 * PADK;
    constexpr int XW = 64 + 2 * PADK;
    constexpr int PIX = YR * XW;
    constexpr int ABYTES = (PIX * 80 + 127) & ~127;
    constexpr int BBYTES = CO * 80;

    extern __shared__ char sm[];
    char* Abuf = sm;
    const uint32_t smA = s2u(sm);
    const uint32_t smB = s2u(sm + ABYTES);

    const int tid = threadIdx.x;
    const int lane = tid & 31;
    const int warp = tid >> 5;
    const int wm = (NW == 1) ? warp : (warp & (MW - 1));
    const int wn = (NW == 1) ? 0 : (warp >> 2);

    const int mtile = blockIdx.x * MC;
    const int nimg = mtile >> 12;
    const int y0 = (mtile >> 6) & 63;
    const float* inb = in + ((long)nimg * CI << 12);

    const int q = lane >> 3, r = lane & 7;
    const int m_off = ((q & 1) << 3) + r;
    const int k8b = (q >> 1) * 16;

    uint32_t laneA[2];
#pragma unroll
    for (int im = 0; im < 2; im++) {
        const int mrow = wm * 32 + im * 16 + m_off;
        laneA[im] = smA + (uint32_t)((mrow >> 6) * XW + (mrow & 63)) * 80 + k8b;
    }
    const uint32_t laneBoff = (uint32_t)(wn * NWT + m_off) * 80 + k8b;

    float acc[2][2 * NB][4];
#pragma unroll
    for (int im = 0; im < 2; im++)
#pragma unroll
        for (int j = 0; j < 2 * NB; j++)
#pragma unroll
            for (int e = 0; e < 4; e++) acc[im][j][e] = 0.f;

    auto stageB = [&](int c, int t, int b) {
        const char* src = (const char*)(wb + (long)(c * T + t) * CO * 40);
        const uint32_t d = smB + (uint32_t)b * BBYTES;
        for (int i = tid; i < CO * 5; i += 256)
            cpa16(d + (uint32_t)i * 16, src + (long)i * 16);
    };
    auto stageA = [&](int c) {
        const int ci0 = c * 16;
        for (int i = tid; i < 8 * PIX; i += 256) {
            const int cp = i / PIX, p = i - cp * PIX;
            const int yy = p / XW, xx = p - yy * XW;
            const int iy = y0 + yy - PADK, ix = xx - PADK;
            float v0 = 0.f, v1 = 0.f;
            if (iy >= 0 && iy < 64 && ix >= 0 && ix < 64) {
                const float* pp = inb + ((long)(ci0 + 2 * cp) << 12) + (iy << 6) + ix;
                v0 = __ldg(pp); v1 = __ldg(pp + 4096);
            }
            if (RIN) { v0 = fmaxf(v0, 0.f); v1 = fmaxf(v1, 0.f); }
            uint32_t lo, hi = bfsplit2(v0, v1, lo);
            *(uint32_t*)(Abuf + p * 80 + 4 * cp) = hi;
            *(uint32_t*)(Abuf + p * 80 + 32 + 4 * cp) = lo;
        }
    };

    stageB(0, 0, 0);
    cpacommit();
    int bi = 0;

    for (int c = 0; c < CH; c++) {
        __syncthreads();
        stageA(c);
        __syncthreads();
#pragma unroll 1
        for (int t = 0; t < T; t++) {
            __syncthreads();
            const bool pf = (t + 1 < T) || (c + 1 < CH);
            if (t + 1 < T) stageB(c, t + 1, bi ^ 1);
            else if (c + 1 < CH) stageB(c + 1, 0, bi ^ 1);
            if (pf) { cpacommit(); cpawait<1>(); }
            else cpawait<0>();
            __syncthreads();

            const int dy = t / KS, dx = t - dy * KS;
            const uint32_t dt = (uint32_t)(dy * XW + dx) * 80;

            uint32_t ah[2][4], al[2][4];
            ldsm4(ah[0], laneA[0] + dt);
            ldsm4(ah[1], laneA[1] + dt);
            ldsm4(al[0], laneA[0] + dt + 32);
            ldsm4(al[1], laneA[1] + dt + 32);

            const uint32_t bb = smB + (uint32_t)bi * BBYTES + laneBoff;
            uint32_t bf[NB][4];
#pragma unroll
            for (int nb = 0; nb < NB; nb++) ldsm4(bf[nb], bb + (uint32_t)nb * 1280);
#pragma unroll
            for (int im = 0; im < 2; im++)
#pragma unroll
                for (int nb = 0; nb < NB; nb++) {
                    mma16816(acc[im][2 * nb], ah[im], bf[nb][0], bf[nb][2]);
                    mma16816(acc[im][2 * nb + 1], ah[im], bf[nb][1], bf[nb][3]);
                    mma16816(acc[im][2 * nb], al[im], bf[nb][0], bf[nb][2]);
                    mma16816(acc[im][2 * nb + 1], al[im], bf[nb][1], bf[nb][3]);
                }
#pragma unroll
            for (int nb = 0; nb < NB; nb++) ldsm4(bf[nb], bb + (uint32_t)nb * 1280 + 32);
#pragma unroll
            for (int im = 0; im < 2; im++)
#pragma unroll
                for (int nb = 0; nb < NB; nb++) {
                    mma16816(acc[im][2 * nb], ah[im], bf[nb][0], bf[nb][2]);
                    mma16816(acc[im][2 * nb + 1], ah[im], bf[nb][1], bf[nb][3]);
                }
            bi ^= 1;
        }
    }

    const int gid = lane >> 2, tg = lane & 3;
    const int l0 = (mtile & 4095) + wm * 32 + gid;
#pragma unroll
    for (int im = 0; im < 2; im++) {
#pragma unroll
        for (int j = 0; j < 2 * NB; j++) {
            const int col = wn * NWT + j * 8 + 2 * tg;
            const float b0 = __ldg(bias + col), b1 = __ldg(bias + col + 1);
            const long cbase = ((long)nimg * CO + col) << 12;
#pragma unroll
            for (int h = 0; h < 2; h++) {
                const int pix = l0 + im * 16 + h * 8;
                float v0 = acc[im][j][2 * h] + b0;
                float v1 = acc[im][j][2 * h + 1] + b1;
                const long o0 = cbase + pix;
                if (ADD) { v0 += __ldg(res + o0); v1 += __ldg(res + o0 + 4096); }
                out[o0] = v0;
                out[o0 + 4096] = v1;
            }
        }
    }
}

// ---------------------------------------------------------------------------
// fp32 conv (stride-2 layers), cp.async double-buffered, f32x2 inner loop.
// ---------------------------------------------------------------------------
template <int KH, int KW, int S, int P, int OWt, int OHB, int CIB,
          bool RIN, bool ROUT, bool ADD>
__global__ void __launch_bounds__(256) conv2(
    const float* __restrict__ in, const float* __restrict__ wt,
    const float* __restrict__ bias, const float* __restrict__ res,
    float* __restrict__ out, int N, int CI, int CO, int IH, int IW, int OH)
{
    constexpr int OW = OWt;
    constexpr int TAPS = KH * KW;
    constexpr int TWID = (OW - 1) * S + KW;
    constexpr int TWIDP = (TWID + 3) & ~3;
    constexpr int TROWS = (OHB - 1) * S + KH;
    constexpr int TILE_CI = TROWS * TWIDP;
    constexpr int TILE = CIB * TILE_CI;
    constexpr int WSTR = CIB * TAPS + 1;
    constexpr int STRIDEB = TILE * 4 + 16 * WSTR * 8;
    constexpr int LW = 7 * S + KW;
    constexpr int OWG8 = OW / 8;
    static_assert(OWG8 * OHB * 4 == 256, "map");

    extern __shared__ char smx[];
    const int RB = OH / OHB;
    const int n = blockIdx.x / RB;
    const int rb = blockIdx.x % RB;
    const int oy0 = rb * OHB;
    const int co0 = blockIdx.y * 16;
    const int tid = threadIdx.x;
    const int cog = tid & 3;
    const int spat = tid >> 2;
    const int owg = spat % OWG8;
    const int ohr = spat / OWG8;
    const int co_l = cog * 4;
    const int iy0 = oy0 * S - P;
    const float* inn = in + (long)n * CI * IH * IW;
    const int G = CI / CIB;

    ull acc[4][4];
#pragma unroll
    for (int c = 0; c < 4; c++) {
        const float b = __ldg(bias + co0 + co_l + c);
        const ull bb = pk2(b, b);
#pragma unroll
        for (int m = 0; m < 4; m++) acc[c][m] = bb;
    }
    auto stage = [&](int gidx, int bi) {
        char* buf = smx + bi * STRIDEB;
        float* tile = (float*)buf;
        ull* wp = (ull*)(buf + TILE * 4);
        const uint32_t tadr = s2u(tile);
        const int ci0 = gidx * CIB;
        for (int i = tid; i < TILE; i += 256) {
            const int ci_l = i / TILE_CI;
            const int rem = i - ci_l * TILE_CI;
            const int r = rem / TWIDP, c = rem - r * TWIDP;
            const int iy = iy0 + r, ix = c - P;
            const bool ok = (c < TWID) & (iy >= 0) & (iy < IH) & (ix >= 0) & (ix < IW);
            const float* src = ok ? inn + ((long)(ci0 + ci_l) * IH + iy) * IW + ix : inn;
            cpa4(tadr + 4u * (uint32_t)i, src, ok);
        }
        for (int i = tid; i < 16 * CIB * TAPS; i += 256) {
            const int c = i / (CIB * TAPS);
            const int rem = i - c * (CIB * TAPS);
            const float w = __ldg(wt + ((long)(co0 + c) * CI + ci0 + rem / TAPS) * TAPS + rem % TAPS);
            wp[c * WSTR + rem] = pk2(w, w);
        }
    };
    stage(0, 0);
    cpacommit();
    for (int g = 0; g < G; g++) {
        const int bi = g & 1;
        if (g + 1 < G) { stage(g + 1, bi ^ 1); cpacommit(); cpawait<1>(); }
        else cpawait<0>();
        __syncthreads();
        const float* tb = (const float*)(smx + bi * STRIDEB);
        const ull* wbp = (const ull*)(smx + bi * STRIDEB + TILE * 4);
#pragma unroll 1
        for (int ci_l = 0; ci_l < CIB; ci_l++) {
            const float* tci = tb + ci_l * TILE_CI;
#pragma unroll
            for (int kh = 0; kh < KH; kh++) {
                const float* trow = tci + (ohr * S + kh) * TWIDP + owg * 8 * S;
                float ir[LW];
#pragma unroll
                for (int v = 0; v < LW / 4; v++) {
                    const float4 q4 = reinterpret_cast<const float4*>(trow)[v];
                    ir[4 * v] = q4.x; ir[4 * v + 1] = q4.y; ir[4 * v + 2] = q4.z; ir[4 * v + 3] = q4.w;
                }
#pragma unroll
                for (int l = (LW / 4) * 4; l < LW; l++) ir[l] = trow[l];
                if (RIN) {
#pragma unroll
                    for (int l = 0; l < LW; l++) ir[l] = fmaxf(ir[l], 0.f);
                }
#pragma unroll
                for (int kw = 0; kw < KW; kw++) {
                    ull p[4];
#pragma unroll
                    for (int m = 0; m < 4; m++)
                        p[m] = pk2(ir[2 * m * S + kw], ir[(2 * m + 1) * S + kw]);
#pragma unroll
                    for (int c = 0; c < 4; c++) {
                        const ull w2 = wbp[(co_l + c) * WSTR + ci_l * TAPS + kh * KW + kw];
#pragma unroll
                        for (int m = 0; m < 4; m++) fma2(acc[c][m], p[m], w2);
                    }
                }
            }
        }
        __syncthreads();
    }
    const int oy = oy0 + ohr;
    const long chs = (long)OH * OW;
    const long ob = (((long)n * CO + co0 + co_l) * OH + oy) * OW + owg * 8;
#pragma unroll
    for (int c = 0; c < 4; c++) {
        float o[8];
#pragma unroll
        for (int m = 0; m < 4; m++) {
            const float2 t = upk(acc[c][m]);
            o[2 * m] = t.x; o[2 * m + 1] = t.y;
        }
        float* op = out + ob + c * chs;
        if (ADD) {
            const float* rp = res + ob + c * chs;
#pragma unroll
            for (int j = 0; j < 8; j++) o[j] += __ldg(rp + j);
        }
        if (ROUT) {
#pragma unroll
            for (int j = 0; j < 8; j++) o[j] = fmaxf(o[j], 0.f);
        }
        reinterpret_cast<float4*>(op)[0] = make_float4(o[0], o[1], o[2], o[3]);
        reinterpret_cast<float4*>(op)[1] = make_float4(o[4], o[5], o[6], o[7]);
    }
}

// ---------------------------------------------------------------------------
// ConvTranspose2d k=4 s=2 p=1, fp32 f32x2 (co-pairs).
// ---------------------------------------------------------------------------
template <int OWt, int OHB, int CIB, int COB, int COT, bool RIN, bool ROUT>
__global__ void __launch_bounds__(256) convt2(
    const float* __restrict__ in, const float* __restrict__ wt,
    const float* __restrict__ bias, float* __restrict__ out,
    int N, int CI, int CO, int IH, int IW, int OH)
{
    constexpr int OW = OWt;
    constexpr int COG = COB / COT;
    constexpr int CP = COT / 2;
    constexpr int TROWS = OHB / 2 + 2;
    constexpr int TWID = OW / 2 + 2;
    constexpr int TWIDP = (TWID + 3) & ~3;
    constexpr int TILE_CI = TROWS * TWIDP;
    constexpr int TILE = CIB * TILE_CI;
    constexpr int WTSTR = CIB * 16 + 1;
    constexpr int STRIDEB = TILE * 4 + (COB / 2) * WTSTR * 8;
    constexpr int OWG8 = OW / 8;
    static_assert(OWG8 * OHB * COG == 256, "map");

    extern __shared__ char smx[];
    const int RB = OH / OHB;
    const int n = blockIdx.x / RB;
    const int rb = blockIdx.x % RB;
    const int oy0 = rb * OHB;
    const int co0 = blockIdx.y * COB;
    const int tid = threadIdx.x;
    const int cog = tid % COG;
    const int spat = tid / COG;
    const int owg = spat % OWG8;
    const int ohr = spat / OWG8;
    const int co_l = cog * COT;
    const int iy0 = oy0 / 2 - 1;
    const int oy = oy0 + ohr;
    const int ky0 = (oy + 1) & 1;
    const float* inn = in + (long)n * CI * IH * IW;
    const int G = CI / CIB;

    ull accp[CP][8];
#pragma unroll
    for (int qq = 0; qq < CP; qq++) {
        const int c0 = co0 + co_l + 2 * qq, c1 = c0 + 1;
        const float b0 = (c0 < CO) ? __ldg(bias + c0) : 0.f;
        const float b1 = (c1 < CO) ? __ldg(bias + c1) : 0.f;
        const ull bb = pk2(b0, b1);
#pragma unroll
        for (int j = 0; j < 8; j++) accp[qq][j] = bb;
    }
    auto stage = [&](int gidx, int bi) {
        char* buf = smx + bi * STRIDEB;
        float* tile = (float*)buf;
        ull* wp = (ull*)(buf + TILE * 4);
        const uint32_t tadr = s2u(tile);
        const int ci0 = gidx * CIB;
        for (int i = tid; i < TILE; i += 256) {
            const int ci_l = i / TILE_CI;
            const int rem = i - ci_l * TILE_CI;
            const int r = rem / TWIDP, c = rem - r * TWIDP;
            const int iy = iy0 + r, ix = c - 1;
            const bool ok = (c < TWID) & (iy >= 0) & (iy < IH) & (ix >= 0) & (ix < IW);
            const float* src = ok ? inn + ((long)(ci0 + ci_l) * IH + iy) * IW + ix : inn;
            cpa4(tadr + 4u * (uint32_t)i, src, ok);
        }
        for (int i = tid; i < (COB / 2) * CIB * 16; i += 256) {
            const int cpg = i / (CIB * 16);
            const int rem = i - cpg * (CIB * 16);
            const int ci_l = rem >> 4, tap = rem & 15;
            const int c0 = co0 + 2 * cpg, c1 = c0 + 1;
            const float w0 = (c0 < CO) ? __ldg(wt + ((long)(ci0 + ci_l) * CO + c0) * 16 + tap) : 0.f;
            const float w1 = (c1 < CO) ? __ldg(wt + ((long)(ci0 + ci_l) * CO + c1) * 16 + tap) : 0.f;
            wp[cpg * WTSTR + rem] = pk2(w0, w1);
        }
    };
    stage(0, 0);
    cpacommit();
    for (int g = 0; g < G; g++) {
        const int bi = g & 1;
        if (g + 1 < G) { stage(g + 1, bi ^ 1); cpacommit(); cpawait<1>(); }
        else cpawait<0>();
        __syncthreads();
        const float* tb = (const float*)(smx + bi * STRIDEB);
        const ull* wbp = (const ull*)(smx + bi * STRIDEB + TILE * 4);
#pragma unroll 1
        for (int ci_l = 0; ci_l < CIB; ci_l++) {
            const float* tci = tb + ci_l * TILE_CI;
#pragma unroll
            for (int t2 = 0; t2 < 2; t2++) {
                const int ky = ky0 + 2 * t2;
                const int r = ((oy + 1 - ky) >> 1) - iy0;
                const float* trow = tci + r * TWIDP + owg * 4;
                float ir[6];
                {
                    const float4 q4 = *reinterpret_cast<const float4*>(trow);
                    ir[0] = q4.x; ir[1] = q4.y; ir[2] = q4.z; ir[3] = q4.w;
                    ir[4] = trow[4]; ir[5] = trow[5];
                }
                if (RIN) {
#pragma unroll
                    for (int l = 0; l < 6; l++) ir[l] = fmaxf(ir[l], 0.f);
                }
#pragma unroll
                for (int kx = 0; kx < 4; kx++) {
                    const int ph = (kx + 1) & 1;
                    const int dt = (kx == 0) ? 1 : ((kx == 3) ? -1 : 0);
                    ull vv[4];
#pragma unroll
                    for (int m = 0; m < 4; m++) {
                        const float v = ir[m + dt + 1];
                        vv[m] = pk2(v, v);
                    }
#pragma unroll
                    for (int qq = 0; qq < CP; qq++) {
                        const ull w2 = wbp[(cog * CP + qq) * WTSTR + ci_l * 16 + ky * 4 + kx];
#pragma unroll
                        for (int m = 0; m < 4; m++) fma2(accp[qq][2 * m + ph], vv[m], w2);
                    }
                }
            }
        }
        __syncthreads();
    }
#pragma unroll
    for (int qq = 0; qq < CP; qq++) {
        float o0[8], o1[8];
#pragma unroll
        for (int j = 0; j < 8; j++) {
            const float2 t = upk(accp[qq][j]);
            o0[j] = ROUT ? fmaxf(t.x, 0.f) : t.x;
            o1[j] = ROUT ? fmaxf(t.y, 0.f) : t.y;
        }
        const int c0 = co0 + co_l + 2 * qq, c1 = c0 + 1;
        if (c0 < CO) {
            float* op = out + (((long)n * CO + c0) * OH + oy) * OW + owg * 8;
            reinterpret_cast<float4*>(op)[0] = make_float4(o0[0], o0[1], o0[2], o0[3]);
            reinterpret_cast<float4*>(op)[1] = make_float4(o0[4], o0[5], o0[6], o0[7]);
        }
        if (c1 < CO) {
            float* op = out + (((long)n * CO + c1) * OH + oy) * OW + owg * 8;
            reinterpret_cast<float4*>(op)[0] = make_float4(o1[0], o1[1], o1[2], o1[3]);
            reinterpret_cast<float4*>(op)[1] = make_float4(o1[4], o1[5], o1[6], o1[7]);
        }
    }
}

// ---------------------------------------------------------------------------
// VQ (unchanged)
// ---------------------------------------------------------------------------
__global__ void __launch_bounds__(256) vqk2(
    const float* __restrict__ z, const float* __restrict__ cb, float* __restrict__ q)
{
    constexpr int NPIX = 4096;
    __shared__ float cbs[128][68];
    __shared__ float cns[128];
    const int tid = threadIdx.x;
    const int p = blockIdx.x * 256 + tid;
    const int b = p >> 12;
    const int pix = p & 4095;
    const float* zp = z + (long)b * 64 * NPIX + pix;
    float f[64];
#pragma unroll
    for (int d = 0; d < 64; d++) f[d] = zp[(long)d * NPIX];
    ull fp[32];
#pragma unroll
    for (int i = 0; i < 32; i++) fp[i] = pk2(f[2 * i], f[2 * i + 1]);
    float best = 3.4e38f;
    int bidx = 0;
    for (int t = 0; t < 4; t++) {
        __syncthreads();
        for (int i = tid; i < 8192; i += 256) {
            const int d = i >> 7, kk = i & 127;
            cbs[kk][d] = __ldg(cb + d * 512 + t * 128 + kk);
        }
        __syncthreads();
        if (tid < 128) {
            const float* row = cbs[tid];
            float s = 0.f;
#pragma unroll
            for (int d = 0; d < 64; d++) s += row[d] * row[d];
            cns[tid] = s;
        }
        __syncthreads();
        for (int kk = 0; kk < 128; kk++) {
            const ulonglong2* row = reinterpret_cast<const ulonglong2*>(cbs[kk]);
            ull a0 = 0, a1 = 0, a2 = 0, a3 = 0;
#pragma unroll
            for (int i = 0; i < 16; i += 2) {
                const ulonglong2 u = row[i];
                const ulonglong2 v = row[i + 1];
                fma2(a0, u.x, fp[2 * i]);
                fma2(a1, u.y, fp[2 * i + 1]);
                fma2(a2, v.x, fp[2 * i + 2]);
                fma2(a3, v.y, fp[2 * i + 3]);
            }
            const float2 x0 = upk(a0), x1 = upk(a1), x2 = upk(a2), x3 = upk(a3);
            const float dot = ((x0.x + x0.y) + (x1.x + x1.y)) + ((x2.x + x2.y) + (x3.x + x3.y));
            const float dist = cns[kk] - 2.f * dot;
            if (dist < best) { best = dist; bidx = t * 128 + kk; }
        }
    }
    float* qp = q + (long)b * 64 * NPIX + pix;
#pragma unroll
    for (int d = 0; d < 64; d++) qp[(long)d * NPIX] = __ldg(cb + d * 512 + bidx);
}

// ---------------------------------------------------------------------------
// Host launcher
// ---------------------------------------------------------------------------
extern "C" void kernel_launch(void* const* d_in, const int* in_sizes, int n_in,
                              void* d_out, int out_size)
{
    (void)in_sizes; (void)n_in; (void)out_size;
    const float* x        = (const float*)d_in[0];
    const float* enc_w0   = (const float*)d_in[1];
    const float* enc_b0   = (const float*)d_in[2];
    const float* enc_w1   = (const float*)d_in[3];
    const float* enc_b1   = (const float*)d_in[4];
    const float* enc_wf   = (const float*)d_in[5];
    const float* enc_bf   = (const float*)d_in[6];
    const float* enc_rw1  = (const float*)d_in[7];
    const float* enc_rb1  = (const float*)d_in[8];
    const float* enc_rw2  = (const float*)d_in[9];
    const float* enc_rb2  = (const float*)d_in[10];
    const float* pre_w    = (const float*)d_in[11];
    const float* pre_b    = (const float*)d_in[12];
    const float* codebook = (const float*)d_in[13];
    const float* dec_w    = (const float*)d_in[14];
    const float* dec_b    = (const float*)d_in[15];
    const float* dec_rw1  = (const float*)d_in[16];
    const float* dec_rb1  = (const float*)d_in[17];
    const float* dec_rw2  = (const float*)d_in[18];
    const float* dec_rb2  = (const float*)d_in[19];
    const float* up_w0    = (const float*)d_in[20];
    const float* up_b0    = (const float*)d_in[21];
    const float* up_w1    = (const float*)d_in[22];
    const float* up_b1    = (const float*)d_in[23];
    float* out = (float*)d_out;

    float *pA, *pB, *pC, *pT, *pZ, *pQ;
    unsigned short* pW;
    cudaGetSymbolAddress((void**)&pA, g_bufA);
    cudaGetSymbolAddress((void**)&pB, g_bufB);
    cudaGetSymbolAddress((void**)&pC, g_bufC);
    cudaGetSymbolAddress((void**)&pT, g_bufT);
    cudaGetSymbolAddress((void**)&pZ, g_bufZ);
    cudaGetSymbolAddress((void**)&pQ, g_bufQ);
    cudaGetSymbolAddress((void**)&pW, g_wb);

    const int N = 16;

    cudaFuncSetAttribute((const void*)conv2<4,4,2,1,64,8,4,false,true,false>,
        cudaFuncAttributeMaxDynamicSharedMemorySize, c2_smem(4,4,2,64,8,4,64));
    cudaFuncSetAttribute((const void*)convt2<256,8,8,4,4,false,false>,
        cudaFuncAttributeMaxDynamicSharedMemorySize, 2 * ct_stride(256,8,8,4));

    // g_wb offsets (shorts)
    const long oWF = 0;                 // enc_wf  8*9*128 rec
    const long oER1a = 368640, oER1b = 460800;
    const long oER2a = 552960, oER2b = 563200;
    const long oPRE = 573440;
    const long oDEC = 593920;
    const long oDR1a = 778240, oDR1b = 870400;
    const long oDR2a = 962560, oDR2b = 972800;

    auto prep = [&](const float* w, long off, int CI, int CO, int KS) {
        const int total = (CI / 16) * KS * KS * CO * 8;
        prepw<<<(total + 255) / 256, 256>>>(w, pW + off, CI, CO, KS, total);
    };
    prep(enc_wf, oWF, 128, 128, 3);
    prep(enc_rw1, oER1a, 128, 32, 3);
    prep(enc_rw1 + (long)32 * 128 * 9, oER1b, 128, 32, 3);
    prep(enc_rw2, oER2a, 32, 128, 1);
    prep(enc_rw2 + (long)128 * 32, oER2b, 32, 128, 1);
    prep(pre_w, oPRE, 128, 64, 1);
    prep(dec_w, oDEC, 64, 128, 3);
    prep(dec_rw1, oDR1a, 128, 32, 3);
    prep(dec_rw1 + (long)32 * 128 * 9, oDR1b, 128, 32, 3);
    prep(dec_rw2, oDR2a, 32, 128, 1);
    prep(dec_rw2 + (long)128 * 32, oDR2b, 32, 128, 1);

    // Encoder stride-2 (fp32)
    conv2<4,4,2,1,128,4,3,false,true,false>
        <<<dim3(N * 32, 4), 256, c2_smem(4,4,2,128,4,3,3)>>>(
        x, enc_w0, enc_b0, nullptr, pA, N, 3, 64, 256, 256, 128);
    conv2<4,4,2,1,64,8,4,false,true,false>
        <<<dim3(N * 8, 8), 256, c2_smem(4,4,2,64,8,4,64)>>>(
        pA, enc_w1, enc_b1, nullptr, pB, N, 64, 128, 128, 128, 64);

    // 64x64 family on tensor cores
    convmma<128,128,3,4,2,false,false><<<512, 256, cmma_smem(128,3,4)>>>(
        pB, pW + oWF, enc_bf, nullptr, pC);
    convmma<128,32,3,8,1,true,false><<<256, 256, cmma_smem(32,3,8)>>>(
        pC, pW + oER1a, enc_rb1, nullptr, pT);
    convmma<32,128,1,4,2,true,true><<<512, 256, cmma_smem(128,1,4)>>>(
        pT, pW + oER2a, enc_rb2, pC, pC);
    convmma<128,32,3,8,1,true,false><<<256, 256, cmma_smem(32,3,8)>>>(
        pC, pW + oER1b, enc_rb1 + 32, nullptr, pT);
    convmma<32,128,1,4,2,true,true><<<512, 256, cmma_smem(128,1,4)>>>(
        pT, pW + oER2b, enc_rb2 + 128, pC, pC);
    convmma<128,64,1,4,2,true,false><<<512, 256, cmma_smem(64,1,4)>>>(
        pC, pW + oPRE, pre_b, nullptr, pZ);

    vqk2<<<256, 256>>>(pZ, codebook, pQ);

    convmma<64,128,3,4,2,false,false><<<512, 256, cmma_smem(128,3,4)>>>(
        pQ, pW + oDEC, dec_b, nullptr, pB);
    convmma<128,32,3,8,1,true,false><<<256, 256, cmma_smem(32,3,8)>>>(
        pB, pW + oDR1a, dec_rb1, nullptr, pT);
    convmma<32,128,1,4,2,true,true><<<512, 256, cmma_smem(128,1,4)>>>(
        pT, pW + oDR2a, dec_rb2, pB, pB);
    convmma<128,32,3,8,1,true,false><<<256, 256, cmma_smem(32,3,8)>>>(
        pB, pW + oDR1b, dec_rb1 + 32, nullptr, pT);
    convmma<32,128,1,4,2,true,true><<<512, 256, cmma_smem(128,1,4)>>>(
        pT, pW + oDR2b, dec_rb2 + 128, pB, pB);

    // Decoder upsampling (fp32 conv-T)
    convt2<128,4,8,16,4,true,true>
        <<<dim3(N * 32, 4), 256, 2 * ct_stride(128,4,8,16)>>>(
        pB, up_w0, up_b0, pA, N, 128, 64, 64, 64, 128);
    convt2<256,8,8,4,4,false,false>
        <<<dim3(N * 32, 1), 256, 2 * ct_stride(256,8,8,4)>>>(
        pA, up_w1, up_b1, out, N, 64, 3, 128, 128, 256);
}

// round 6
// speedup vs baseline: 9.6377x; 1.5663x over previous
#include <cuda_runtime.h>
#include <cstdint>

typedef unsigned long long ull;

__device__ float g_bufA[16 * 64 * 128 * 128];
__device__ float g_bufB[16 * 128 * 64 * 64];
__device__ float g_bufC[16 * 128 * 64 * 64];
__device__ float g_bufT[16 * 32 * 64 * 64];
__device__ float g_bufZ[16 * 64 * 64 * 64];
__device__ float g_bufQ[16 * 64 * 64 * 64];
__device__ float g_bufS[16 * 256 * 64 * 64];          // s2d of L1 output
__device__ __align__(16) unsigned short g_wb[1638400];

// ---------------- helpers ----------------
__device__ __forceinline__ ull pk2(float lo, float hi) {
    ull r; asm("mov.b64 %0, {%1, %2};" : "=l"(r) : "f"(lo), "f"(hi)); return r;
}
__device__ __forceinline__ void fma2(ull& a, ull v, ull w) {
    asm("fma.rn.f32x2 %0, %1, %2, %0;" : "+l"(a) : "l"(v), "l"(w));
}
__device__ __forceinline__ float2 upk(ull v) {
    float2 r; asm("mov.b64 {%0, %1}, %2;" : "=f"(r.x), "=f"(r.y) : "l"(v)); return r;
}
__device__ __forceinline__ void cpa4(uint32_t s, const float* g, bool ok) {
    asm volatile("cp.async.ca.shared.global [%0], [%1], 4, %2;" :: "r"(s), "l"(g), "r"(ok ? 4u : 0u));
}
__device__ __forceinline__ void cpa16(uint32_t s, const void* g) {
    asm volatile("cp.async.cg.shared.global [%0], [%1], 16;" :: "r"(s), "l"(g));
}
__device__ __forceinline__ void cpacommit() { asm volatile("cp.async.commit_group;"); }
template <int NN> __device__ __forceinline__ void cpawait() {
    asm volatile("cp.async.wait_group %0;" :: "n"(NN));
}
__device__ __forceinline__ uint32_t s2u(const void* p) { return (uint32_t)__cvta_generic_to_shared(p); }
__device__ __forceinline__ void ldsm4(uint32_t* r, uint32_t a) {
    asm volatile("ldmatrix.sync.aligned.m8n8.x4.shared.b16 {%0,%1,%2,%3}, [%4];"
                 : "=r"(r[0]), "=r"(r[1]), "=r"(r[2]), "=r"(r[3]) : "r"(a));
}
__device__ __forceinline__ void mma16816(float* c, const uint32_t* a, uint32_t b0, uint32_t b1) {
    asm volatile("mma.sync.aligned.m16n8k16.row.col.f32.bf16.bf16.f32 "
                 "{%0,%1,%2,%3}, {%4,%5,%6,%7}, {%8,%9}, {%0,%1,%2,%3};"
                 : "+f"(c[0]), "+f"(c[1]), "+f"(c[2]), "+f"(c[3])
                 : "r"(a[0]), "r"(a[1]), "r"(a[2]), "r"(a[3]), "r"(b0), "r"(b1));
}
__device__ __forceinline__ uint32_t bfsplit2(float x0, float x1, uint32_t& lopair) {
    unsigned short h0, h1, l0, l1; float f0, f1;
    asm("cvt.rn.bf16.f32 %0, %1;" : "=h"(h0) : "f"(x0));
    asm("cvt.f32.bf16 %0, %1;" : "=f"(f0) : "h"(h0));
    asm("cvt.rn.bf16.f32 %0, %1;" : "=h"(l0) : "f"(x0 - f0));
    asm("cvt.rn.bf16.f32 %0, %1;" : "=h"(h1) : "f"(x1));
    asm("cvt.f32.bf16 %0, %1;" : "=f"(f1) : "h"(h1));
    asm("cvt.rn.bf16.f32 %0, %1;" : "=h"(l1) : "f"(x1 - f1));
    lopair = (uint32_t)l0 | ((uint32_t)l1 << 16);
    return (uint32_t)h0 | ((uint32_t)h1 << 16);
}

// smem formulas
__host__ __device__ constexpr int c2_stride(int KH, int KW, int S, int OW, int OHB, int CIB) {
    int TWID = (OW - 1) * S + KW; int TWIDP = (TWID + 3) & ~3;
    int TROWS = (OHB - 1) * S + KH;
    return CIB * TROWS * TWIDP * 4 + 16 * (CIB * KH * KW + 1) * 8;
}
__host__ __device__ constexpr int c2_smem(int KH, int KW, int S, int OW, int OHB, int CIB, int CI) {
    return (CI > CIB ? 2 : 1) * c2_stride(KH, KW, S, OW, OHB, CIB);
}
__host__ __device__ constexpr int ct_stride(int OW, int OHB, int CIB, int COB) {
    int TWIDP = ((OW / 2 + 2) + 3) & ~3;
    return CIB * (OHB / 2 + 2) * TWIDP * 4 + (COB / 2) * (CIB * 16 + 1) * 8;
}
__host__ __device__ constexpr int cmma_smem(int CO, int PADK, int MW) {
    int PIX = (MW * 32 / 64 + 2 * PADK) * (64 + 2 * PADK);
    return ((PIX * 80 + 127) & ~127) + 2 * CO * 80;
}

// ---------------------------------------------------------------------------
// Weight preps: -> records per (chunk, tap): CO recs x 80B = [16 hi][16 lo]
// ---------------------------------------------------------------------------
__global__ void prepw(const float* __restrict__ w, unsigned short* __restrict__ dst,
                      int CI, int CO, int KS, int total)
{
    int i = blockIdx.x * 256 + threadIdx.x;
    if (i >= total) return;
    const int TT = KS * KS;
    const int kp = i & 7;
    int rest = i >> 3;
    const int n = rest % CO; rest /= CO;
    const int t = rest % TT;
    const int c = rest / TT;
    const int ci = c * 16 + 2 * kp;
    const float* base = w + (((long)n * CI + ci) * TT) + t;
    const float x0 = base[0], x1 = base[TT];
    uint32_t lo, hi = bfsplit2(x0, x1, lo);
    unsigned short* rec = dst + ((long)(c * TT + t) * CO + n) * 40;
    *(uint32_t*)(rec + 2 * kp) = hi;
    *(uint32_t*)(rec + 16 + 2 * kp) = lo;
}

// enc_w1 [128co][64ci][4][4] -> s2d-conv records: 16 chunks x 4 taps x 128 co
__global__ void prepw_s2d(const float* __restrict__ w, unsigned short* __restrict__ dst)
{
    int i = blockIdx.x * 256 + threadIdx.x;
    if (i >= 65536) return;
    const int kp = i & 7;
    int rest = i >> 3;
    const int co = rest & 127; rest >>= 7;
    const int t = rest & 3;
    const int c = rest >> 2;
    const int p = c >> 2, py = p >> 1, px = p & 1;
    const int jy = t >> 1, jx = t & 1;
    const int kh = 2 * jy + 1 - py, kw = 2 * jx + 1 - px;
    const int ci = (c & 3) * 16 + 2 * kp;
    const float* s = w + (((long)co * 64 + ci) * 16) + kh * 4 + kw;
    uint32_t lo, hi = bfsplit2(s[0], s[16], lo);
    unsigned short* rec = dst + ((long)(c * 4 + t) * 128 + co) * 40;
    *(uint32_t*)(rec + 2 * kp) = hi;
    *(uint32_t*)(rec + 16 + 2 * kp) = lo;
}

// up_w0 [128ci][64co][4][4] -> per-phase convT records: 4 ph x 8 chunks x 4 taps x 64 co
__global__ void prepw_ct(const float* __restrict__ w, unsigned short* __restrict__ dst)
{
    int i = blockIdx.x * 256 + threadIdx.x;
    if (i >= 65536) return;
    const int kp = i & 7;
    int rest = i >> 3;
    const int co = rest & 63; rest >>= 6;
    const int t = rest & 3; rest >>= 2;
    const int c = rest & 7;
    const int ph = rest >> 3;
    const int py = ph >> 1, px = ph & 1;
    const int jy = t >> 1, jx = t & 1;
    const int ky = 2 * jy + 1 - py, kx = 2 * jx + 1 - px;
    const int ci = c * 16 + 2 * kp;
    const float* s = w + (((long)ci * 64 + co) * 16) + ky * 4 + kx;
    uint32_t lo, hi = bfsplit2(s[0], s[1024], lo);
    unsigned short* rec = dst + ((long)((ph * 8 + c) * 4 + t) * 64 + co) * 40;
    *(uint32_t*)(rec + 2 * kp) = hi;
    *(uint32_t*)(rec + 16 + 2 * kp) = lo;
}

// ---------------------------------------------------------------------------
// Generalized tensor-core conv on 64x64 index space.
// MODE 0: stride-1 KSxKS conv (KS in {1,3}), output [n][CO][64][64]
// MODE 1: s2d stride-2 4x4 conv: input [n][256][64][64] phase-major,
//         per-chunk taps (dy=jy-py, dx=jx-px), output [n][CO][64][64]
// MODE 2: convT 4x4/s2 sub-pixel phase (blockIdx.y): taps dy=py-jy,
//         output interleaved into [n][CO][128][128]
// ---------------------------------------------------------------------------
template <int MODE, int CI, int CO, int KS, int MW, int NW, bool RIN, bool ROUT, bool ADD>
__global__ void __launch_bounds__(256, 2) convmma(
    const float* __restrict__ in, const unsigned short* __restrict__ wb,
    const float* __restrict__ bias, const float* __restrict__ res,
    float* __restrict__ out)
{
    constexpr int CH = CI / 16;
    constexpr int T = (MODE == 0) ? KS * KS : 4;
    constexpr int PADK = (MODE == 0) ? (KS - 1) / 2 : 1;
    constexpr int MC = MW * 32;
    constexpr int NWT = CO / NW;
    constexpr int NB = NWT / 16;
    constexpr int YO = MC / 64;
    constexpr int YR = YO + 2 * PADK;
    constexpr int XW = 64 + 2 * PADK;
    constexpr int PIX = YR * XW;
    constexpr int ABYTES = (PIX * 80 + 127) & ~127;
    constexpr int BBYTES = CO * 80;

    extern __shared__ char sm[];
    char* Abuf = sm;
    const uint32_t smA = s2u(sm);
    const uint32_t smB = s2u(sm + ABYTES);

    const int tid = threadIdx.x;
    const int lane = tid & 31;
    const int warp = tid >> 5;
    const int wm = (NW == 1) ? warp : (warp & (MW - 1));
    const int wn = (NW == 1) ? 0 : (warp >> 2);

    const int py = (MODE == 2) ? ((int)blockIdx.y >> 1) : 0;
    const int px = (MODE == 2) ? ((int)blockIdx.y & 1) : 0;
    const unsigned short* wbp = (MODE == 2) ? wb + (long)blockIdx.y * CH * T * CO * 40 : wb;

    const int mtile = blockIdx.x * MC;
    const int nimg = mtile >> 12;
    const int y0 = (mtile >> 6) & 63;
    const float* inb = in + ((long)nimg * CI << 12);

    const int q = lane >> 3, r = lane & 7;
    const int m_off = ((q & 1) << 3) + r;
    const int k8b = (q >> 1) * 16;

    uint32_t laneA[2];
#pragma unroll
    for (int im = 0; im < 2; im++) {
        const int mrow = wm * 32 + im * 16 + m_off;
        laneA[im] = smA + (uint32_t)((mrow >> 6) * XW + (mrow & 63)) * 80 + k8b;
    }
    const uint32_t laneBoff = (uint32_t)(wn * NWT + m_off) * 80 + k8b;

    float acc[2][2 * NB][4];
#pragma unroll
    for (int im = 0; im < 2; im++)
#pragma unroll
        for (int j = 0; j < 2 * NB; j++)
#pragma unroll
            for (int e = 0; e < 4; e++) acc[im][j][e] = 0.f;

    auto stageB = [&](int c, int t, int b) {
        const char* src = (const char*)(wbp + (long)(c * T + t) * CO * 40);
        const uint32_t d = smB + (uint32_t)b * BBYTES;
        for (int i = tid; i < CO * 5; i += 256)
            cpa16(d + (uint32_t)i * 16, src + (long)i * 16);
    };
    auto stageA = [&](int c) {
        const int ci0 = c * 16;
        for (int i = tid; i < 8 * PIX; i += 256) {
            const int cp = i / PIX, p = i - cp * PIX;
            const int yy = p / XW, xx = p - yy * XW;
            const int iy = y0 + yy - PADK, ix = xx - PADK;
            float v0 = 0.f, v1 = 0.f;
            if (iy >= 0 && iy < 64 && ix >= 0 && ix < 64) {
                const float* pp = inb + ((long)(ci0 + 2 * cp) << 12) + (iy << 6) + ix;
                v0 = __ldg(pp); v1 = __ldg(pp + 4096);
            }
            if (RIN) { v0 = fmaxf(v0, 0.f); v1 = fmaxf(v1, 0.f); }
            uint32_t lo, hi = bfsplit2(v0, v1, lo);
            *(uint32_t*)(Abuf + p * 80 + 4 * cp) = hi;
            *(uint32_t*)(Abuf + p * 80 + 32 + 4 * cp) = lo;
        }
    };

    stageB(0, 0, 0);
    cpacommit();
    int bi = 0;

    for (int c = 0; c < CH; c++) {
        __syncthreads();
        stageA(c);
        __syncthreads();
#pragma unroll 1
        for (int t = 0; t < T; t++) {
            __syncthreads();
            const bool pf = (t + 1 < T) || (c + 1 < CH);
            if (t + 1 < T) stageB(c, t + 1, bi ^ 1);
            else if (c + 1 < CH) stageB(c + 1, 0, bi ^ 1);
            if (pf) { cpacommit(); cpawait<1>(); }
            else cpawait<0>();
            __syncthreads();

            int dyr, dxr;
            if (MODE == 0) { dyr = t / KS; dxr = t - (t / KS) * KS; }
            else if (MODE == 1) {
                const int pc = c >> 2;
                dyr = (t >> 1) - (pc >> 1) + 1;
                dxr = (t & 1) - (pc & 1) + 1;
            } else {
                dyr = py - (t >> 1) + 1;
                dxr = px - (t & 1) + 1;
            }
            const uint32_t dt = (uint32_t)(dyr * XW + dxr) * 80;

            uint32_t ah[2][4], al[2][4];
            ldsm4(ah[0], laneA[0] + dt);
            ldsm4(ah[1], laneA[1] + dt);
            ldsm4(al[0], laneA[0] + dt + 32);
            ldsm4(al[1], laneA[1] + dt + 32);

            const uint32_t bb = smB + (uint32_t)bi * BBYTES + laneBoff;
            uint32_t bf[NB][4];
#pragma unroll
            for (int nb = 0; nb < NB; nb++) ldsm4(bf[nb], bb + (uint32_t)nb * 1280);
#pragma unroll
            for (int im = 0; im < 2; im++)
#pragma unroll
                for (int nb = 0; nb < NB; nb++) {
                    mma16816(acc[im][2 * nb], ah[im], bf[nb][0], bf[nb][2]);
                    mma16816(acc[im][2 * nb + 1], ah[im], bf[nb][1], bf[nb][3]);
                    mma16816(acc[im][2 * nb], al[im], bf[nb][0], bf[nb][2]);
                    mma16816(acc[im][2 * nb + 1], al[im], bf[nb][1], bf[nb][3]);
                }
#pragma unroll
            for (int nb = 0; nb < NB; nb++) ldsm4(bf[nb], bb + (uint32_t)nb * 1280 + 32);
#pragma unroll
            for (int im = 0; im < 2; im++)
#pragma unroll
                for (int nb = 0; nb < NB; nb++) {
                    mma16816(acc[im][2 * nb], ah[im], bf[nb][0], bf[nb][2]);
                    mma16816(acc[im][2 * nb + 1], ah[im], bf[nb][1], bf[nb][3]);
                }
            bi ^= 1;
        }
    }

    const int gid = lane >> 2, tg = lane & 3;
    const int l0 = (mtile & 4095) + wm * 32 + gid;
#pragma unroll
    for (int im = 0; im < 2; im++) {
#pragma unroll
        for (int j = 0; j < 2 * NB; j++) {
            const int col = wn * NWT + j * 8 + 2 * tg;
            const float b0 = __ldg(bias + col), b1 = __ldg(bias + col + 1);
#pragma unroll
            for (int h = 0; h < 2; h++) {
                const int sp = l0 + im * 16 + h * 8;
                float v0 = acc[im][j][2 * h] + b0;
                float v1 = acc[im][j][2 * h + 1] + b1;
                if (MODE == 2) {
                    if (ROUT) { v0 = fmaxf(v0, 0.f); v1 = fmaxf(v1, 0.f); }
                    const long cb2 = ((long)nimg * CO + col) << 14;
                    const int oo = (((sp >> 6) * 2 + py) << 7) + ((sp & 63) * 2 + px);
                    out[cb2 + oo] = v0;
                    out[cb2 + oo + 16384] = v1;
                } else {
                    const long o0 = (((long)nimg * CO + col) << 12) + sp;
                    if (ADD) { v0 += __ldg(res + o0); v1 += __ldg(res + o0 + 4096); }
                    if (ROUT) { v0 = fmaxf(v0, 0.f); v1 = fmaxf(v1, 0.f); }
                    out[o0] = v0;
                    out[o0 + 4096] = v1;
                }
            }
        }
    }
}

// ---------------------------------------------------------------------------
// fp32 conv (L1 only now), f32x2, optional s2d-layout output
// ---------------------------------------------------------------------------
template <int KH, int KW, int S, int P, int OWt, int OHB, int CIB,
          bool RIN, bool ROUT, bool ADD, bool S2D>
__global__ void __launch_bounds__(256) conv2(
    const float* __restrict__ in, const float* __restrict__ wt,
    const float* __restrict__ bias, const float* __restrict__ res,
    float* __restrict__ out, int N, int CI, int CO, int IH, int IW, int OH)
{
    constexpr int OW = OWt;
    constexpr int TAPS = KH * KW;
    constexpr int TWID = (OW - 1) * S + KW;
    constexpr int TWIDP = (TWID + 3) & ~3;
    constexpr int TROWS = (OHB - 1) * S + KH;
    constexpr int TILE_CI = TROWS * TWIDP;
    constexpr int TILE = CIB * TILE_CI;
    constexpr int WSTR = CIB * TAPS + 1;
    constexpr int STRIDEB = TILE * 4 + 16 * WSTR * 8;
    constexpr int LW = 7 * S + KW;
    constexpr int OWG8 = OW / 8;
    static_assert(OWG8 * OHB * 4 == 256, "map");

    extern __shared__ char smx[];
    const int RB = OH / OHB;
    const int n = blockIdx.x / RB;
    const int rb = blockIdx.x % RB;
    const int oy0 = rb * OHB;
    const int co0 = blockIdx.y * 16;
    const int tid = threadIdx.x;
    const int cog = tid & 3;
    const int spat = tid >> 2;
    const int owg = spat % OWG8;
    const int ohr = spat / OWG8;
    const int co_l = cog * 4;
    const int iy0 = oy0 * S - P;
    const float* inn = in + (long)n * CI * IH * IW;
    const int G = CI / CIB;

    ull acc[4][4];
#pragma unroll
    for (int c = 0; c < 4; c++) {
        const float b = __ldg(bias + co0 + co_l + c);
        const ull bb = pk2(b, b);
#pragma unroll
        for (int m = 0; m < 4; m++) acc[c][m] = bb;
    }
    auto stage = [&](int gidx, int bi) {
        char* buf = smx + bi * STRIDEB;
        float* tile = (float*)buf;
        ull* wp = (ull*)(buf + TILE * 4);
        const uint32_t tadr = s2u(tile);
        const int ci0 = gidx * CIB;
        for (int i = tid; i < TILE; i += 256) {
            const int ci_l = i / TILE_CI;
            const int rem = i - ci_l * TILE_CI;
            const int r = rem / TWIDP, c = rem - r * TWIDP;
            const int iy = iy0 + r, ix = c - P;
            const bool ok = (c < TWID) & (iy >= 0) & (iy < IH) & (ix >= 0) & (ix < IW);
            const float* src = ok ? inn + ((long)(ci0 + ci_l) * IH + iy) * IW + ix : inn;
            cpa4(tadr + 4u * (uint32_t)i, src, ok);
        }
        for (int i = tid; i < 16 * CIB * TAPS; i += 256) {
            const int c = i / (CIB * TAPS);
            const int rem = i - c * (CIB * TAPS);
            const float w = __ldg(wt + ((long)(co0 + c) * CI + ci0 + rem / TAPS) * TAPS + rem % TAPS);
            wp[c * WSTR + rem] = pk2(w, w);
        }
    };
    stage(0, 0);
    cpacommit();
    for (int g = 0; g < G; g++) {
        const int bi = g & 1;
        if (g + 1 < G) { stage(g + 1, bi ^ 1); cpacommit(); cpawait<1>(); }
        else cpawait<0>();
        __syncthreads();
        const float* tb = (const float*)(smx + bi * STRIDEB);
        const ull* wbp = (const ull*)(smx + bi * STRIDEB + TILE * 4);
#pragma unroll 1
        for (int ci_l = 0; ci_l < CIB; ci_l++) {
            const float* tci = tb + ci_l * TILE_CI;
#pragma unroll
            for (int kh = 0; kh < KH; kh++) {
                const float* trow = tci + (ohr * S + kh) * TWIDP + owg * 8 * S;
                float ir[LW];
#pragma unroll
                for (int v = 0; v < LW / 4; v++) {
                    const float4 q4 = reinterpret_cast<const float4*>(trow)[v];
                    ir[4 * v] = q4.x; ir[4 * v + 1] = q4.y; ir[4 * v + 2] = q4.z; ir[4 * v + 3] = q4.w;
                }
#pragma unroll
                for (int l = (LW / 4) * 4; l < LW; l++) ir[l] = trow[l];
                if (RIN) {
#pragma unroll
                    for (int l = 0; l < LW; l++) ir[l] = fmaxf(ir[l], 0.f);
                }
#pragma unroll
                for (int kw = 0; kw < KW; kw++) {
                    ull p[4];
#pragma unroll
                    for (int m = 0; m < 4; m++)
                        p[m] = pk2(ir[2 * m * S + kw], ir[(2 * m + 1) * S + kw]);
#pragma unroll
                    for (int c = 0; c < 4; c++) {
                        const ull w2 = wbp[(co_l + c) * WSTR + ci_l * TAPS + kh * KW + kw];
#pragma unroll
                        for (int m = 0; m < 4; m++) fma2(acc[c][m], p[m], w2);
                    }
                }
            }
        }
        __syncthreads();
    }
    const int oy = oy0 + ohr;
#pragma unroll
    for (int c = 0; c < 4; c++) {
        float o[8];
#pragma unroll
        for (int m = 0; m < 4; m++) {
            const float2 t = upk(acc[c][m]);
            o[2 * m] = t.x; o[2 * m + 1] = t.y;
        }
        if (ROUT) {
#pragma unroll
            for (int j = 0; j < 8; j++) o[j] = fmaxf(o[j], 0.f);
        }
        if (S2D) {
            // write phase-separated: [n][ph*64+ch][64][64], ph = (oy&1)*2 + (ox&1)
            const int pyl = oy & 1, yh = oy >> 1, xh0 = owg * 4;
            const int ch = co0 + co_l + c;
            float* p0 = out + (((long)n * 256 + (pyl * 2 + 0) * 64 + ch) << 12) + (yh << 6) + xh0;
            float* p1 = out + (((long)n * 256 + (pyl * 2 + 1) * 64 + ch) << 12) + (yh << 6) + xh0;
            *reinterpret_cast<float4*>(p0) = make_float4(o[0], o[2], o[4], o[6]);
            *reinterpret_cast<float4*>(p1) = make_float4(o[1], o[3], o[5], o[7]);
        } else {
            const long chs = (long)OH * OW;
            const long ob = (((long)n * CO + co0 + co_l + c) * OH + oy) * OW + owg * 8;
            float* op = out + ob;
            if (ADD) {
                const float* rp = res + ob;
#pragma unroll
                for (int j = 0; j < 8; j++) o[j] += __ldg(rp + j);
            }
            (void)chs;
            reinterpret_cast<float4*>(op)[0] = make_float4(o[0], o[1], o[2], o[3]);
            reinterpret_cast<float4*>(op)[1] = make_float4(o[4], o[5], o[6], o[7]);
        }
    }
}

// ---------------------------------------------------------------------------
// ConvTranspose2d k=4 s=2 p=1 fp32 (up1 only)
// ---------------------------------------------------------------------------
template <int OWt, int OHB, int CIB, int COB, int COT, bool RIN, bool ROUT>
__global__ void __launch_bounds__(256) convt2(
    const float* __restrict__ in, const float* __restrict__ wt,
    const float* __restrict__ bias, float* __restrict__ out,
    int N, int CI, int CO, int IH, int IW, int OH)
{
    constexpr int OW = OWt;
    constexpr int COG = COB / COT;
    constexpr int CP = COT / 2;
    constexpr int TROWS = OHB / 2 + 2;
    constexpr int TWID = OW / 2 + 2;
    constexpr int TWIDP = (TWID + 3) & ~3;
    constexpr int TILE_CI = TROWS * TWIDP;
    constexpr int TILE = CIB * TILE_CI;
    constexpr int WTSTR = CIB * 16 + 1;
    constexpr int STRIDEB = TILE * 4 + (COB / 2) * WTSTR * 8;
    constexpr int OWG8 = OW / 8;
    static_assert(OWG8 * OHB * COG == 256, "map");

    extern __shared__ char smx[];
    const int RB = OH / OHB;
    const int n = blockIdx.x / RB;
    const int rb = blockIdx.x % RB;
    const int oy0 = rb * OHB;
    const int co0 = blockIdx.y * COB;
    const int tid = threadIdx.x;
    const int cog = tid % COG;
    const int spat = tid / COG;
    const int owg = spat % OWG8;
    const int ohr = spat / OWG8;
    const int co_l = cog * COT;
    const int iy0 = oy0 / 2 - 1;
    const int oy = oy0 + ohr;
    const int ky0 = (oy + 1) & 1;
    const float* inn = in + (long)n * CI * IH * IW;
    const int G = CI / CIB;

    ull accp[CP][8];
#pragma unroll
    for (int qq = 0; qq < CP; qq++) {
        const int c0 = co0 + co_l + 2 * qq, c1 = c0 + 1;
        const float b0 = (c0 < CO) ? __ldg(bias + c0) : 0.f;
        const float b1 = (c1 < CO) ? __ldg(bias + c1) : 0.f;
        const ull bb = pk2(b0, b1);
#pragma unroll
        for (int j = 0; j < 8; j++) accp[qq][j] = bb;
    }
    auto stage = [&](int gidx, int bi) {
        char* buf = smx + bi * STRIDEB;
        float* tile = (float*)buf;
        ull* wp = (ull*)(buf + TILE * 4);
        const uint32_t tadr = s2u(tile);
        const int ci0 = gidx * CIB;
        for (int i = tid; i < TILE; i += 256) {
            const int ci_l = i / TILE_CI;
            const int rem = i - ci_l * TILE_CI;
            const int r = rem / TWIDP, c = rem - r * TWIDP;
            const int iy = iy0 + r, ix = c - 1;
            const bool ok = (c < TWID) & (iy >= 0) & (iy < IH) & (ix >= 0) & (ix < IW);
            const float* src = ok ? inn + ((long)(ci0 + ci_l) * IH + iy) * IW + ix : inn;
            cpa4(tadr + 4u * (uint32_t)i, src, ok);
        }
        for (int i = tid; i < (COB / 2) * CIB * 16; i += 256) {
            const int cpg = i / (CIB * 16);
            const int rem = i - cpg * (CIB * 16);
            const int ci_l = rem >> 4, tap = rem & 15;
            const int c0 = co0 + 2 * cpg, c1 = c0 + 1;
            const float w0 = (c0 < CO) ? __ldg(wt + ((long)(ci0 + ci_l) * CO + c0) * 16 + tap) : 0.f;
            const float w1 = (c1 < CO) ? __ldg(wt + ((long)(ci0 + ci_l) * CO + c1) * 16 + tap) : 0.f;
            wp[cpg * WTSTR + rem] = pk2(w0, w1);
        }
    };
    stage(0, 0);
    cpacommit();
    for (int g = 0; g < G; g++) {
        const int bi = g & 1;
        if (g + 1 < G) { stage(g + 1, bi ^ 1); cpacommit(); cpawait<1>(); }
        else cpawait<0>();
        __syncthreads();
        const float* tb = (const float*)(smx + bi * STRIDEB);
        const ull* wbp = (const ull*)(smx + bi * STRIDEB + TILE * 4);
#pragma unroll 1
        for (int ci_l = 0; ci_l < CIB; ci_l++) {
            const float* tci = tb + ci_l * TILE_CI;
#pragma unroll
            for (int t2 = 0; t2 < 2; t2++) {
                const int ky = ky0 + 2 * t2;
                const int r = ((oy + 1 - ky) >> 1) - iy0;
                const float* trow = tci + r * TWIDP + owg * 4;
                float ir[6];
                {
                    const float4 q4 = *reinterpret_cast<const float4*>(trow);
                    ir[0] = q4.x; ir[1] = q4.y; ir[2] = q4.z; ir[3] = q4.w;
                    ir[4] = trow[4]; ir[5] = trow[5];
                }
                if (RIN) {
#pragma unroll
                    for (int l = 0; l < 6; l++) ir[l] = fmaxf(ir[l], 0.f);
                }
#pragma unroll
                for (int kx = 0; kx < 4; kx++) {
                    const int ph = (kx + 1) & 1;
                    const int dt = (kx == 0) ? 1 : ((kx == 3) ? -1 : 0);
                    ull vv[4];
#pragma unroll
                    for (int m = 0; m < 4; m++) {
                        const float v = ir[m + dt + 1];
                        vv[m] = pk2(v, v);
                    }
#pragma unroll
                    for (int qq = 0; qq < CP; qq++) {
                        const ull w2 = wbp[(cog * CP + qq) * WTSTR + ci_l * 16 + ky * 4 + kx];
#pragma unroll
                        for (int m = 0; m < 4; m++) fma2(accp[qq][2 * m + ph], vv[m], w2);
                    }
                }
            }
        }
        __syncthreads();
    }
#pragma unroll
    for (int qq = 0; qq < CP; qq++) {
        float o0[8], o1[8];
#pragma unroll
        for (int j = 0; j < 8; j++) {
            const float2 t = upk(accp[qq][j]);
            o0[j] = ROUT ? fmaxf(t.x, 0.f) : t.x;
            o1[j] = ROUT ? fmaxf(t.y, 0.f) : t.y;
        }
        const int c0 = co0 + co_l + 2 * qq, c1 = c0 + 1;
        if (c0 < CO) {
            float* op = out + (((long)n * CO + c0) * OH + oy) * OW + owg * 8;
            reinterpret_cast<float4*>(op)[0] = make_float4(o0[0], o0[1], o0[2], o0[3]);
            reinterpret_cast<float4*>(op)[1] = make_float4(o0[4], o0[5], o0[6], o0[7]);
        }
        if (c1 < CO) {
            float* op = out + (((long)n * CO + c1) * OH + oy) * OW + owg * 8;
            reinterpret_cast<float4*>(op)[0] = make_float4(o1[0], o1[1], o1[2], o1[3]);
            reinterpret_cast<float4*>(op)[1] = make_float4(o1[4], o1[5], o1[6], o1[7]);
        }
    }
}

// ---------------------------------------------------------------------------
// VQ (unchanged)
// ---------------------------------------------------------------------------
__global__ void __launch_bounds__(256) vqk2(
    const float* __restrict__ z, const float* __restrict__ cb, float* __restrict__ q)
{
    constexpr int NPIX = 4096;
    __shared__ float cbs[128][68];
    __shared__ float cns[128];
    const int tid = threadIdx.x;
    const int p = blockIdx.x * 256 + tid;
    const int b = p >> 12;
    const int pix = p & 4095;
    const float* zp = z + (long)b * 64 * NPIX + pix;
    float f[64];
#pragma unroll
    for (int d = 0; d < 64; d++) f[d] = zp[(long)d * NPIX];
    ull fp[32];
#pragma unroll
    for (int i = 0; i < 32; i++) fp[i] = pk2(f[2 * i], f[2 * i + 1]);
    float best = 3.4e38f;
    int bidx = 0;
    for (int t = 0; t < 4; t++) {
        __syncthreads();
        for (int i = tid; i < 8192; i += 256) {
            const int d = i >> 7, kk = i & 127;
            cbs[kk][d] = __ldg(cb + d * 512 + t * 128 + kk);
        }
        __syncthreads();
        if (tid < 128) {
            const float* row = cbs[tid];
            float s = 0.f;
#pragma unroll
            for (int d = 0; d < 64; d++) s += row[d] * row[d];
            cns[tid] = s;
        }
        __syncthreads();
        for (int kk = 0; kk < 128; kk++) {
            const ulonglong2* row = reinterpret_cast<const ulonglong2*>(cbs[kk]);
            ull a0 = 0, a1 = 0, a2 = 0, a3 = 0;
#pragma unroll
            for (int i = 0; i < 16; i += 2) {
                const ulonglong2 u = row[i];
                const ulonglong2 v = row[i + 1];
                fma2(a0, u.x, fp[2 * i]);
                fma2(a1, u.y, fp[2 * i + 1]);
                fma2(a2, v.x, fp[2 * i + 2]);
                fma2(a3, v.y, fp[2 * i + 3]);
            }
            const float2 x0 = upk(a0), x1 = upk(a1), x2 = upk(a2), x3 = upk(a3);
            const float dot = ((x0.x + x0.y) + (x1.x + x1.y)) + ((x2.x + x2.y) + (x3.x + x3.y));
            const float dist = cns[kk] - 2.f * dot;
            if (dist < best) { best = dist; bidx = t * 128 + kk; }
        }
    }
    float* qp = q + (long)b * 64 * NPIX + pix;
#pragma unroll
    for (int d = 0; d < 64; d++) qp[(long)d * NPIX] = __ldg(cb + d * 512 + bidx);
}

// ---------------------------------------------------------------------------
// Host launcher
// ---------------------------------------------------------------------------
extern "C" void kernel_launch(void* const* d_in, const int* in_sizes, int n_in,
                              void* d_out, int out_size)
{
    (void)in_sizes; (void)n_in; (void)out_size;
    const float* x        = (const float*)d_in[0];
    const float* enc_w0   = (const float*)d_in[1];
    const float* enc_b0   = (const float*)d_in[2];
    const float* enc_w1   = (const float*)d_in[3];
    const float* enc_b1   = (const float*)d_in[4];
    const float* enc_wf   = (const float*)d_in[5];
    const float* enc_bf   = (const float*)d_in[6];
    const float* enc_rw1  = (const float*)d_in[7];
    const float* enc_rb1  = (const float*)d_in[8];
    const float* enc_rw2  = (const float*)d_in[9];
    const float* enc_rb2  = (const float*)d_in[10];
    const float* pre_w    = (const float*)d_in[11];
    const float* pre_b    = (const float*)d_in[12];
    const float* codebook = (const float*)d_in[13];
    const float* dec_w    = (const float*)d_in[14];
    const float* dec_b    = (const float*)d_in[15];
    const float* dec_rw1  = (const float*)d_in[16];
    const float* dec_rb1  = (const float*)d_in[17];
    const float* dec_rw2  = (const float*)d_in[18];
    const float* dec_rb2  = (const float*)d_in[19];
    const float* up_w0    = (const float*)d_in[20];
    const float* up_b0    = (const float*)d_in[21];
    const float* up_w1    = (const float*)d_in[22];
    const float* up_b1    = (const float*)d_in[23];
    float* out = (float*)d_out;

    float *pA, *pB, *pC, *pT, *pZ, *pQ, *pS;
    unsigned short* pW;
    cudaGetSymbolAddress((void**)&pA, g_bufA);
    cudaGetSymbolAddress((void**)&pB, g_bufB);
    cudaGetSymbolAddress((void**)&pC, g_bufC);
    cudaGetSymbolAddress((void**)&pT, g_bufT);
    cudaGetSymbolAddress((void**)&pZ, g_bufZ);
    cudaGetSymbolAddress((void**)&pQ, g_bufQ);
    cudaGetSymbolAddress((void**)&pS, g_bufS);
    cudaGetSymbolAddress((void**)&pW, g_wb);

    const int N = 16;

    cudaFuncSetAttribute((const void*)convt2<256,8,8,4,4,false,false>,
        cudaFuncAttributeMaxDynamicSharedMemorySize, 2 * ct_stride(256,8,8,4));

    // g_wb offsets (shorts)
    const long oWF = 0;
    const long oER1a = 368640, oER1b = 460800;
    const long oER2a = 552960, oER2b = 563200;
    const long oPRE = 573440;
    const long oDEC = 593920;
    const long oDR1a = 778240, oDR1b = 870400;
    const long oDR2a = 962560, oDR2b = 972800;
    const long oL2  = 983040;    // 16*4*128*40 = 327680
    const long oUP0 = 1310720;   // 4*8*4*64*40 = 327680

    auto prep = [&](const float* w, long off, int CI, int CO, int KS) {
        const int total = (CI / 16) * KS * KS * CO * 8;
        prepw<<<(total + 255) / 256, 256>>>(w, pW + off, CI, CO, KS, total);
    };
    prep(enc_wf, oWF, 128, 128, 3);
    prep(enc_rw1, oER1a, 128, 32, 3);
    prep(enc_rw1 + (long)32 * 128 * 9, oER1b, 128, 32, 3);
    prep(enc_rw2, oER2a, 32, 128, 1);
    prep(enc_rw2 + (long)128 * 32, oER2b, 32, 128, 1);
    prep(pre_w, oPRE, 128, 64, 1);
    prep(dec_w, oDEC, 64, 128, 3);
    prep(dec_rw1, oDR1a, 128, 32, 3);
    prep(dec_rw1 + (long)32 * 128 * 9, oDR1b, 128, 32, 3);
    prep(dec_rw2, oDR2a, 32, 128, 1);
    prep(dec_rw2 + (long)128 * 32, oDR2b, 32, 128, 1);
    prepw_s2d<<<256, 256>>>(enc_w1, pW + oL2);
    prepw_ct<<<256, 256>>>(up_w0, pW + oUP0);

    // L1: x -> relu -> s2d layout in bufS  [n][256][64][64]
    conv2<4,4,2,1,128,4,3,false,true,false,true>
        <<<dim3(N * 32, 4), 256, c2_smem(4,4,2,128,4,3,3)>>>(
        x, enc_w0, enc_b0, nullptr, pS, N, 3, 64, 256, 256, 128);

    // L2 on tensor cores: s2d conv, relu-out -> bufB [16,128,64,64]
    convmma<1,256,128,0,4,2,false,true,false><<<512, 256, cmma_smem(128,1,4)>>>(
        pS, pW + oL2, enc_b1, nullptr, pB);

    // 64x64 stride-1 family on tensor cores
    convmma<0,128,128,3,4,2,false,false,false><<<512, 256, cmma_smem(128,1,4)>>>(
        pB, pW + oWF, enc_bf, nullptr, pC);
    convmma<0,128,32,3,8,1,true,false,false><<<256, 256, cmma_smem(32,1,8)>>>(
        pC, pW + oER1a, enc_rb1, nullptr, pT);
    convmma<0,32,128,1,4,2,true,false,true><<<512, 256, cmma_smem(128,0,4)>>>(
        pT, pW + oER2a, enc_rb2, pC, pC);
    convmma<0,128,32,3,8,1,true,false,false><<<256, 256, cmma_smem(32,1,8)>>>(
        pC, pW + oER1b, enc_rb1 + 32, nullptr, pT);
    convmma<0,32,128,1,4,2,true,false,true><<<512, 256, cmma_smem(128,0,4)>>>(
        pT, pW + oER2b, enc_rb2 + 128, pC, pC);
    convmma<0,128,64,1,4,2,true,false,false><<<512, 256, cmma_smem(64,0,4)>>>(
        pC, pW + oPRE, pre_b, nullptr, pZ);

    vqk2<<<256, 256>>>(pZ, codebook, pQ);

    convmma<0,64,128,3,4,2,false,false,false><<<512, 256, cmma_smem(128,1,4)>>>(
        pQ, pW + oDEC, dec_b, nullptr, pB);
    convmma<0,128,32,3,8,1,true,false,false><<<256, 256, cmma_smem(32,1,8)>>>(
        pB, pW + oDR1a, dec_rb1, nullptr, pT);
    convmma<0,32,128,1,4,2,true,false,true><<<512, 256, cmma_smem(128,0,4)>>>(
        pT, pW + oDR2a, dec_rb2, pB, pB);
    convmma<0,128,32,3,8,1,true,false,false><<<256, 256, cmma_smem(32,1,8)>>>(
        pB, pW + oDR1b, dec_rb1 + 32, nullptr, pT);
    convmma<0,32,128,1,4,2,true,false,true><<<512, 256, cmma_smem(128,0,4)>>>(
        pT, pW + oDR2b, dec_rb2 + 128, pB, pB);

    // up0 on tensor cores: 4 sub-pixel phases, relu-in + relu-out -> bufA
    convmma<2,128,64,0,4,2,true,true,false><<<dim3(512, 4), 256, cmma_smem(64,1,4)>>>(
        pB, pW + oUP0, up_b0, nullptr, pA);

    // up1 fp32 conv-T: bufA -> out [16,3,256,256]
    convt2<256,8,8,4,4,false,false>
        <<<dim3(N * 32, 1), 256, 2 * ct_stride(256,8,8,4)>>>(
        pA, up_w1, up_b1, out, N, 64, 3, 128, 128, 256);
}

// round 7
// speedup vs baseline: 10.0976x; 1.0477x over previous
#include <cuda_runtime.h>
#include <cstdint>

typedef unsigned long long ull;

__device__ float g_bufA[16 * 64 * 128 * 128];
__device__ float g_bufB[16 * 128 * 64 * 64];
__device__ float g_bufC[16 * 128 * 64 * 64];
__device__ float g_bufT[16 * 32 * 64 * 64];
__device__ float g_bufZ[16 * 64 * 64 * 64];
__device__ float g_bufQ[16 * 64 * 64 * 64];
__device__ float g_bufS[16 * 256 * 64 * 64];          // s2d of L1 output
__device__ __align__(16) unsigned short g_wb[1638400];

// ---------------- helpers ----------------
__device__ __forceinline__ ull pk2(float lo, float hi) {
    ull r; asm("mov.b64 %0, {%1, %2};" : "=l"(r) : "f"(lo), "f"(hi)); return r;
}
__device__ __forceinline__ void fma2(ull& a, ull v, ull w) {
    asm("fma.rn.f32x2 %0, %1, %2, %0;" : "+l"(a) : "l"(v), "l"(w));
}
__device__ __forceinline__ float2 upk(ull v) {
    float2 r; asm("mov.b64 {%0, %1}, %2;" : "=f"(r.x), "=f"(r.y) : "l"(v)); return r;
}
__device__ __forceinline__ void cpa4(uint32_t s, const float* g, bool ok) {
    asm volatile("cp.async.ca.shared.global [%0], [%1], 4, %2;" :: "r"(s), "l"(g), "r"(ok ? 4u : 0u));
}
__device__ __forceinline__ void cpa16(uint32_t s, const void* g) {
    asm volatile("cp.async.cg.shared.global [%0], [%1], 16;" :: "r"(s), "l"(g));
}
__device__ __forceinline__ void cpacommit() { asm volatile("cp.async.commit_group;"); }
template <int NN> __device__ __forceinline__ void cpawait() {
    asm volatile("cp.async.wait_group %0;" :: "n"(NN));
}
__device__ __forceinline__ uint32_t s2u(const void* p) { return (uint32_t)__cvta_generic_to_shared(p); }
__device__ __forceinline__ void ldsm4(uint32_t* r, uint32_t a) {
    asm volatile("ldmatrix.sync.aligned.m8n8.x4.shared.b16 {%0,%1,%2,%3}, [%4];"
                 : "=r"(r[0]), "=r"(r[1]), "=r"(r[2]), "=r"(r[3]) : "r"(a));
}
__device__ __forceinline__ void mma16816(float* c, const uint32_t* a, uint32_t b0, uint32_t b1) {
    asm volatile("mma.sync.aligned.m16n8k16.row.col.f32.bf16.bf16.f32 "
                 "{%0,%1,%2,%3}, {%4,%5,%6,%7}, {%8,%9}, {%0,%1,%2,%3};"
                 : "+f"(c[0]), "+f"(c[1]), "+f"(c[2]), "+f"(c[3])
                 : "r"(a[0]), "r"(a[1]), "r"(a[2]), "r"(a[3]), "r"(b0), "r"(b1));
}
__device__ __forceinline__ uint32_t bfsplit2(float x0, float x1, uint32_t& lopair) {
    unsigned short h0, h1, l0, l1; float f0, f1;
    asm("cvt.rn.bf16.f32 %0, %1;" : "=h"(h0) : "f"(x0));
    asm("cvt.f32.bf16 %0, %1;" : "=f"(f0) : "h"(h0));
    asm("cvt.rn.bf16.f32 %0, %1;" : "=h"(l0) : "f"(x0 - f0));
    asm("cvt.rn.bf16.f32 %0, %1;" : "=h"(h1) : "f"(x1));
    asm("cvt.f32.bf16 %0, %1;" : "=f"(f1) : "h"(h1));
    asm("cvt.rn.bf16.f32 %0, %1;" : "=h"(l1) : "f"(x1 - f1));
    lopair = (uint32_t)l0 | ((uint32_t)l1 << 16);
    return (uint32_t)h0 | ((uint32_t)h1 << 16);
}

// smem formulas
__host__ __device__ constexpr int c2_stride(int KH, int KW, int S, int OW, int OHB, int CIB) {
    int TWID = (OW - 1) * S + KW; int TWIDP = (TWID + 3) & ~3;
    int TROWS = (OHB - 1) * S + KH;
    return CIB * TROWS * TWIDP * 4 + 16 * (CIB * KH * KW + 1) * 8;
}
__host__ __device__ constexpr int c2_smem(int KH, int KW, int S, int OW, int OHB, int CIB, int CI) {
    return (CI > CIB ? 2 : 1) * c2_stride(KH, KW, S, OW, OHB, CIB);
}
__host__ __device__ constexpr int ct_stride(int OW, int OHB, int CIB, int COB) {
    int TWIDP = ((OW / 2 + 2) + 3) & ~3;
    return CIB * (OHB / 2 + 2) * TWIDP * 4 + (COB / 2) * (CIB * 16 + 1) * 8;
}
__host__ __device__ constexpr int cmma_smem(int CO, int T, int PADK, int MW) {
    int PIX = (MW * 32 / 64 + 2 * PADK) * (64 + 2 * PADK);
    return (((PIX * 80 + 127) & ~127)) + 2 * T * CO * 80;
}

// ---------------------------------------------------------------------------
// Batched weight prep: 11 standard layers in one launch (blockIdx.y = layer).
// Record per (chunk, tap): CO recs x 80B = [16 hi][16 lo]
// ---------------------------------------------------------------------------
struct PrepJob { const float* w; int off; int CI; int CO; int KS; int total; };
struct PrepJobs { PrepJob j[11]; };

__global__ void prepw_all(PrepJobs jobs, unsigned short* __restrict__ dstbase)
{
    const PrepJob J = jobs.j[blockIdx.y];
    int i = blockIdx.x * 256 + threadIdx.x;
    if (i >= J.total) return;
    unsigned short* dst = dstbase + J.off;
    const int TT = J.KS * J.KS;
    const int kp = i & 7;
    int rest = i >> 3;
    const int n = rest % J.CO; rest /= J.CO;
    const int t = rest % TT;
    const int c = rest / TT;
    const int ci = c * 16 + 2 * kp;
    const float* base = J.w + (((long)n * J.CI + ci) * TT) + t;
    const float x0 = base[0], x1 = base[TT];
    uint32_t lo, hi = bfsplit2(x0, x1, lo);
    unsigned short* rec = dst + ((long)(c * TT + t) * J.CO + n) * 40;
    *(uint32_t*)(rec + 2 * kp) = hi;
    *(uint32_t*)(rec + 16 + 2 * kp) = lo;
}

// enc_w1 [128co][64ci][4][4] -> s2d-conv records: 16 chunks x 4 taps x 128 co
__global__ void prepw_s2d(const float* __restrict__ w, unsigned short* __restrict__ dst)
{
    int i = blockIdx.x * 256 + threadIdx.x;
    if (i >= 65536) return;
    const int kp = i & 7;
    int rest = i >> 3;
    const int co = rest & 127; rest >>= 7;
    const int t = rest & 3;
    const int c = rest >> 2;
    const int p = c >> 2, py = p >> 1, px = p & 1;
    const int jy = t >> 1, jx = t & 1;
    const int kh = 2 * jy + 1 - py, kw = 2 * jx + 1 - px;
    const int ci = (c & 3) * 16 + 2 * kp;
    const float* s = w + (((long)co * 64 + ci) * 16) + kh * 4 + kw;
    uint32_t lo, hi = bfsplit2(s[0], s[16], lo);
    unsigned short* rec = dst + ((long)(c * 4 + t) * 128 + co) * 40;
    *(uint32_t*)(rec + 2 * kp) = hi;
    *(uint32_t*)(rec + 16 + 2 * kp) = lo;
}

// up_w0 [128ci][64co][4][4] -> per-phase convT records: 4 ph x 8 chunks x 4 taps x 64 co
__global__ void prepw_ct(const float* __restrict__ w, unsigned short* __restrict__ dst)
{
    int i = blockIdx.x * 256 + threadIdx.x;
    if (i >= 65536) return;
    const int kp = i & 7;
    int rest = i >> 3;
    const int co = rest & 63; rest >>= 6;
    const int t = rest & 3; rest >>= 2;
    const int c = rest & 7;
    const int ph = rest >> 3;
    const int py = ph >> 1, px = ph & 1;
    const int jy = t >> 1, jx = t & 1;
    const int ky = 2 * jy + 1 - py, kx = 2 * jx + 1 - px;
    const int ci = c * 16 + 2 * kp;
    const float* s = w + (((long)ci * 64 + co) * 16) + ky * 4 + kx;
    uint32_t lo, hi = bfsplit2(s[0], s[1024], lo);
    unsigned short* rec = dst + ((long)((ph * 8 + c) * 4 + t) * 64 + co) * 40;
    *(uint32_t*)(rec + 2 * kp) = hi;
    *(uint32_t*)(rec + 16 + 2 * kp) = lo;
}

// ---------------------------------------------------------------------------
// Generalized tensor-core conv on 64x64 index space.
// B is staged for ALL taps of a ci-chunk at once (double-buffered across
// chunks) -> only 2 __syncthreads per chunk; taps run barrier-free.
// MODE 0: stride-1 KSxKS conv; MODE 1: s2d stride-2 4x4; MODE 2: convT phase.
// ---------------------------------------------------------------------------
template <int MODE, int CI, int CO, int KS, int MW, int NW, int OCC,
          bool RIN, bool ROUT, bool ADD>
__global__ void __launch_bounds__(256, OCC) convmma(
    const float* __restrict__ in, const unsigned short* __restrict__ wb,
    const float* __restrict__ bias, const float* __restrict__ res,
    float* __restrict__ out)
{
    constexpr int CH = CI / 16;
    constexpr int T = (MODE == 0) ? KS * KS : 4;
    constexpr int PADK = (MODE == 0) ? (KS - 1) / 2 : 1;
    constexpr int MC = MW * 32;
    constexpr int NWT = CO / NW;
    constexpr int NB = NWT / 16;
    constexpr int YO = MC / 64;
    constexpr int YR = YO + 2 * PADK;
    constexpr int XW = 64 + 2 * PADK;
    constexpr int PIX = YR * XW;
    constexpr int ABYTES = (PIX * 80 + 127) & ~127;
    constexpr int BSTAGE = T * CO * 80;

    extern __shared__ char sm[];
    char* Abuf = sm;
    const uint32_t smA = s2u(sm);
    const uint32_t smB = s2u(sm + ABYTES);

    const int tid = threadIdx.x;
    const int lane = tid & 31;
    const int warp = tid >> 5;
    const int wm = (NW == 1) ? warp : (warp & (MW - 1));
    const int wn = (NW == 1) ? 0 : (warp >> 2);

    const int py = (MODE == 2) ? ((int)blockIdx.y >> 1) : 0;
    const int px = (MODE == 2) ? ((int)blockIdx.y & 1) : 0;
    const unsigned short* wbp = (MODE == 2) ? wb + (long)blockIdx.y * CH * T * CO * 40 : wb;

    const int mtile = blockIdx.x * MC;
    const int nimg = mtile >> 12;
    const int y0 = (mtile >> 6) & 63;
    const float* inb = in + ((long)nimg * CI << 12);

    const int q = lane >> 3, r = lane & 7;
    const int m_off = ((q & 1) << 3) + r;
    const int k8b = (q >> 1) * 16;

    uint32_t laneA[2];
#pragma unroll
    for (int im = 0; im < 2; im++) {
        const int mrow = wm * 32 + im * 16 + m_off;
        laneA[im] = smA + (uint32_t)((mrow >> 6) * XW + (mrow & 63)) * 80 + k8b;
    }
    const uint32_t laneBoff = (uint32_t)(wn * NWT + m_off) * 80 + k8b;

    float acc[2][2 * NB][4];
#pragma unroll
    for (int im = 0; im < 2; im++)
#pragma unroll
        for (int j = 0; j < 2 * NB; j++)
#pragma unroll
            for (int e = 0; e < 4; e++) acc[im][j][e] = 0.f;

    auto stageBall = [&](int c, int b) {
        const char* src = (const char*)(wbp + (long)c * T * CO * 40);
        const uint32_t d = smB + (uint32_t)b * BSTAGE;
        for (int i = tid; i < T * CO * 5; i += 256)
            cpa16(d + (uint32_t)i * 16, src + (long)i * 16);
    };
    auto stageA = [&](int c) {
        const int ci0 = c * 16;
        for (int i = tid; i < 8 * PIX; i += 256) {
            const int cp = i / PIX, p = i - cp * PIX;
            const int yy = p / XW, xx = p - yy * XW;
            const int iy = y0 + yy - PADK, ix = xx - PADK;
            float v0 = 0.f, v1 = 0.f;
            if (iy >= 0 && iy < 64 && ix >= 0 && ix < 64) {
                const float* pp = inb + ((long)(ci0 + 2 * cp) << 12) + (iy << 6) + ix;
                v0 = __ldg(pp); v1 = __ldg(pp + 4096);
            }
            if (RIN) { v0 = fmaxf(v0, 0.f); v1 = fmaxf(v1, 0.f); }
            uint32_t lo, hi = bfsplit2(v0, v1, lo);
            *(uint32_t*)(Abuf + p * 80 + 4 * cp) = hi;
            *(uint32_t*)(Abuf + p * 80 + 32 + 4 * cp) = lo;
        }
    };

    stageBall(0, 0);
    cpacommit();

    for (int c = 0; c < CH; c++) {
        __syncthreads();                 // A + old B stage free
        if (c + 1 < CH) { stageBall(c + 1, (c + 1) & 1); cpacommit(); }
        stageA(c);
        if (c + 1 < CH) cpawait<1>(); else cpawait<0>();
        __syncthreads();                 // A + B[c] visible

        const uint32_t bstage = smB + (uint32_t)(c & 1) * BSTAGE;
#pragma unroll 1
        for (int t = 0; t < T; t++) {
            int dyr, dxr;
            if (MODE == 0) { dyr = t / KS; dxr = t - (t / KS) * KS; }
            else if (MODE == 1) {
                const int pc = c >> 2;
                dyr = (t >> 1) - (pc >> 1) + 1;
                dxr = (t & 1) - (pc & 1) + 1;
            } else {
                dyr = py - (t >> 1) + 1;
                dxr = px - (t & 1) + 1;
            }
            const uint32_t dt = (uint32_t)(dyr * XW + dxr) * 80;

            uint32_t ah[2][4], al[2][4];
            ldsm4(ah[0], laneA[0] + dt);
            ldsm4(ah[1], laneA[1] + dt);
            ldsm4(al[0], laneA[0] + dt + 32);
            ldsm4(al[1], laneA[1] + dt + 32);

            const uint32_t bb = bstage + (uint32_t)t * (CO * 80) + laneBoff;
            uint32_t bf[NB][4];
#pragma unroll
            for (int nb = 0; nb < NB; nb++) ldsm4(bf[nb], bb + (uint32_t)nb * 1280);
#pragma unroll
            for (int im = 0; im < 2; im++)
#pragma unroll
                for (int nb = 0; nb < NB; nb++) {
                    mma16816(acc[im][2 * nb], ah[im], bf[nb][0], bf[nb][2]);
                    mma16816(acc[im][2 * nb + 1], ah[im], bf[nb][1], bf[nb][3]);
                    mma16816(acc[im][2 * nb], al[im], bf[nb][0], bf[nb][2]);
                    mma16816(acc[im][2 * nb + 1], al[im], bf[nb][1], bf[nb][3]);
                }
#pragma unroll
            for (int nb = 0; nb < NB; nb++) ldsm4(bf[nb], bb + (uint32_t)nb * 1280 + 32);
#pragma unroll
            for (int im = 0; im < 2; im++)
#pragma unroll
                for (int nb = 0; nb < NB; nb++) {
                    mma16816(acc[im][2 * nb], ah[im], bf[nb][0], bf[nb][2]);
                    mma16816(acc[im][2 * nb + 1], ah[im], bf[nb][1], bf[nb][3]);
                }
        }
    }

    const int gid = lane >> 2, tg = lane & 3;
    const int l0 = (mtile & 4095) + wm * 32 + gid;
#pragma unroll
    for (int im = 0; im < 2; im++) {
#pragma unroll
        for (int j = 0; j < 2 * NB; j++) {
            const int col = wn * NWT + j * 8 + 2 * tg;
            const float b0 = __ldg(bias + col), b1 = __ldg(bias + col + 1);
#pragma unroll
            for (int h = 0; h < 2; h++) {
                const int sp = l0 + im * 16 + h * 8;
                float v0 = acc[im][j][2 * h] + b0;
                float v1 = acc[im][j][2 * h + 1] + b1;
                if (MODE == 2) {
                    if (ROUT) { v0 = fmaxf(v0, 0.f); v1 = fmaxf(v1, 0.f); }
                    const long cb2 = ((long)nimg * CO + col) << 14;
                    const int oo = (((sp >> 6) * 2 + py) << 7) + ((sp & 63) * 2 + px);
                    out[cb2 + oo] = v0;
                    out[cb2 + oo + 16384] = v1;
                } else {
                    const long o0 = (((long)nimg * CO + col) << 12) + sp;
                    if (ADD) { v0 += __ldg(res + o0); v1 += __ldg(res + o0 + 4096); }
                    if (ROUT) { v0 = fmaxf(v0, 0.f); v1 = fmaxf(v1, 0.f); }
                    out[o0] = v0;
                    out[o0 + 4096] = v1;
                }
            }
        }
    }
}

// ---------------------------------------------------------------------------
// fp32 conv (L1 only), f32x2, s2d-layout output
// ---------------------------------------------------------------------------
template <int KH, int KW, int S, int P, int OWt, int OHB, int CIB,
          bool RIN, bool ROUT, bool ADD, bool S2D>
__global__ void __launch_bounds__(256) conv2(
    const float* __restrict__ in, const float* __restrict__ wt,
    const float* __restrict__ bias, const float* __restrict__ res,
    float* __restrict__ out, int N, int CI, int CO, int IH, int IW, int OH)
{
    constexpr int OW = OWt;
    constexpr int TAPS = KH * KW;
    constexpr int TWID = (OW - 1) * S + KW;
    constexpr int TWIDP = (TWID + 3) & ~3;
    constexpr int TROWS = (OHB - 1) * S + KH;
    constexpr int TILE_CI = TROWS * TWIDP;
    constexpr int TILE = CIB * TILE_CI;
    constexpr int WSTR = CIB * TAPS + 1;
    constexpr int STRIDEB = TILE * 4 + 16 * WSTR * 8;
    constexpr int LW = 7 * S + KW;
    constexpr int OWG8 = OW / 8;
    static_assert(OWG8 * OHB * 4 == 256, "map");

    extern __shared__ char smx[];
    const int RB = OH / OHB;
    const int n = blockIdx.x / RB;
    const int rb = blockIdx.x % RB;
    const int oy0 = rb * OHB;
    const int co0 = blockIdx.y * 16;
    const int tid = threadIdx.x;
    const int cog = tid & 3;
    const int spat = tid >> 2;
    const int owg = spat % OWG8;
    const int ohr = spat / OWG8;
    const int co_l = cog * 4;
    const int iy0 = oy0 * S - P;
    const float* inn = in + (long)n * CI * IH * IW;
    const int G = CI / CIB;

    ull acc[4][4];
#pragma unroll
    for (int c = 0; c < 4; c++) {
        const float b = __ldg(bias + co0 + co_l + c);
        const ull bb = pk2(b, b);
#pragma unroll
        for (int m = 0; m < 4; m++) acc[c][m] = bb;
    }
    auto stage = [&](int gidx, int bi) {
        char* buf = smx + bi * STRIDEB;
        float* tile = (float*)buf;
        ull* wp = (ull*)(buf + TILE * 4);
        const uint32_t tadr = s2u(tile);
        const int ci0 = gidx * CIB;
        for (int i = tid; i < TILE; i += 256) {
            const int ci_l = i / TILE_CI;
            const int rem = i - ci_l * TILE_CI;
            const int r = rem / TWIDP, c = rem - r * TWIDP;
            const int iy = iy0 + r, ix = c - P;
            const bool ok = (c < TWID) & (iy >= 0) & (iy < IH) & (ix >= 0) & (ix < IW);
            const float* src = ok ? inn + ((long)(ci0 + ci_l) * IH + iy) * IW + ix : inn;
            cpa4(tadr + 4u * (uint32_t)i, src, ok);
        }
        for (int i = tid; i < 16 * CIB * TAPS; i += 256) {
            const int c = i / (CIB * TAPS);
            const int rem = i - c * (CIB * TAPS);
            const float w = __ldg(wt + ((long)(co0 + c) * CI + ci0 + rem / TAPS) * TAPS + rem % TAPS);
            wp[c * WSTR + rem] = pk2(w, w);
        }
    };
    stage(0, 0);
    cpacommit();
    for (int g = 0; g < G; g++) {
        const int bi = g & 1;
        if (g + 1 < G) { stage(g + 1, bi ^ 1); cpacommit(); cpawait<1>(); }
        else cpawait<0>();
        __syncthreads();
        const float* tb = (const float*)(smx + bi * STRIDEB);
        const ull* wbp = (const ull*)(smx + bi * STRIDEB + TILE * 4);
#pragma unroll 1
        for (int ci_l = 0; ci_l < CIB; ci_l++) {
            const float* tci = tb + ci_l * TILE_CI;
#pragma unroll
            for (int kh = 0; kh < KH; kh++) {
                const float* trow = tci + (ohr * S + kh) * TWIDP + owg * 8 * S;
                float ir[LW];
#pragma unroll
                for (int v = 0; v < LW / 4; v++) {
                    const float4 q4 = reinterpret_cast<const float4*>(trow)[v];
                    ir[4 * v] = q4.x; ir[4 * v + 1] = q4.y; ir[4 * v + 2] = q4.z; ir[4 * v + 3] = q4.w;
                }
#pragma unroll
                for (int l = (LW / 4) * 4; l < LW; l++) ir[l] = trow[l];
                if (RIN) {
#pragma unroll
                    for (int l = 0; l < LW; l++) ir[l] = fmaxf(ir[l], 0.f);
                }
#pragma unroll
                for (int kw = 0; kw < KW; kw++) {
                    ull p[4];
#pragma unroll
                    for (int m = 0; m < 4; m++)
                        p[m] = pk2(ir[2 * m * S + kw], ir[(2 * m + 1) * S + kw]);
#pragma unroll
                    for (int c = 0; c < 4; c++) {
                        const ull w2 = wbp[(co_l + c) * WSTR + ci_l * TAPS + kh * KW + kw];
#pragma unroll
                        for (int m = 0; m < 4; m++) fma2(acc[c][m], p[m], w2);
                    }
                }
            }
        }
        __syncthreads();
    }
    const int oy = oy0 + ohr;
#pragma unroll
    for (int c = 0; c < 4; c++) {
        float o[8];
#pragma unroll
        for (int m = 0; m < 4; m++) {
            const float2 t = upk(acc[c][m]);
            o[2 * m] = t.x; o[2 * m + 1] = t.y;
        }
        if (ROUT) {
#pragma unroll
            for (int j = 0; j < 8; j++) o[j] = fmaxf(o[j], 0.f);
        }
        if (S2D) {
            const int pyl = oy & 1, yh = oy >> 1, xh0 = owg * 4;
            const int ch = co0 + co_l + c;
            float* p0 = out + (((long)n * 256 + (pyl * 2 + 0) * 64 + ch) << 12) + (yh << 6) + xh0;
            float* p1 = out + (((long)n * 256 + (pyl * 2 + 1) * 64 + ch) << 12) + (yh << 6) + xh0;
            *reinterpret_cast<float4*>(p0) = make_float4(o[0], o[2], o[4], o[6]);
            *reinterpret_cast<float4*>(p1) = make_float4(o[1], o[3], o[5], o[7]);
        } else {
            const long ob = (((long)n * CO + co0 + co_l + c) * OH + oy) * OW + owg * 8;
            float* op = out + ob;
            if (ADD) {
                const float* rp = res + ob;
#pragma unroll
                for (int j = 0; j < 8; j++) o[j] += __ldg(rp + j);
            }
            reinterpret_cast<float4*>(op)[0] = make_float4(o[0], o[1], o[2], o[3]);
            reinterpret_cast<float4*>(op)[1] = make_float4(o[4], o[5], o[6], o[7]);
        }
    }
}

// ---------------------------------------------------------------------------
// ConvTranspose2d k=4 s=2 p=1 fp32 (up1 only)
// ---------------------------------------------------------------------------
template <int OWt, int OHB, int CIB, int COB, int COT, bool RIN, bool ROUT>
__global__ void __launch_bounds__(256) convt2(
    const float* __restrict__ in, const float* __restrict__ wt,
    const float* __restrict__ bias, float* __restrict__ out,
    int N, int CI, int CO, int IH, int IW, int OH)
{
    constexpr int OW = OWt;
    constexpr int COG = COB / COT;
    constexpr int CP = COT / 2;
    constexpr int TROWS = OHB / 2 + 2;
    constexpr int TWID = OW / 2 + 2;
    constexpr int TWIDP = (TWID + 3) & ~3;
    constexpr int TILE_CI = TROWS * TWIDP;
    constexpr int TILE = CIB * TILE_CI;
    constexpr int WTSTR = CIB * 16 + 1;
    constexpr int STRIDEB = TILE * 4 + (COB / 2) * WTSTR * 8;
    constexpr int OWG8 = OW / 8;
    static_assert(OWG8 * OHB * COG == 256, "map");

    extern __shared__ char smx[];
    const int RB = OH / OHB;
    const int n = blockIdx.x / RB;
    const int rb = blockIdx.x % RB;
    const int oy0 = rb * OHB;
    const int co0 = blockIdx.y * COB;
    const int tid = threadIdx.x;
    const int cog = tid % COG;
    const int spat = tid / COG;
    const int owg = spat % OWG8;
    const int ohr = spat / OWG8;
    const int co_l = cog * COT;
    const int iy0 = oy0 / 2 - 1;
    const int oy = oy0 + ohr;
    const int ky0 = (oy + 1) & 1;
    const float* inn = in + (long)n * CI * IH * IW;
    const int G = CI / CIB;

    ull accp[CP][8];
#pragma unroll
    for (int qq = 0; qq < CP; qq++) {
        const int c0 = co0 + co_l + 2 * qq, c1 = c0 + 1;
        const float b0 = (c0 < CO) ? __ldg(bias + c0) : 0.f;
        const float b1 = (c1 < CO) ? __ldg(bias + c1) : 0.f;
        const ull bb = pk2(b0, b1);
#pragma unroll
        for (int j = 0; j < 8; j++) accp[qq][j] = bb;
    }
    auto stage = [&](int gidx, int bi) {
        char* buf = smx + bi * STRIDEB;
        float* tile = (float*)buf;
        ull* wp = (ull*)(buf + TILE * 4);
        const uint32_t tadr = s2u(tile);
        const int ci0 = gidx * CIB;
        for (int i = tid; i < TILE; i += 256) {
            const int ci_l = i / TILE_CI;
            const int rem = i - ci_l * TILE_CI;
            const int r = rem / TWIDP, c = rem - r * TWIDP;
            const int iy = iy0 + r, ix = c - 1;
            const bool ok = (c < TWID) & (iy >= 0) & (iy < IH) & (ix >= 0) & (ix < IW);
            const float* src = ok ? inn + ((long)(ci0 + ci_l) * IH + iy) * IW + ix : inn;
            cpa4(tadr + 4u * (uint32_t)i, src, ok);
        }
        for (int i = tid; i < (COB / 2) * CIB * 16; i += 256) {
            const int cpg = i / (CIB * 16);
            const int rem = i - cpg * (CIB * 16);
            const int ci_l = rem >> 4, tap = rem & 15;
            const int c0 = co0 + 2 * cpg, c1 = c0 + 1;
            const float w0 = (c0 < CO) ? __ldg(wt + ((long)(ci0 + ci_l) * CO + c0) * 16 + tap) : 0.f;
            const float w1 = (c1 < CO) ? __ldg(wt + ((long)(ci0 + ci_l) * CO + c1) * 16 + tap) : 0.f;
            wp[cpg * WTSTR + rem] = pk2(w0, w1);
        }
    };
    stage(0, 0);
    cpacommit();
    for (int g = 0; g < G; g++) {
        const int bi = g & 1;
        if (g + 1 < G) { stage(g + 1, bi ^ 1); cpacommit(); cpawait<1>(); }
        else cpawait<0>();
        __syncthreads();
        const float* tb = (const float*)(smx + bi * STRIDEB);
        const ull* wbp = (const ull*)(smx + bi * STRIDEB + TILE * 4);
#pragma unroll 1
        for (int ci_l = 0; ci_l < CIB; ci_l++) {
            const float* tci = tb + ci_l * TILE_CI;
#pragma unroll
            for (int t2 = 0; t2 < 2; t2++) {
                const int ky = ky0 + 2 * t2;
                const int r = ((oy + 1 - ky) >> 1) - iy0;
                const float* trow = tci + r * TWIDP + owg * 4;
                float ir[6];
                {
                    const float4 q4 = *reinterpret_cast<const float4*>(trow);
                    ir[0] = q4.x; ir[1] = q4.y; ir[2] = q4.z; ir[3] = q4.w;
                    ir[4] = trow[4]; ir[5] = trow[5];
                }
                if (RIN) {
#pragma unroll
                    for (int l = 0; l < 6; l++) ir[l] = fmaxf(ir[l], 0.f);
                }
#pragma unroll
                for (int kx = 0; kx < 4; kx++) {
                    const int ph = (kx + 1) & 1;
                    const int dt = (kx == 0) ? 1 : ((kx == 3) ? -1 : 0);
                    ull vv[4];
#pragma unroll
                    for (int m = 0; m < 4; m++) {
                        const float v = ir[m + dt + 1];
                        vv[m] = pk2(v, v);
                    }
#pragma unroll
                    for (int qq = 0; qq < CP; qq++) {
                        const ull w2 = wbp[(cog * CP + qq) * WTSTR + ci_l * 16 + ky * 4 + kx];
#pragma unroll
                        for (int m = 0; m < 4; m++) fma2(accp[qq][2 * m + ph], vv[m], w2);
                    }
                }
            }
        }
        __syncthreads();
    }
#pragma unroll
    for (int qq = 0; qq < CP; qq++) {
        float o0[8], o1[8];
#pragma unroll
        for (int j = 0; j < 8; j++) {
            const float2 t = upk(accp[qq][j]);
            o0[j] = ROUT ? fmaxf(t.x, 0.f) : t.x;
            o1[j] = ROUT ? fmaxf(t.y, 0.f) : t.y;
        }
        const int c0 = co0 + co_l + 2 * qq, c1 = c0 + 1;
        if (c0 < CO) {
            float* op = out + (((long)n * CO + c0) * OH + oy) * OW + owg * 8;
            reinterpret_cast<float4*>(op)[0] = make_float4(o0[0], o0[1], o0[2], o0[3]);
            reinterpret_cast<float4*>(op)[1] = make_float4(o0[4], o0[5], o0[6], o0[7]);
        }
        if (c1 < CO) {
            float* op = out + (((long)n * CO + c1) * OH + oy) * OW + owg * 8;
            reinterpret_cast<float4*>(op)[0] = make_float4(o1[0], o1[1], o1[2], o1[3]);
            reinterpret_cast<float4*>(op)[1] = make_float4(o1[4], o1[5], o1[6], o1[7]);
        }
    }
}

// ---------------------------------------------------------------------------
// VQ (unchanged)
// ---------------------------------------------------------------------------
__global__ void __launch_bounds__(256) vqk2(
    const float* __restrict__ z, const float* __restrict__ cb, float* __restrict__ q)
{
    constexpr int NPIX = 4096;
    __shared__ float cbs[128][68];
    __shared__ float cns[128];
    const int tid = threadIdx.x;
    const int p = blockIdx.x * 256 + tid;
    const int b = p >> 12;
    const int pix = p & 4095;
    const float* zp = z + (long)b * 64 * NPIX + pix;
    float f[64];
#pragma unroll
    for (int d = 0; d < 64; d++) f[d] = zp[(long)d * NPIX];
    ull fp[32];
#pragma unroll
    for (int i = 0; i < 32; i++) fp[i] = pk2(f[2 * i], f[2 * i + 1]);
    float best = 3.4e38f;
    int bidx = 0;
    for (int t = 0; t < 4; t++) {
        __syncthreads();
        for (int i = tid; i < 8192; i += 256) {
            const int d = i >> 7, kk = i & 127;
            cbs[kk][d] = __ldg(cb + d * 512 + t * 128 + kk);
        }
        __syncthreads();
        if (tid < 128) {
            const float* row = cbs[tid];
            float s = 0.f;
#pragma unroll
            for (int d = 0; d < 64; d++) s += row[d] * row[d];
            cns[tid] = s;
        }
        __syncthreads();
        for (int kk = 0; kk < 128; kk++) {
            const ulonglong2* row = reinterpret_cast<const ulonglong2*>(cbs[kk]);
            ull a0 = 0, a1 = 0, a2 = 0, a3 = 0;
#pragma unroll
            for (int i = 0; i < 16; i += 2) {
                const ulonglong2 u = row[i];
                const ulonglong2 v = row[i + 1];
                fma2(a0, u.x, fp[2 * i]);
                fma2(a1, u.y, fp[2 * i + 1]);
                fma2(a2, v.x, fp[2 * i + 2]);
                fma2(a3, v.y, fp[2 * i + 3]);
            }
            const float2 x0 = upk(a0), x1 = upk(a1), x2 = upk(a2), x3 = upk(a3);
            const float dot = ((x0.x + x0.y) + (x1.x + x1.y)) + ((x2.x + x2.y) + (x3.x + x3.y));
            const float dist = cns[kk] - 2.f * dot;
            if (dist < best) { best = dist; bidx = t * 128 + kk; }
        }
    }
    float* qp = q + (long)b * 64 * NPIX + pix;
#pragma unroll
    for (int d = 0; d < 64; d++) qp[(long)d * NPIX] = __ldg(cb + d * 512 + bidx);
}

// ---------------------------------------------------------------------------
// Host launcher
// ---------------------------------------------------------------------------
extern "C" void kernel_launch(void* const* d_in, const int* in_sizes, int n_in,
                              void* d_out, int out_size)
{
    (void)in_sizes; (void)n_in; (void)out_size;
    const float* x        = (const float*)d_in[0];
    const float* enc_w0   = (const float*)d_in[1];
    const float* enc_b0   = (const float*)d_in[2];
    const float* enc_w1   = (const float*)d_in[3];
    const float* enc_b1   = (const float*)d_in[4];
    const float* enc_wf   = (const float*)d_in[5];
    const float* enc_bf   = (const float*)d_in[6];
    const float* enc_rw1  = (const float*)d_in[7];
    const float* enc_rb1  = (const float*)d_in[8];
    const float* enc_rw2  = (const float*)d_in[9];
    const float* enc_rb2  = (const float*)d_in[10];
    const float* pre_w    = (const float*)d_in[11];
    const float* pre_b    = (const float*)d_in[12];
    const float* codebook = (const float*)d_in[13];
    const float* dec_w    = (const float*)d_in[14];
    const float* dec_b    = (const float*)d_in[15];
    const float* dec_rw1  = (const float*)d_in[16];
    const float* dec_rb1  = (const float*)d_in[17];
    const float* dec_rw2  = (const float*)d_in[18];
    const float* dec_rb2  = (const float*)d_in[19];
    const float* up_w0    = (const float*)d_in[20];
    const float* up_b0    = (const float*)d_in[21];
    const float* up_w1    = (const float*)d_in[22];
    const float* up_b1    = (const float*)d_in[23];
    float* out = (float*)d_out;

    float *pA, *pB, *pC, *pT, *pZ, *pQ, *pS;
    unsigned short* pW;
    cudaGetSymbolAddress((void**)&pA, g_bufA);
    cudaGetSymbolAddress((void**)&pB, g_bufB);
    cudaGetSymbolAddress((void**)&pC, g_bufC);
    cudaGetSymbolAddress((void**)&pT, g_bufT);
    cudaGetSymbolAddress((void**)&pZ, g_bufZ);
    cudaGetSymbolAddress((void**)&pQ, g_bufQ);
    cudaGetSymbolAddress((void**)&pS, g_bufS);
    cudaGetSymbolAddress((void**)&pW, g_wb);

    const int N = 16;

    // g_wb offsets (shorts)
    const int oWF = 0;
    const int oER1a = 368640, oER1b = 460800;
    const int oER2a = 552960, oER2b = 563200;
    const int oPRE = 573440;
    const int oDEC = 593920;
    const int oDR1a = 778240, oDR1b = 870400;
    const int oDR2a = 962560, oDR2b = 972800;
    const int oL2  = 983040;
    const int oUP0 = 1310720;

    // smem attrs (idempotent)
    cudaFuncSetAttribute((const void*)convmma<1,256,128,0,4,2,2,false,true,false>,
        cudaFuncAttributeMaxDynamicSharedMemorySize, cmma_smem(128,4,1,4));
    cudaFuncSetAttribute((const void*)convmma<0,128,128,3,4,2,1,false,false,false>,
        cudaFuncAttributeMaxDynamicSharedMemorySize, cmma_smem(128,9,1,4));
    cudaFuncSetAttribute((const void*)convmma<0,64,128,3,4,2,1,false,false,false>,
        cudaFuncAttributeMaxDynamicSharedMemorySize, cmma_smem(128,9,1,4));
    cudaFuncSetAttribute((const void*)convmma<0,128,32,3,8,1,2,true,false,false>,
        cudaFuncAttributeMaxDynamicSharedMemorySize, cmma_smem(32,9,1,8));
    cudaFuncSetAttribute((const void*)convmma<2,128,64,0,4,2,2,true,true,false>,
        cudaFuncAttributeMaxDynamicSharedMemorySize, cmma_smem(64,4,1,4));
    cudaFuncSetAttribute((const void*)convt2<256,8,8,4,4,false,false>,
        cudaFuncAttributeMaxDynamicSharedMemorySize, 2 * ct_stride(256,8,8,4));

    // --- batched weight prep (11 standard layers, 1 launch) ---
    PrepJobs jobs;
    auto J = [&](int k, const float* w, int off, int CI, int CO, int KS) {
        jobs.j[k] = PrepJob{w, off, CI, CO, KS, (CI / 16) * KS * KS * CO * 8};
    };
    J(0, enc_wf, oWF, 128, 128, 3);
    J(1, enc_rw1, oER1a, 128, 32, 3);
    J(2, enc_rw1 + (long)32 * 128 * 9, oER1b, 128, 32, 3);
    J(3, enc_rw2, oER2a, 32, 128, 1);
    J(4, enc_rw2 + (long)128 * 32, oER2b, 32, 128, 1);
    J(5, pre_w, oPRE, 128, 64, 1);
    J(6, dec_w, oDEC, 64, 128, 3);
    J(7, dec_rw1, oDR1a, 128, 32, 3);
    J(8, dec_rw1 + (long)32 * 128 * 9, oDR1b, 128, 32, 3);
    J(9, dec_rw2, oDR2a, 32, 128, 1);
    J(10, dec_rw2 + (long)128 * 32, oDR2b, 32, 128, 1);
    prepw_all<<<dim3(288, 11), 256>>>(jobs, pW);
    prepw_s2d<<<256, 256>>>(enc_w1, pW + oL2);
    prepw_ct<<<256, 256>>>(up_w0, pW + oUP0);

    // L1: x -> relu -> s2d layout in bufS
    conv2<4,4,2,1,128,4,3,false,true,false,true>
        <<<dim3(N * 32, 4), 256, c2_smem(4,4,2,128,4,3,3)>>>(
        x, enc_w0, enc_b0, nullptr, pS, N, 3, 64, 256, 256, 128);

    // L2 (s2d conv) on tensor cores
    convmma<1,256,128,0,4,2,2,false,true,false><<<512, 256, cmma_smem(128,4,1,4)>>>(
        pS, pW + oL2, enc_b1, nullptr, pB);

    // 64x64 stride-1 family
    convmma<0,128,128,3,4,2,1,false,false,false><<<512, 256, cmma_smem(128,9,1,4)>>>(
        pB, pW + oWF, enc_bf, nullptr, pC);
    convmma<0,128,32,3,8,1,2,true,false,false><<<256, 256, cmma_smem(32,9,1,8)>>>(
        pC, pW + oER1a, enc_rb1, nullptr, pT);
    convmma<0,32,128,1,4,2,2,true,false,true><<<512, 256, cmma_smem(128,1,0,4)>>>(
        pT, pW + oER2a, enc_rb2, pC, pC);
    convmma<0,128,32,3,8,1,2,true,false,false><<<256, 256, cmma_smem(32,9,1,8)>>>(
        pC, pW + oER1b, enc_rb1 + 32, nullptr, pT);
    convmma<0,32,128,1,4,2,2,true,false,true><<<512, 256, cmma_smem(128,1,0,4)>>>(
        pT, pW + oER2b, enc_rb2 + 128, pC, pC);
    convmma<0,128,64,1,4,2,2,true,false,false><<<512, 256, cmma_smem(64,1,0,4)>>>(
        pC, pW + oPRE, pre_b, nullptr, pZ);

    vqk2<<<256, 256>>>(pZ, codebook, pQ);

    convmma<0,64,128,3,4,2,1,false,false,false><<<512, 256, cmma_smem(128,9,1,4)>>>(
        pQ, pW + oDEC, dec_b, nullptr, pB);
    convmma<0,128,32,3,8,1,2,true,false,false><<<256, 256, cmma_smem(32,9,1,8)>>>(
        pB, pW + oDR1a, dec_rb1, nullptr, pT);
    convmma<0,32,128,1,4,2,2,true,false,true><<<512, 256, cmma_smem(128,1,0,4)>>>(
        pT, pW + oDR2a, dec_rb2, pB, pB);
    convmma<0,128,32,3,8,1,2,true,false,false><<<256, 256, cmma_smem(32,9,1,8)>>>(
        pB, pW + oDR1b, dec_rb1 + 32, nullptr, pT);
    convmma<0,32,128,1,4,2,2,true,false,true><<<512, 256, cmma_smem(128,1,0,4)>>>(
        pT, pW + oDR2b, dec_rb2 + 128, pB, pB);

    // up0 on tensor cores (4 sub-pixel phases)
    convmma<2,128,64,0,4,2,2,true,true,false><<<dim3(512, 4), 256, cmma_smem(64,4,1,4)>>>(
        pB, pW + oUP0, up_b0, nullptr, pA);

    // up1 fp32 conv-T
    convt2<256,8,8,4,4,false,false>
        <<<dim3(N * 32, 1), 256, 2 * ct_stride(256,8,8,4)>>>(
        pA, up_w1, up_b1, out, N, 64, 3, 128, 128, 256);
}